// round 8
// baseline (speedup 1.0000x reference)
#include <cuda_runtime.h>
#include <cuda_fp16.h>
#include <math.h>
#include <stdint.h>

#define NB      4
#define TSEQ    2048
#define NHEAD   16
#define HD      64
#define DMODEL  1024
#define ROWS    (NB * TSEQ)          // 8192
#define QKVCOLS (3 * DMODEL)         // 3072
#define WIN     128

// ---------------- scratch (allocation-free rule: device globals) ----------
__device__ __align__(16) __half g_Ah[ROWS   * DMODEL];
__device__ __align__(16) __half g_Al[ROWS   * DMODEL];
__device__ __align__(16) __half g_Bh[QKVCOLS * DMODEL];  // [N][K] transposed fp16
__device__ __align__(16) __half g_qr[ROWS * DMODEL];     // [b,h][t][d] roped+scaled Q
__device__ __align__(16) __half g_kr[ROWS * DMODEL];     // [b,h][t][d] roped K
__device__ __align__(16) __half g_vp[ROWS * DMODEL];     // [b,h][t][d] packed V
__device__ float4 g_rope[TSEQ * 16];  // (t, pg): cos/sin for freqs 2pg, 2pg+1

// ---------------- PTX helpers ---------------------------------------------
__device__ __forceinline__ uint32_t smem_u32(const void* p) {
    uint32_t a;
    asm("{ .reg .u64 t; cvta.to.shared.u64 t, %1; cvt.u32.u64 %0, t; }" : "=r"(a) : "l"(p));
    return a;
}
__device__ __forceinline__ void cp16(uint32_t dst, const void* src) {
    asm volatile("cp.async.cg.shared.global [%0], [%1], 16;" :: "r"(dst), "l"(src));
}
#define CP_COMMIT() asm volatile("cp.async.commit_group;" ::: "memory")
#define CP_WAIT(n)  asm volatile("cp.async.wait_group %0;" :: "n"(n) : "memory")

#define LDSM_X4(r, addr) \
    asm volatile("ldmatrix.sync.aligned.m8n8.x4.shared.b16 {%0,%1,%2,%3}, [%4];" \
        : "=r"((r)[0]), "=r"((r)[1]), "=r"((r)[2]), "=r"((r)[3]) : "r"(addr))
#define LDSM_X4_T(r, addr) \
    asm volatile("ldmatrix.sync.aligned.m8n8.x4.trans.shared.b16 {%0,%1,%2,%3}, [%4];" \
        : "=r"((r)[0]), "=r"((r)[1]), "=r"((r)[2]), "=r"((r)[3]) : "r"(addr))

#define MMA_F16(c, a, b0, b1) \
    asm volatile("mma.sync.aligned.m16n8k16.row.col.f32.f16.f16.f32 " \
        "{%0,%1,%2,%3}, {%4,%5,%6,%7}, {%8,%9}, {%0,%1,%2,%3};" \
        : "+f"((c)[0]), "+f"((c)[1]), "+f"((c)[2]), "+f"((c)[3]) \
        : "r"((a)[0]), "r"((a)[1]), "r"((a)[2]), "r"((a)[3]), "r"(b0), "r"(b1))

__device__ __forceinline__ uint32_t packh2(float a, float b) {
    __half2 h = __floats2half2_rn(a, b);
    return *reinterpret_cast<uint32_t*>(&h);
}

// ---------------- mma.sync GEMM: C = A[M,K]*Bt[N,K]^T, fp16 2-term A -------
// CTA 128x128, 8 warps (4m x 2n), warp 32x64, 3-stage cp.async, reg-pipelined.
// MODE 0: fp32 C + bias.  MODE 1: fused rope/pack epilogue -> g_qr/g_kr/g_vp.
#define BM 128
#define BN 128
#define BK 32
#define PADK 40
#define MAT_BYTES (128 * PADK * 2)    // 10240
#define SM_AH 0
#define SM_AL (1 * MAT_BYTES)
#define SM_BH (2 * MAT_BYTES)
#define STAGE_BYTES (3 * MAT_BYTES)   // 30720
#define GEMM_SMEM (3 * STAGE_BYTES)   // 92160

__device__ __forceinline__ void load_chunk(
    uint32_t sb, const __half* __restrict__ Ah, const __half* __restrict__ Al,
    const __half* __restrict__ Bh,
    int brow, int bcol, int K, int kc, int stage, int tid)
{
    uint32_t base = sb + stage * STAGE_BYTES;
#pragma unroll
    for (int t = 0; t < 2; t++) {
        int idx = tid + t * 256;
        int row = idx >> 2;
        int c16 = idx & 3;
        uint32_t so = (uint32_t)(row * (PADK * 2) + c16 * 16);
        size_t ga = (size_t)(brow + row) * K + kc + c16 * 8;
        size_t gb = (size_t)(bcol + row) * K + kc + c16 * 8;
        cp16(base + SM_AH + so, Ah + ga);
        cp16(base + SM_AL + so, Al + ga);
        cp16(base + SM_BH + so, Bh + gb);
    }
}

template <int MODE>
__global__ __launch_bounds__(256, 2)
void gemm_mma(const __half* __restrict__ Ah, const __half* __restrict__ Al,
              const __half* __restrict__ Bh,
              float* __restrict__ C, int M, int N, int K,
              const float* __restrict__ bias)
{
    extern __shared__ __align__(128) char smem[];
    uint32_t sb = smem_u32(smem);
    const int tid  = threadIdx.x;
    const int wid  = tid >> 5;
    const int lane = tid & 31;
    const int wm = (wid & 3) * 32;      // 4 warp-rows
    const int wn = (wid >> 2) * 64;     // 2 warp-cols
    const int brow = blockIdx.y * BM, bcol = blockIdx.x * BN;

    float c[2][8][4];
#pragma unroll
    for (int i = 0; i < 2; i++)
#pragma unroll
        for (int j = 0; j < 8; j++)
#pragma unroll
            for (int r = 0; r < 4; r++) c[i][j][r] = 0.0f;

    const int nchunks = K / BK;
    load_chunk(sb, Ah, Al, Bh, brow, bcol, K, 0, 0, tid);
    CP_COMMIT();
    load_chunk(sb, Ah, Al, Bh, brow, bcol, K, BK, 1, tid);
    CP_COMMIT();

    const int a_r = lane & 15;
    const int a_c = (lane >> 4) << 3;
    const int b_r = ((lane < 16) ? (lane & 7) : (8 + (lane & 7)));
    const int b_c = ((lane >> 3) & 1) << 3;

    for (int ch = 0; ch < nchunks; ch++) {
        if (ch + 1 < nchunks) { CP_WAIT(1); } else { CP_WAIT(0); }
        __syncthreads();
        if (ch + 2 < nchunks) {
            load_chunk(sb, Ah, Al, Bh, brow, bcol, K, (ch + 2) * BK, (ch + 2) % 3, tid);
            CP_COMMIT();
        }
        uint32_t stb = sb + (ch % 3) * STAGE_BYTES;
        const uint32_t aad = stb + SM_AH + (uint32_t)((wm + a_r) * (PADK * 2) + a_c * 2);
        const uint32_t bad = stb + SM_BH + (uint32_t)((wn + b_r) * (PADK * 2) + b_c * 2);

        uint32_t a0h[2][4], a0l[2][4], b0[4][4];
        uint32_t a1h[2][4], a1l[2][4], b1[4][4];
        // ---- ks0 fragments
#pragma unroll
        for (int mt = 0; mt < 2; mt++) {
            LDSM_X4(a0h[mt], aad + (uint32_t)(mt * 16 * PADK * 2));
            LDSM_X4(a0l[mt], aad + (uint32_t)(mt * 16 * PADK * 2) + (SM_AL - SM_AH));
        }
#pragma unroll
        for (int nt = 0; nt < 4; nt++)
            LDSM_X4(b0[nt], bad + (uint32_t)(nt * 16 * PADK * 2));
        // ---- prefetch ah(ks1)
#pragma unroll
        for (int mt = 0; mt < 2; mt++)
            LDSM_X4(a1h[mt], aad + (uint32_t)(mt * 16 * PADK * 2) + 32);
        // ---- h-term MMAs ks0
#pragma unroll
        for (int mt = 0; mt < 2; mt++)
#pragma unroll
            for (int n8 = 0; n8 < 8; n8++)
                MMA_F16(c[mt][n8], a0h[mt],
                        b0[n8 >> 1][(n8 & 1) * 2], b0[n8 >> 1][(n8 & 1) * 2 + 1]);
        // ---- prefetch b(ks1)
#pragma unroll
        for (int nt = 0; nt < 4; nt++)
            LDSM_X4(b1[nt], bad + (uint32_t)(nt * 16 * PADK * 2) + 32);
        // ---- l-term MMAs ks0
#pragma unroll
        for (int mt = 0; mt < 2; mt++)
#pragma unroll
            for (int n8 = 0; n8 < 8; n8++)
                MMA_F16(c[mt][n8], a0l[mt],
                        b0[n8 >> 1][(n8 & 1) * 2], b0[n8 >> 1][(n8 & 1) * 2 + 1]);
        // ---- al(ks1)
#pragma unroll
        for (int mt = 0; mt < 2; mt++)
            LDSM_X4(a1l[mt], aad + (uint32_t)(mt * 16 * PADK * 2) + (SM_AL - SM_AH) + 32);
        // ---- ks1 MMAs
#pragma unroll
        for (int mt = 0; mt < 2; mt++)
#pragma unroll
            for (int n8 = 0; n8 < 8; n8++)
                MMA_F16(c[mt][n8], a1h[mt],
                        b1[n8 >> 1][(n8 & 1) * 2], b1[n8 >> 1][(n8 & 1) * 2 + 1]);
#pragma unroll
        for (int mt = 0; mt < 2; mt++)
#pragma unroll
            for (int n8 = 0; n8 < 8; n8++)
                MMA_F16(c[mt][n8], a1l[mt],
                        b1[n8 >> 1][(n8 & 1) * 2], b1[n8 >> 1][(n8 & 1) * 2 + 1]);
    }

    if (MODE == 0) {
#pragma unroll
        for (int mt = 0; mt < 2; mt++) {
            int row0 = brow + wm + mt * 16 + (lane >> 2);
#pragma unroll
            for (int n8 = 0; n8 < 8; n8++) {
                int col = bcol + wn + n8 * 8 + (lane & 3) * 2;
                float bx = bias[col], by = bias[col + 1];
                *(float2*)(C + (size_t)row0 * N + col) =
                    make_float2(c[mt][n8][0] + bx, c[mt][n8][1] + by);
                *(float2*)(C + (size_t)(row0 + 8) * N + col) =
                    make_float2(c[mt][n8][2] + bx, c[mt][n8][3] + by);
            }
        }
    } else {
        // fused rope/pack: warp's 64-col block = one (comp, head); pairs
        // (n8, n8+4) hold dims (d, d+32).
        const int colbase = bcol + wn;
        const int comp = colbase >> 10;            // 0=q 1=k 2=v
        const int head = (colbase & 1023) >> 6;
#pragma unroll
        for (int mt = 0; mt < 2; mt++) {
#pragma unroll
            for (int r = 0; r < 2; r++) {
                int row = brow + wm + mt * 16 + (lane >> 2) + 8 * r;   // b*T + t
                int t = row & (TSEQ - 1);
                int bidx = row >> 11;
                size_t dst = ((size_t)(bidx * NHEAD + head) * TSEQ + t) * HD;
#pragma unroll
                for (int n8 = 0; n8 < 4; n8++) {
                    int d = n8 * 8 + 2 * (lane & 3);
                    float x1a = c[mt][n8][2 * r],     x1b = c[mt][n8][2 * r + 1];
                    float x2a = c[mt][n8 + 4][2 * r], x2b = c[mt][n8 + 4][2 * r + 1];
                    if (comp == 2) {
                        *(__half2*)(g_vp + dst + d)      = __floats2half2_rn(x1a, x1b);
                        *(__half2*)(g_vp + dst + d + 32) = __floats2half2_rn(x2a, x2b);
                    } else {
                        float4 cs = g_rope[t * 16 + (d >> 1)];
                        float o1a = x1a * cs.x - x2a * cs.y;
                        float o1b = x1b * cs.z - x2b * cs.w;
                        float o2a = x1a * cs.y + x2a * cs.x;
                        float o2b = x1b * cs.w + x2b * cs.z;
                        if (comp == 0) {
                            *(__half2*)(g_qr + dst + d) =
                                __floats2half2_rn(0.125f * o1a, 0.125f * o1b);
                            *(__half2*)(g_qr + dst + d + 32) =
                                __floats2half2_rn(0.125f * o2a, 0.125f * o2b);
                        } else {
                            *(__half2*)(g_kr + dst + d)      = __floats2half2_rn(o1a, o1b);
                            *(__half2*)(g_kr + dst + d + 32) = __floats2half2_rn(o2a, o2b);
                        }
                    }
                }
            }
        }
    }
}

// ---------------- fp32 -> fp16 hi/lo split (x input only) -------------------
__global__ void split_a(const float* __restrict__ src,
                        __half* __restrict__ h, __half* __restrict__ l, int n)
{
    int i = blockIdx.x * blockDim.x + threadIdx.x;
    if (i >= n) return;
    float v = src[i];
    __half hb = __float2half(v);
    h[i] = hb;
    l[i] = __float2half(v - __half2float(hb));
}

// W[K][N] -> Bt[N][K] fp16, smem-tiled transpose
__global__ void wconv(const float* __restrict__ W, __half* __restrict__ Bt, int K, int N)
{
    __shared__ float tile[32][33];
    int n0 = blockIdx.x * 32, k0 = blockIdx.y * 32;
    int tx = threadIdx.x & 31, ty = threadIdx.x >> 5;
#pragma unroll
    for (int r = 0; r < 4; r++)
        tile[ty + 8 * r][tx] = W[(size_t)(k0 + ty + 8 * r) * N + n0 + tx];
    __syncthreads();
#pragma unroll
    for (int r = 0; r < 4; r++)
        Bt[(size_t)(n0 + ty + 8 * r) * K + k0 + tx] = __float2half(tile[tx][ty + 8 * r]);
}

// ---------------- RoPE cos/sin table ----------------------------------------
__global__ void rope_table()
{
    int idx = blockIdx.x * blockDim.x + threadIdx.x;
    if (idx >= TSEQ * 16) return;
    int t = idx >> 4, pg = idx & 15;
    float c0, s0, c1, s1;
    {
        float e = (float)(2 * (2 * pg)) * (1.0f / 64.0f);
        float ang = (float)t * exp2f(-e * 13.2877123795494493f);
        sincosf(ang, &s0, &c0);
    }
    {
        float e = (float)(2 * (2 * pg + 1)) * (1.0f / 64.0f);
        float ang = (float)t * exp2f(-e * 13.2877123795494493f);
        sincosf(ang, &s1, &c1);
    }
    g_rope[idx] = make_float4(c0, s0, c1, s1);
}

// ---------------- flash attention via mma.sync -------------------------------
#define PADH 72
#define QS_BYTES (64 * PADH * 2)        // 9216
#define KS_OFF   QS_BYTES
#define KS_BYTES (320 * PADH * 2)       // 46080
#define VS_OFF   (KS_OFF + KS_BYTES)
#define ATTN_SMEM (VS_OFF + KS_BYTES)   // 101376

__global__ __launch_bounds__(256, 2)
void attn_kernel()
{
    extern __shared__ __align__(128) char asmem[];
    uint32_t sb = smem_u32(asmem);
    float* mgb = (float*)(asmem + KS_OFF);   // merge buffer aliases Ks

    const int tid = threadIdx.x, wid = tid >> 5, lane = tid & 31;
    const int b = blockIdx.z, h = blockIdx.y;
    const int t0 = blockIdx.x * 64;
    const int warp_m = wid & 3, warp_n = wid >> 2;

    const size_t bh = (size_t)(b * NHEAD + h) * TSEQ;

    {
        const __half* qsrc = g_qr + (bh + t0) * HD;
        for (int idx = tid; idx < 64 * 8; idx += 256) {
            int row = idx >> 3, cc = idx & 7;
            cp16(sb + (uint32_t)(row * PADH + cc * 8) * 2, qsrc + row * HD + cc * 8);
        }
    }
    {
        const __half* ksrc = g_kr + bh * HD;
        const __half* vsrc = g_vp + bh * HD;
        for (int idx = tid; idx < 320 * 8; idx += 256) {
            int kk = idx >> 3, cc = idx & 7;
            int kg = t0 - 128 + kk;
            kg = kg < 0 ? 0 : (kg > TSEQ - 1 ? TSEQ - 1 : kg);
            cp16(sb + KS_OFF + (uint32_t)(kk * PADH + cc * 8) * 2, ksrc + (size_t)kg * HD + cc * 8);
            cp16(sb + VS_OFF + (uint32_t)(kk * PADH + cc * 8) * 2, vsrc + (size_t)kg * HD + cc * 8);
        }
    }
    CP_COMMIT();
    CP_WAIT(0);
    __syncthreads();

    const int a_r = lane & 15;
    const int a_c = (lane >> 4) << 3;
    const int b_r = ((lane < 16) ? (lane & 7) : (8 + (lane & 7)));
    const int b_c = ((lane >> 3) & 1) << 3;
    const int qlo = t0 + warp_m * 16;
    const int qi0 = qlo + (lane >> 2);

    float m0 = -1e30f, m1 = -1e30f, l0 = 0.f, l1 = 0.f;
    float o[8][4];
#pragma unroll
    for (int t = 0; t < 8; t++)
#pragma unroll
        for (int j = 0; j < 4; j++) o[t][j] = 0.f;

    for (int c = 0; c < 5; c++) {
        int kk0 = 64 * c + 32 * warp_n;
        int kgb = t0 - 128 + kk0;
        if (kgb + 31 < qlo - WIN || kgb > qlo + 15 + WIN) continue;

        float cS[4][4];
#pragma unroll
        for (int i = 0; i < 4; i++)
#pragma unroll
            for (int j = 0; j < 4; j++) cS[i][j] = 0.f;
#pragma unroll
        for (int ks = 0; ks < 4; ks++) {
            uint32_t aq[4], bk0[4], bk1[4];
            LDSM_X4(aq, sb + (uint32_t)((warp_m * 16 + a_r) * PADH + ks * 16 + a_c) * 2);
            LDSM_X4(bk0, sb + KS_OFF + (uint32_t)((kk0 + b_r) * PADH + ks * 16 + b_c) * 2);
            LDSM_X4(bk1, sb + KS_OFF + (uint32_t)((kk0 + 16 + b_r) * PADH + ks * 16 + b_c) * 2);
            MMA_F16(cS[0], aq, bk0[0], bk0[1]);
            MMA_F16(cS[1], aq, bk0[2], bk0[3]);
            MMA_F16(cS[2], aq, bk1[0], bk1[1]);
            MMA_F16(cS[3], aq, bk1[2], bk1[3]);
        }

        float rmax0 = -1e30f, rmax1 = -1e30f;
#pragma unroll
        for (int n8 = 0; n8 < 4; n8++) {
            int jb = kgb + 8 * n8 + 2 * (lane & 3);
#pragma unroll
            for (int e = 0; e < 2; e++) {
                int j = jb + e;
                bool okj = (j >= 0) && (j < TSEQ);
                if (!(okj && j >= qi0 - WIN && j <= qi0 + WIN))         cS[n8][e]     = -1e30f;
                if (!(okj && j >= qi0 + 8 - WIN && j <= qi0 + 8 + WIN)) cS[n8][e + 2] = -1e30f;
            }
            rmax0 = fmaxf(rmax0, fmaxf(cS[n8][0], cS[n8][1]));
            rmax1 = fmaxf(rmax1, fmaxf(cS[n8][2], cS[n8][3]));
        }
        rmax0 = fmaxf(rmax0, __shfl_xor_sync(0xffffffffu, rmax0, 1));
        rmax0 = fmaxf(rmax0, __shfl_xor_sync(0xffffffffu, rmax0, 2));
        rmax1 = fmaxf(rmax1, __shfl_xor_sync(0xffffffffu, rmax1, 1));
        rmax1 = fmaxf(rmax1, __shfl_xor_sync(0xffffffffu, rmax1, 2));

        float mn0 = fmaxf(m0, rmax0), mn1 = fmaxf(m1, rmax1);
        float sc0 = __expf(m0 - mn0), sc1 = __expf(m1 - mn1);
        m0 = mn0; m1 = mn1;

        float ps0 = 0.f, ps1 = 0.f;
        uint32_t pa[4][2];
#pragma unroll
        for (int n8 = 0; n8 < 4; n8++) {
            float p0 = (cS[n8][0] < -1e29f) ? 0.f : __expf(cS[n8][0] - mn0);
            float p1 = (cS[n8][1] < -1e29f) ? 0.f : __expf(cS[n8][1] - mn0);
            float p2 = (cS[n8][2] < -1e29f) ? 0.f : __expf(cS[n8][2] - mn1);
            float p3 = (cS[n8][3] < -1e29f) ? 0.f : __expf(cS[n8][3] - mn1);
            ps0 += p0 + p1; ps1 += p2 + p3;
            pa[n8][0] = packh2(p0, p1);
            pa[n8][1] = packh2(p2, p3);
        }
        ps0 += __shfl_xor_sync(0xffffffffu, ps0, 1);
        ps0 += __shfl_xor_sync(0xffffffffu, ps0, 2);
        ps1 += __shfl_xor_sync(0xffffffffu, ps1, 1);
        ps1 += __shfl_xor_sync(0xffffffffu, ps1, 2);
        l0 = l0 * sc0 + ps0;
        l1 = l1 * sc1 + ps1;
#pragma unroll
        for (int t = 0; t < 8; t++) {
            o[t][0] *= sc0; o[t][1] *= sc0; o[t][2] *= sc1; o[t][3] *= sc1;
        }

#pragma unroll
        for (int kp = 0; kp < 2; kp++) {
            uint32_t a[4] = { pa[2 * kp][0], pa[2 * kp][1], pa[2 * kp + 1][0], pa[2 * kp + 1][1] };
#pragma unroll
            for (int np = 0; np < 4; np++) {
                uint32_t bv[4];
                LDSM_X4_T(bv, sb + VS_OFF +
                    (uint32_t)((kk0 + kp * 16 + a_r) * PADH + np * 16 + a_c) * 2);
                MMA_F16(o[2 * np],     a, bv[0], bv[1]);
                MMA_F16(o[2 * np + 1], a, bv[2], bv[3]);
            }
        }
    }

    __syncthreads();
    float* ob = mgb + (warp_m * 32 + lane) * 33;
    float2* mlb = (float2*)(mgb + 4 * 32 * 33);
    if (warp_n == 1) {
#pragma unroll
        for (int t = 0; t < 8; t++)
#pragma unroll
            for (int j = 0; j < 4; j++) ob[4 * t + j] = o[t][j];
        if ((lane & 3) == 0) {
            mlb[warp_m * 16 + (lane >> 2)]     = make_float2(m0, l0);
            mlb[warp_m * 16 + 8 + (lane >> 2)] = make_float2(m1, l1);
        }
    }
    __syncthreads();
    if (warp_n == 0) {
        float2 M0 = mlb[warp_m * 16 + (lane >> 2)];
        float2 M1 = mlb[warp_m * 16 + 8 + (lane >> 2)];
        float mm0 = fmaxf(m0, M0.x), mm1 = fmaxf(m1, M1.x);
        float w00 = __expf(m0 - mm0), w01 = __expf(M0.x - mm0);
        float w10 = __expf(m1 - mm1), w11 = __expf(M1.x - mm1);
        float inv0 = 1.0f / (l0 * w00 + M0.y * w01);
        float inv1 = 1.0f / (l1 * w10 + M1.y * w11);
        size_t r0 = (size_t)(b * TSEQ + qlo + (lane >> 2)) * DMODEL;
        size_t r1 = r0 + 8 * DMODEL;
#pragma unroll
        for (int t = 0; t < 8; t++) {
            int col = h * HD + t * 8 + 2 * (lane & 3);
            float v0 = (o[t][0] * w00 + ob[4 * t + 0] * w01) * inv0;
            float v1 = (o[t][1] * w00 + ob[4 * t + 1] * w01) * inv0;
            float v2 = (o[t][2] * w10 + ob[4 * t + 2] * w11) * inv1;
            float v3 = (o[t][3] * w10 + ob[4 * t + 3] * w11) * inv1;
            __half h0 = __float2half(v0), h1 = __float2half(v1);
            __half h2 = __float2half(v2), h3 = __float2half(v3);
            *(__half2*)(g_Ah + r0 + col) = __halves2half2(h0, h1);
            *(__half2*)(g_Ah + r1 + col) = __halves2half2(h2, h3);
            *(__half2*)(g_Al + r0 + col) = __halves2half2(
                __float2half(v0 - __half2float(h0)), __float2half(v1 - __half2float(h1)));
            *(__half2*)(g_Al + r1 + col) = __halves2half2(
                __float2half(v2 - __half2float(h2)), __float2half(v3 - __half2float(h3)));
        }
    }
}

// ---------------------------------------------------------------------------
extern "C" void kernel_launch(void* const* d_in, const int* in_sizes, int n_in,
                              void* d_out, int out_size)
{
    const float* x    = (const float*)d_in[0];
    const float* Wqkv = (const float*)d_in[1];
    const float* Wout = (const float*)d_in[2];
    const float* bout = (const float*)d_in[3];
    float* out = (float*)d_out;

    __half *Ah, *Al, *Bh;
    cudaGetSymbolAddress((void**)&Ah, g_Ah);
    cudaGetSymbolAddress((void**)&Al, g_Al);
    cudaGetSymbolAddress((void**)&Bh, g_Bh);

    cudaFuncSetAttribute(gemm_mma<0>, cudaFuncAttributeMaxDynamicSharedMemorySize, GEMM_SMEM);
    cudaFuncSetAttribute(gemm_mma<1>, cudaFuncAttributeMaxDynamicSharedMemorySize, GEMM_SMEM);
    cudaFuncSetAttribute(attn_kernel, cudaFuncAttributeMaxDynamicSharedMemorySize, ATTN_SMEM);

    rope_table<<<(TSEQ * 16 + 255) / 256, 256>>>();

    split_a<<<(ROWS * DMODEL + 511) / 512, 512>>>(x, Ah, Al, ROWS * DMODEL);
    wconv<<<dim3(QKVCOLS / 32, DMODEL / 32), 256>>>(Wqkv, Bh, DMODEL, QKVCOLS);
    // QKV projection with fused rope/pack epilogue
    gemm_mma<1><<<dim3(QKVCOLS / BN, ROWS / BM), 256, GEMM_SMEM>>>(
        Ah, Al, Bh, nullptr, ROWS, QKVCOLS, DMODEL, nullptr);

    attn_kernel<<<dim3(TSEQ / 64, NHEAD, NB), 256, ATTN_SMEM>>>();

    wconv<<<dim3(DMODEL / 32, DMODEL / 32), 256>>>(Wout, Bh, DMODEL, DMODEL);
    gemm_mma<0><<<dim3(DMODEL / BN, ROWS / BM), 256, GEMM_SMEM>>>(
        Ah, Al, Bh, out, ROWS, DMODEL, DMODEL, bout);
}

// round 9
// speedup vs baseline: 1.1215x; 1.1215x over previous
#include <cuda_runtime.h>
#include <cuda_fp16.h>
#include <math.h>
#include <stdint.h>

#define NB      4
#define TSEQ    2048
#define NHEAD   16
#define HD      64
#define DMODEL  1024
#define ROWS    (NB * TSEQ)          // 8192
#define QKVCOLS (3 * DMODEL)         // 3072
#define WIN     128

// ---------------- scratch (allocation-free rule: device globals) ----------
__device__ __align__(16) __half g_Ah[ROWS   * DMODEL];
__device__ __align__(16) __half g_Al[ROWS   * DMODEL];
__device__ __align__(16) __half g_Bh[QKVCOLS * DMODEL];  // [N][K] transposed fp16
__device__ __align__(16) __half g_qr[ROWS * DMODEL];     // [b,h][t][d] roped+scaled Q
__device__ __align__(16) __half g_kr[ROWS * DMODEL];     // [b,h][t][d] roped K
__device__ __align__(16) __half g_vp[ROWS * DMODEL];     // [b,h][t][d] packed V
__device__ float4 g_rope[TSEQ * 16];  // (t, pg): cos/sin for freqs 2pg, 2pg+1

// ---------------- PTX helpers ---------------------------------------------
__device__ __forceinline__ uint32_t smem_u32(const void* p) {
    uint32_t a;
    asm("{ .reg .u64 t; cvta.to.shared.u64 t, %1; cvt.u32.u64 %0, t; }" : "=r"(a) : "l"(p));
    return a;
}
__device__ __forceinline__ void cp16(uint32_t dst, const void* src) {
    asm volatile("cp.async.cg.shared.global [%0], [%1], 16;" :: "r"(dst), "l"(src));
}
#define CP_COMMIT() asm volatile("cp.async.commit_group;" ::: "memory")
#define CP_WAIT(n)  asm volatile("cp.async.wait_group %0;" :: "n"(n) : "memory")

#define LDSM_X4(r, addr) \
    asm volatile("ldmatrix.sync.aligned.m8n8.x4.shared.b16 {%0,%1,%2,%3}, [%4];" \
        : "=r"((r)[0]), "=r"((r)[1]), "=r"((r)[2]), "=r"((r)[3]) : "r"(addr))
#define LDSM_X4_T(r, addr) \
    asm volatile("ldmatrix.sync.aligned.m8n8.x4.trans.shared.b16 {%0,%1,%2,%3}, [%4];" \
        : "=r"((r)[0]), "=r"((r)[1]), "=r"((r)[2]), "=r"((r)[3]) : "r"(addr))

#define MMA_F16(c, a, b0, b1) \
    asm volatile("mma.sync.aligned.m16n8k16.row.col.f32.f16.f16.f32 " \
        "{%0,%1,%2,%3}, {%4,%5,%6,%7}, {%8,%9}, {%0,%1,%2,%3};" \
        : "+f"((c)[0]), "+f"((c)[1]), "+f"((c)[2]), "+f"((c)[3]) \
        : "r"((a)[0]), "r"((a)[1]), "r"((a)[2]), "r"((a)[3]), "r"(b0), "r"(b1))

__device__ __forceinline__ uint32_t packh2(float a, float b) {
    __half2 h = __floats2half2_rn(a, b);
    return *reinterpret_cast<uint32_t*>(&h);
}

// ---------------- mma.sync GEMM: C = A[M,K]*Bt[N,K]^T, fp16 2-term A -------
// CTA 128x128, 8 warps (4m x 2n), warp 32x64. BK=64, 2-stage cp.async,
// ONE barrier per chunk (16 total). MODE 0: fp32 C + bias. MODE 1: fused
// rope/pack epilogue -> g_qr/g_kr/g_vp.
#define BM 128
#define BN 128
#define BK 64
#define PADK 72                       // 64 + 8 pad halves: 144B rows, ldsm conflict-free
#define MAT_BYTES (128 * PADK * 2)    // 18432
#define SM_AH 0
#define SM_AL (1 * MAT_BYTES)
#define SM_BH (2 * MAT_BYTES)
#define STAGE_BYTES (3 * MAT_BYTES)   // 55296
#define GEMM_SMEM (2 * STAGE_BYTES)   // 110592 (2 CTA/SM: 221184 <= 228KB)

__device__ __forceinline__ void load_chunk(
    uint32_t sb, const __half* __restrict__ Ah, const __half* __restrict__ Al,
    const __half* __restrict__ Bh,
    int brow, int bcol, int K, int kc, int stage, int tid)
{
    uint32_t base = sb + stage * STAGE_BYTES;
#pragma unroll
    for (int t = 0; t < 4; t++) {
        int idx = tid + t * 256;          // 0..1023
        int row = idx >> 3;               // 0..127
        int c16 = idx & 7;                // 16B chunk in 128B row
        uint32_t so = (uint32_t)(row * (PADK * 2) + c16 * 16);
        size_t ga = (size_t)(brow + row) * K + kc + c16 * 8;
        size_t gb = (size_t)(bcol + row) * K + kc + c16 * 8;
        cp16(base + SM_AH + so, Ah + ga);
        cp16(base + SM_AL + so, Al + ga);
        cp16(base + SM_BH + so, Bh + gb);
    }
}

template <int MODE>
__global__ __launch_bounds__(256, 2)
void gemm_mma(const __half* __restrict__ Ah, const __half* __restrict__ Al,
              const __half* __restrict__ Bh,
              float* __restrict__ C, int M, int N, int K,
              const float* __restrict__ bias)
{
    extern __shared__ __align__(128) char smem[];
    uint32_t sb = smem_u32(smem);
    const int tid  = threadIdx.x;
    const int wid  = tid >> 5;
    const int lane = tid & 31;
    const int wm = (wid & 3) * 32;      // 4 warp-rows
    const int wn = (wid >> 2) * 64;     // 2 warp-cols
    const int brow = blockIdx.y * BM, bcol = blockIdx.x * BN;

    float c[2][8][4];
#pragma unroll
    for (int i = 0; i < 2; i++)
#pragma unroll
        for (int j = 0; j < 8; j++)
#pragma unroll
            for (int r = 0; r < 4; r++) c[i][j][r] = 0.0f;

    const int nchunks = K / BK;         // 16
    load_chunk(sb, Ah, Al, Bh, brow, bcol, K, 0, 0, tid);
    CP_COMMIT();

    const int a_r = lane & 15;
    const int a_c = (lane >> 4) << 3;
    const int b_r = ((lane < 16) ? (lane & 7) : (8 + (lane & 7)));
    const int b_c = ((lane >> 3) & 1) << 3;

    for (int ch = 0; ch < nchunks; ch++) {
        CP_WAIT(0);                      // chunk ch's data landed
        __syncthreads();                 // visible to all; prev stage vacated
        if (ch + 1 < nchunks) {          // prefetch next chunk (hidden under compute)
            load_chunk(sb, Ah, Al, Bh, brow, bcol, K, (ch + 1) * BK, (ch + 1) & 1, tid);
            CP_COMMIT();
        }
        uint32_t stb = sb + (ch & 1) * STAGE_BYTES;
#pragma unroll
        for (int ks = 0; ks < 4; ks++) {
            const int kb = ks * 16;
            uint32_t ah[2][4], al[2][4], bh[4][4];
#pragma unroll
            for (int mt = 0; mt < 2; mt++) {
                uint32_t ad = stb + SM_AH +
                    (uint32_t)((wm + mt * 16 + a_r) * (PADK * 2) + (kb + a_c) * 2);
                LDSM_X4(ah[mt], ad);
                LDSM_X4(al[mt], ad + (SM_AL - SM_AH));
            }
#pragma unroll
            for (int nt = 0; nt < 4; nt++) {
                uint32_t bd = stb + SM_BH +
                    (uint32_t)((wn + nt * 16 + b_r) * (PADK * 2) + (kb + b_c) * 2);
                LDSM_X4(bh[nt], bd);
            }
            // all h-term MMAs, then l-term: no back-to-back same accumulator
#pragma unroll
            for (int mt = 0; mt < 2; mt++)
#pragma unroll
                for (int n8 = 0; n8 < 8; n8++)
                    MMA_F16(c[mt][n8], ah[mt],
                            bh[n8 >> 1][(n8 & 1) * 2], bh[n8 >> 1][(n8 & 1) * 2 + 1]);
#pragma unroll
            for (int mt = 0; mt < 2; mt++)
#pragma unroll
                for (int n8 = 0; n8 < 8; n8++)
                    MMA_F16(c[mt][n8], al[mt],
                            bh[n8 >> 1][(n8 & 1) * 2], bh[n8 >> 1][(n8 & 1) * 2 + 1]);
        }
    }

    if (MODE == 0) {
#pragma unroll
        for (int mt = 0; mt < 2; mt++) {
            int row0 = brow + wm + mt * 16 + (lane >> 2);
#pragma unroll
            for (int n8 = 0; n8 < 8; n8++) {
                int col = bcol + wn + n8 * 8 + (lane & 3) * 2;
                float bx = bias[col], by = bias[col + 1];
                *(float2*)(C + (size_t)row0 * N + col) =
                    make_float2(c[mt][n8][0] + bx, c[mt][n8][1] + by);
                *(float2*)(C + (size_t)(row0 + 8) * N + col) =
                    make_float2(c[mt][n8][2] + bx, c[mt][n8][3] + by);
            }
        }
    } else {
        // fused rope/pack: warp's 64-col block = one (comp, head); pairs
        // (n8, n8+4) hold dims (d, d+32).
        const int colbase = bcol + wn;
        const int comp = colbase >> 10;            // 0=q 1=k 2=v
        const int head = (colbase & 1023) >> 6;
#pragma unroll
        for (int mt = 0; mt < 2; mt++) {
#pragma unroll
            for (int r = 0; r < 2; r++) {
                int row = brow + wm + mt * 16 + (lane >> 2) + 8 * r;   // b*T + t
                int t = row & (TSEQ - 1);
                int bidx = row >> 11;
                size_t dst = ((size_t)(bidx * NHEAD + head) * TSEQ + t) * HD;
#pragma unroll
                for (int n8 = 0; n8 < 4; n8++) {
                    int d = n8 * 8 + 2 * (lane & 3);
                    float x1a = c[mt][n8][2 * r],     x1b = c[mt][n8][2 * r + 1];
                    float x2a = c[mt][n8 + 4][2 * r], x2b = c[mt][n8 + 4][2 * r + 1];
                    if (comp == 2) {
                        *(__half2*)(g_vp + dst + d)      = __floats2half2_rn(x1a, x1b);
                        *(__half2*)(g_vp + dst + d + 32) = __floats2half2_rn(x2a, x2b);
                    } else {
                        float4 cs = g_rope[t * 16 + (d >> 1)];
                        float o1a = x1a * cs.x - x2a * cs.y;
                        float o1b = x1b * cs.z - x2b * cs.w;
                        float o2a = x1a * cs.y + x2a * cs.x;
                        float o2b = x1b * cs.w + x2b * cs.z;
                        if (comp == 0) {
                            *(__half2*)(g_qr + dst + d) =
                                __floats2half2_rn(0.125f * o1a, 0.125f * o1b);
                            *(__half2*)(g_qr + dst + d + 32) =
                                __floats2half2_rn(0.125f * o2a, 0.125f * o2b);
                        } else {
                            *(__half2*)(g_kr + dst + d)      = __floats2half2_rn(o1a, o1b);
                            *(__half2*)(g_kr + dst + d + 32) = __floats2half2_rn(o2a, o2b);
                        }
                    }
                }
            }
        }
    }
}

// ---------------- fp32 -> fp16 hi/lo split (x input only) -------------------
__global__ void split_a(const float* __restrict__ src,
                        __half* __restrict__ h, __half* __restrict__ l, int n)
{
    int i = blockIdx.x * blockDim.x + threadIdx.x;
    if (i >= n) return;
    float v = src[i];
    __half hb = __float2half(v);
    h[i] = hb;
    l[i] = __float2half(v - __half2float(hb));
}

// W[K][N] -> Bt[N][K] fp16, smem-tiled transpose
__global__ void wconv(const float* __restrict__ W, __half* __restrict__ Bt, int K, int N)
{
    __shared__ float tile[32][33];
    int n0 = blockIdx.x * 32, k0 = blockIdx.y * 32;
    int tx = threadIdx.x & 31, ty = threadIdx.x >> 5;
#pragma unroll
    for (int r = 0; r < 4; r++)
        tile[ty + 8 * r][tx] = W[(size_t)(k0 + ty + 8 * r) * N + n0 + tx];
    __syncthreads();
#pragma unroll
    for (int r = 0; r < 4; r++)
        Bt[(size_t)(n0 + ty + 8 * r) * K + k0 + tx] = __float2half(tile[tx][ty + 8 * r]);
}

// ---------------- RoPE cos/sin table ----------------------------------------
__global__ void rope_table()
{
    int idx = blockIdx.x * blockDim.x + threadIdx.x;
    if (idx >= TSEQ * 16) return;
    int t = idx >> 4, pg = idx & 15;
    float c0, s0, c1, s1;
    {
        float e = (float)(2 * (2 * pg)) * (1.0f / 64.0f);
        float ang = (float)t * exp2f(-e * 13.2877123795494493f);
        sincosf(ang, &s0, &c0);
    }
    {
        float e = (float)(2 * (2 * pg + 1)) * (1.0f / 64.0f);
        float ang = (float)t * exp2f(-e * 13.2877123795494493f);
        sincosf(ang, &s1, &c1);
    }
    g_rope[idx] = make_float4(c0, s0, c1, s1);
}

// ---------------- flash attention via mma.sync -------------------------------
#define PADH 72
#define QS_BYTES (64 * PADH * 2)        // 9216
#define KS_OFF   QS_BYTES
#define KS_BYTES (320 * PADH * 2)       // 46080
#define VS_OFF   (KS_OFF + KS_BYTES)
#define ATTN_SMEM (VS_OFF + KS_BYTES)   // 101376

__global__ __launch_bounds__(256, 2)
void attn_kernel()
{
    extern __shared__ __align__(128) char asmem[];
    uint32_t sb = smem_u32(asmem);
    float* mgb = (float*)(asmem + KS_OFF);   // merge buffer aliases Ks

    const int tid = threadIdx.x, wid = tid >> 5, lane = tid & 31;
    const int b = blockIdx.z, h = blockIdx.y;
    const int t0 = blockIdx.x * 64;
    const int warp_m = wid & 3, warp_n = wid >> 2;

    const size_t bh = (size_t)(b * NHEAD + h) * TSEQ;

    {
        const __half* qsrc = g_qr + (bh + t0) * HD;
        for (int idx = tid; idx < 64 * 8; idx += 256) {
            int row = idx >> 3, cc = idx & 7;
            cp16(sb + (uint32_t)(row * PADH + cc * 8) * 2, qsrc + row * HD + cc * 8);
        }
    }
    {
        const __half* ksrc = g_kr + bh * HD;
        const __half* vsrc = g_vp + bh * HD;
        for (int idx = tid; idx < 320 * 8; idx += 256) {
            int kk = idx >> 3, cc = idx & 7;
            int kg = t0 - 128 + kk;
            kg = kg < 0 ? 0 : (kg > TSEQ - 1 ? TSEQ - 1 : kg);
            cp16(sb + KS_OFF + (uint32_t)(kk * PADH + cc * 8) * 2, ksrc + (size_t)kg * HD + cc * 8);
            cp16(sb + VS_OFF + (uint32_t)(kk * PADH + cc * 8) * 2, vsrc + (size_t)kg * HD + cc * 8);
        }
    }
    CP_COMMIT();
    CP_WAIT(0);
    __syncthreads();

    const int a_r = lane & 15;
    const int a_c = (lane >> 4) << 3;
    const int b_r = ((lane < 16) ? (lane & 7) : (8 + (lane & 7)));
    const int b_c = ((lane >> 3) & 1) << 3;
    const int qlo = t0 + warp_m * 16;
    const int qi0 = qlo + (lane >> 2);

    float m0 = -1e30f, m1 = -1e30f, l0 = 0.f, l1 = 0.f;
    float o[8][4];
#pragma unroll
    for (int t = 0; t < 8; t++)
#pragma unroll
        for (int j = 0; j < 4; j++) o[t][j] = 0.f;

    for (int c = 0; c < 5; c++) {
        int kk0 = 64 * c + 32 * warp_n;
        int kgb = t0 - 128 + kk0;
        if (kgb + 31 < qlo - WIN || kgb > qlo + 15 + WIN) continue;

        float cS[4][4];
#pragma unroll
        for (int i = 0; i < 4; i++)
#pragma unroll
            for (int j = 0; j < 4; j++) cS[i][j] = 0.f;
#pragma unroll
        for (int ks = 0; ks < 4; ks++) {
            uint32_t aq[4], bk0[4], bk1[4];
            LDSM_X4(aq, sb + (uint32_t)((warp_m * 16 + a_r) * PADH + ks * 16 + a_c) * 2);
            LDSM_X4(bk0, sb + KS_OFF + (uint32_t)((kk0 + b_r) * PADH + ks * 16 + b_c) * 2);
            LDSM_X4(bk1, sb + KS_OFF + (uint32_t)((kk0 + 16 + b_r) * PADH + ks * 16 + b_c) * 2);
            MMA_F16(cS[0], aq, bk0[0], bk0[1]);
            MMA_F16(cS[1], aq, bk0[2], bk0[3]);
            MMA_F16(cS[2], aq, bk1[0], bk1[1]);
            MMA_F16(cS[3], aq, bk1[2], bk1[3]);
        }

        float rmax0 = -1e30f, rmax1 = -1e30f;
#pragma unroll
        for (int n8 = 0; n8 < 4; n8++) {
            int jb = kgb + 8 * n8 + 2 * (lane & 3);
#pragma unroll
            for (int e = 0; e < 2; e++) {
                int j = jb + e;
                bool okj = (j >= 0) && (j < TSEQ);
                if (!(okj && j >= qi0 - WIN && j <= qi0 + WIN))         cS[n8][e]     = -1e30f;
                if (!(okj && j >= qi0 + 8 - WIN && j <= qi0 + 8 + WIN)) cS[n8][e + 2] = -1e30f;
            }
            rmax0 = fmaxf(rmax0, fmaxf(cS[n8][0], cS[n8][1]));
            rmax1 = fmaxf(rmax1, fmaxf(cS[n8][2], cS[n8][3]));
        }
        rmax0 = fmaxf(rmax0, __shfl_xor_sync(0xffffffffu, rmax0, 1));
        rmax0 = fmaxf(rmax0, __shfl_xor_sync(0xffffffffu, rmax0, 2));
        rmax1 = fmaxf(rmax1, __shfl_xor_sync(0xffffffffu, rmax1, 1));
        rmax1 = fmaxf(rmax1, __shfl_xor_sync(0xffffffffu, rmax1, 2));

        float mn0 = fmaxf(m0, rmax0), mn1 = fmaxf(m1, rmax1);
        float sc0 = __expf(m0 - mn0), sc1 = __expf(m1 - mn1);
        m0 = mn0; m1 = mn1;

        float ps0 = 0.f, ps1 = 0.f;
        uint32_t pa[4][2];
#pragma unroll
        for (int n8 = 0; n8 < 4; n8++) {
            float p0 = (cS[n8][0] < -1e29f) ? 0.f : __expf(cS[n8][0] - mn0);
            float p1 = (cS[n8][1] < -1e29f) ? 0.f : __expf(cS[n8][1] - mn0);
            float p2 = (cS[n8][2] < -1e29f) ? 0.f : __expf(cS[n8][2] - mn1);
            float p3 = (cS[n8][3] < -1e29f) ? 0.f : __expf(cS[n8][3] - mn1);
            ps0 += p0 + p1; ps1 += p2 + p3;
            pa[n8][0] = packh2(p0, p1);
            pa[n8][1] = packh2(p2, p3);
        }
        ps0 += __shfl_xor_sync(0xffffffffu, ps0, 1);
        ps0 += __shfl_xor_sync(0xffffffffu, ps0, 2);
        ps1 += __shfl_xor_sync(0xffffffffu, ps1, 1);
        ps1 += __shfl_xor_sync(0xffffffffu, ps1, 2);
        l0 = l0 * sc0 + ps0;
        l1 = l1 * sc1 + ps1;
#pragma unroll
        for (int t = 0; t < 8; t++) {
            o[t][0] *= sc0; o[t][1] *= sc0; o[t][2] *= sc1; o[t][3] *= sc1;
        }

#pragma unroll
        for (int kp = 0; kp < 2; kp++) {
            uint32_t a[4] = { pa[2 * kp][0], pa[2 * kp][1], pa[2 * kp + 1][0], pa[2 * kp + 1][1] };
#pragma unroll
            for (int np = 0; np < 4; np++) {
                uint32_t bv[4];
                LDSM_X4_T(bv, sb + VS_OFF +
                    (uint32_t)((kk0 + kp * 16 + a_r) * PADH + np * 16 + a_c) * 2);
                MMA_F16(o[2 * np],     a, bv[0], bv[1]);
                MMA_F16(o[2 * np + 1], a, bv[2], bv[3]);
            }
        }
    }

    __syncthreads();
    float* ob = mgb + (warp_m * 32 + lane) * 33;
    float2* mlb = (float2*)(mgb + 4 * 32 * 33);
    if (warp_n == 1) {
#pragma unroll
        for (int t = 0; t < 8; t++)
#pragma unroll
            for (int j = 0; j < 4; j++) ob[4 * t + j] = o[t][j];
        if ((lane & 3) == 0) {
            mlb[warp_m * 16 + (lane >> 2)]     = make_float2(m0, l0);
            mlb[warp_m * 16 + 8 + (lane >> 2)] = make_float2(m1, l1);
        }
    }
    __syncthreads();
    if (warp_n == 0) {
        float2 M0 = mlb[warp_m * 16 + (lane >> 2)];
        float2 M1 = mlb[warp_m * 16 + 8 + (lane >> 2)];
        float mm0 = fmaxf(m0, M0.x), mm1 = fmaxf(m1, M1.x);
        float w00 = __expf(m0 - mm0), w01 = __expf(M0.x - mm0);
        float w10 = __expf(m1 - mm1), w11 = __expf(M1.x - mm1);
        float inv0 = 1.0f / (l0 * w00 + M0.y * w01);
        float inv1 = 1.0f / (l1 * w10 + M1.y * w11);
        size_t r0 = (size_t)(b * TSEQ + qlo + (lane >> 2)) * DMODEL;
        size_t r1 = r0 + 8 * DMODEL;
#pragma unroll
        for (int t = 0; t < 8; t++) {
            int col = h * HD + t * 8 + 2 * (lane & 3);
            float v0 = (o[t][0] * w00 + ob[4 * t + 0] * w01) * inv0;
            float v1 = (o[t][1] * w00 + ob[4 * t + 1] * w01) * inv0;
            float v2 = (o[t][2] * w10 + ob[4 * t + 2] * w11) * inv1;
            float v3 = (o[t][3] * w10 + ob[4 * t + 3] * w11) * inv1;
            __half h0 = __float2half(v0), h1 = __float2half(v1);
            __half h2 = __float2half(v2), h3 = __float2half(v3);
            *(__half2*)(g_Ah + r0 + col) = __halves2half2(h0, h1);
            *(__half2*)(g_Ah + r1 + col) = __halves2half2(h2, h3);
            *(__half2*)(g_Al + r0 + col) = __halves2half2(
                __float2half(v0 - __half2float(h0)), __float2half(v1 - __half2float(h1)));
            *(__half2*)(g_Al + r1 + col) = __halves2half2(
                __float2half(v2 - __half2float(h2)), __float2half(v3 - __half2float(h3)));
        }
    }
}

// ---------------------------------------------------------------------------
extern "C" void kernel_launch(void* const* d_in, const int* in_sizes, int n_in,
                              void* d_out, int out_size)
{
    const float* x    = (const float*)d_in[0];
    const float* Wqkv = (const float*)d_in[1];
    const float* Wout = (const float*)d_in[2];
    const float* bout = (const float*)d_in[3];
    float* out = (float*)d_out;

    __half *Ah, *Al, *Bh;
    cudaGetSymbolAddress((void**)&Ah, g_Ah);
    cudaGetSymbolAddress((void**)&Al, g_Al);
    cudaGetSymbolAddress((void**)&Bh, g_Bh);

    cudaFuncSetAttribute(gemm_mma<0>, cudaFuncAttributeMaxDynamicSharedMemorySize, GEMM_SMEM);
    cudaFuncSetAttribute(gemm_mma<1>, cudaFuncAttributeMaxDynamicSharedMemorySize, GEMM_SMEM);
    cudaFuncSetAttribute(attn_kernel, cudaFuncAttributeMaxDynamicSharedMemorySize, ATTN_SMEM);

    rope_table<<<(TSEQ * 16 + 255) / 256, 256>>>();

    split_a<<<(ROWS * DMODEL + 511) / 512, 512>>>(x, Ah, Al, ROWS * DMODEL);
    wconv<<<dim3(QKVCOLS / 32, DMODEL / 32), 256>>>(Wqkv, Bh, DMODEL, QKVCOLS);
    // QKV projection with fused rope/pack epilogue
    gemm_mma<1><<<dim3(QKVCOLS / BN, ROWS / BM), 256, GEMM_SMEM>>>(
        Ah, Al, Bh, nullptr, ROWS, QKVCOLS, DMODEL, nullptr);

    attn_kernel<<<dim3(TSEQ / 64, NHEAD, NB), 256, ATTN_SMEM>>>();

    wconv<<<dim3(DMODEL / 32, DMODEL / 32), 256>>>(Wout, Bh, DMODEL, DMODEL);
    gemm_mma<0><<<dim3(DMODEL / BN, ROWS / BM), 256, GEMM_SMEM>>>(
        Ah, Al, Bh, out, ROWS, DMODEL, DMODEL, bout);
}

// round 10
// speedup vs baseline: 1.2078x; 1.0769x over previous
#include <cuda_runtime.h>
#include <cuda_fp16.h>
#include <math.h>
#include <stdint.h>

#define NB      4
#define TSEQ    2048
#define NHEAD   16
#define HD      64
#define DMODEL  1024
#define ROWS    (NB * TSEQ)          // 8192
#define QKVCOLS (3 * DMODEL)         // 3072
#define WIN     128

// ---------------- scratch (allocation-free rule: device globals) ----------
__device__ __align__(16) __half g_Ah[ROWS   * DMODEL];
__device__ __align__(16) __half g_Al[ROWS   * DMODEL];
__device__ __align__(16) __half g_Bh[QKVCOLS * DMODEL];  // [N][K] transposed fp16
__device__ __align__(16) __half g_qr[ROWS * DMODEL];     // [b,h][t][d] roped+scaled Q (hi)
__device__ __align__(16) __half g_ql[ROWS * DMODEL];     // [b,h][t][d] roped+scaled Q (lo)
__device__ __align__(16) __half g_kr[ROWS * DMODEL];     // [b,h][t][d] roped K
__device__ __align__(16) __half g_vp[ROWS * DMODEL];     // [b,h][t][d] packed V
__device__ float4 g_rope[TSEQ * 16];  // (t, pg): cos/sin for freqs 2pg, 2pg+1

// ---------------- PTX helpers ---------------------------------------------
__device__ __forceinline__ uint32_t smem_u32(const void* p) {
    uint32_t a;
    asm("{ .reg .u64 t; cvta.to.shared.u64 t, %1; cvt.u32.u64 %0, t; }" : "=r"(a) : "l"(p));
    return a;
}
__device__ __forceinline__ void cp16(uint32_t dst, const void* src) {
    asm volatile("cp.async.cg.shared.global [%0], [%1], 16;" :: "r"(dst), "l"(src));
}
#define CP_COMMIT() asm volatile("cp.async.commit_group;" ::: "memory")
#define CP_WAIT(n)  asm volatile("cp.async.wait_group %0;" :: "n"(n) : "memory")

#define LDSM_X4(r, addr) \
    asm volatile("ldmatrix.sync.aligned.m8n8.x4.shared.b16 {%0,%1,%2,%3}, [%4];" \
        : "=r"((r)[0]), "=r"((r)[1]), "=r"((r)[2]), "=r"((r)[3]) : "r"(addr))
#define LDSM_X4_T(r, addr) \
    asm volatile("ldmatrix.sync.aligned.m8n8.x4.trans.shared.b16 {%0,%1,%2,%3}, [%4];" \
        : "=r"((r)[0]), "=r"((r)[1]), "=r"((r)[2]), "=r"((r)[3]) : "r"(addr))

#define MMA_F16(c, a, b0, b1) \
    asm volatile("mma.sync.aligned.m16n8k16.row.col.f32.f16.f16.f32 " \
        "{%0,%1,%2,%3}, {%4,%5,%6,%7}, {%8,%9}, {%0,%1,%2,%3};" \
        : "+f"((c)[0]), "+f"((c)[1]), "+f"((c)[2]), "+f"((c)[3]) \
        : "r"((a)[0]), "r"((a)[1]), "r"((a)[2]), "r"((a)[3]), "r"(b0), "r"(b1))

__device__ __forceinline__ uint32_t packh2(float a, float b) {
    __half2 h = __floats2half2_rn(a, b);
    return *reinterpret_cast<uint32_t*>(&h);
}

// ---------------- mma.sync GEMM: C = A[M,K]*Bt[N,K]^T -----------------------
// CTA 128x128, 8 warps (4m x 2n), warp 32x64. BK=64, 2-stage cp.async,
// one barrier per chunk. SPLIT=1: A = Ah + Al (2-term). SPLIT=0: A = Ah only.
// MODE 0: fp32 C + bias. MODE 1: fused rope/pack epilogue -> g_qr/g_ql/g_kr/g_vp.
#define BM 128
#define BN 128
#define BK 64
#define PADK 72
#define MAT_BYTES (128 * PADK * 2)    // 18432

template <int SPLIT>
__device__ __forceinline__ void load_chunk(
    uint32_t sb, const __half* __restrict__ Ah, const __half* __restrict__ Al,
    const __half* __restrict__ Bh,
    int brow, int bcol, int K, int kc, int stage, int tid)
{
    const uint32_t STAGE_B = (SPLIT ? 3 : 2) * MAT_BYTES;
    const uint32_t SM_B = (SPLIT ? 2 : 1) * MAT_BYTES;
    uint32_t base = sb + stage * STAGE_B;
#pragma unroll
    for (int t = 0; t < 4; t++) {
        int idx = tid + t * 256;
        int row = idx >> 3;
        int c16 = idx & 7;
        uint32_t so = (uint32_t)(row * (PADK * 2) + c16 * 16);
        size_t ga = (size_t)(brow + row) * K + kc + c16 * 8;
        size_t gb = (size_t)(bcol + row) * K + kc + c16 * 8;
        cp16(base + so, Ah + ga);
        if (SPLIT) cp16(base + MAT_BYTES + so, Al + ga);
        cp16(base + SM_B + so, Bh + gb);
    }
}

template <int MODE, int SPLIT>
__global__ __launch_bounds__(256, 2)
void gemm_mma(const __half* __restrict__ Ah, const __half* __restrict__ Al,
              const __half* __restrict__ Bh,
              float* __restrict__ C, int M, int N, int K,
              const float* __restrict__ bias)
{
    extern __shared__ __align__(128) char smem[];
    uint32_t sb = smem_u32(smem);
    const uint32_t STAGE_B = (SPLIT ? 3 : 2) * MAT_BYTES;
    const uint32_t SM_B = (SPLIT ? 2 : 1) * MAT_BYTES;
    const int tid  = threadIdx.x;
    const int wid  = tid >> 5;
    const int lane = tid & 31;
    const int wm = (wid & 3) * 32;
    const int wn = (wid >> 2) * 64;
    const int brow = blockIdx.y * BM, bcol = blockIdx.x * BN;

    float c[2][8][4];
#pragma unroll
    for (int i = 0; i < 2; i++)
#pragma unroll
        for (int j = 0; j < 8; j++)
#pragma unroll
            for (int r = 0; r < 4; r++) c[i][j][r] = 0.0f;

    const int nchunks = K / BK;
    load_chunk<SPLIT>(sb, Ah, Al, Bh, brow, bcol, K, 0, 0, tid);
    CP_COMMIT();

    const int a_r = lane & 15;
    const int a_c = (lane >> 4) << 3;
    const int b_r = ((lane < 16) ? (lane & 7) : (8 + (lane & 7)));
    const int b_c = ((lane >> 3) & 1) << 3;

    for (int ch = 0; ch < nchunks; ch++) {
        CP_WAIT(0);
        __syncthreads();
        if (ch + 1 < nchunks) {
            load_chunk<SPLIT>(sb, Ah, Al, Bh, brow, bcol, K, (ch + 1) * BK, (ch + 1) & 1, tid);
            CP_COMMIT();
        }
        uint32_t stb = sb + (ch & 1) * STAGE_B;
#pragma unroll
        for (int ks = 0; ks < 4; ks++) {
            const int kb = ks * 16;
            uint32_t ah[2][4], al[2][4], bh[4][4];
#pragma unroll
            for (int mt = 0; mt < 2; mt++) {
                uint32_t ad = stb +
                    (uint32_t)((wm + mt * 16 + a_r) * (PADK * 2) + (kb + a_c) * 2);
                LDSM_X4(ah[mt], ad);
                if (SPLIT) LDSM_X4(al[mt], ad + MAT_BYTES);
            }
#pragma unroll
            for (int nt = 0; nt < 4; nt++) {
                uint32_t bd = stb + SM_B +
                    (uint32_t)((wn + nt * 16 + b_r) * (PADK * 2) + (kb + b_c) * 2);
                LDSM_X4(bh[nt], bd);
            }
#pragma unroll
            for (int mt = 0; mt < 2; mt++)
#pragma unroll
                for (int n8 = 0; n8 < 8; n8++)
                    MMA_F16(c[mt][n8], ah[mt],
                            bh[n8 >> 1][(n8 & 1) * 2], bh[n8 >> 1][(n8 & 1) * 2 + 1]);
            if (SPLIT) {
#pragma unroll
                for (int mt = 0; mt < 2; mt++)
#pragma unroll
                    for (int n8 = 0; n8 < 8; n8++)
                        MMA_F16(c[mt][n8], al[mt],
                                bh[n8 >> 1][(n8 & 1) * 2], bh[n8 >> 1][(n8 & 1) * 2 + 1]);
            }
        }
    }

    if (MODE == 0) {
#pragma unroll
        for (int mt = 0; mt < 2; mt++) {
            int row0 = brow + wm + mt * 16 + (lane >> 2);
#pragma unroll
            for (int n8 = 0; n8 < 8; n8++) {
                int col = bcol + wn + n8 * 8 + (lane & 3) * 2;
                float bx = bias[col], by = bias[col + 1];
                *(float2*)(C + (size_t)row0 * N + col) =
                    make_float2(c[mt][n8][0] + bx, c[mt][n8][1] + by);
                *(float2*)(C + (size_t)(row0 + 8) * N + col) =
                    make_float2(c[mt][n8][2] + bx, c[mt][n8][3] + by);
            }
        }
    } else {
        // fused rope/pack: warp's 64-col block = one (comp, head); pairs
        // (n8, n8+4) hold dims (d, d+32). Q written as hi/lo fp16 split.
        const int colbase = bcol + wn;
        const int comp = colbase >> 10;            // 0=q 1=k 2=v
        const int head = (colbase & 1023) >> 6;
#pragma unroll
        for (int mt = 0; mt < 2; mt++) {
#pragma unroll
            for (int r = 0; r < 2; r++) {
                int row = brow + wm + mt * 16 + (lane >> 2) + 8 * r;   // b*T + t
                int t = row & (TSEQ - 1);
                int bidx = row >> 11;
                size_t dst = ((size_t)(bidx * NHEAD + head) * TSEQ + t) * HD;
#pragma unroll
                for (int n8 = 0; n8 < 4; n8++) {
                    int d = n8 * 8 + 2 * (lane & 3);
                    float x1a = c[mt][n8][2 * r],     x1b = c[mt][n8][2 * r + 1];
                    float x2a = c[mt][n8 + 4][2 * r], x2b = c[mt][n8 + 4][2 * r + 1];
                    if (comp == 2) {
                        *(__half2*)(g_vp + dst + d)      = __floats2half2_rn(x1a, x1b);
                        *(__half2*)(g_vp + dst + d + 32) = __floats2half2_rn(x2a, x2b);
                    } else {
                        float4 cs = g_rope[t * 16 + (d >> 1)];
                        float o1a = x1a * cs.x - x2a * cs.y;
                        float o1b = x1b * cs.z - x2b * cs.w;
                        float o2a = x1a * cs.y + x2a * cs.x;
                        float o2b = x1b * cs.w + x2b * cs.z;
                        if (comp == 0) {
                            o1a *= 0.125f; o1b *= 0.125f; o2a *= 0.125f; o2b *= 0.125f;
                            __half h1a = __float2half(o1a), h1b = __float2half(o1b);
                            __half h2a = __float2half(o2a), h2b = __float2half(o2b);
                            *(__half2*)(g_qr + dst + d)      = __halves2half2(h1a, h1b);
                            *(__half2*)(g_qr + dst + d + 32) = __halves2half2(h2a, h2b);
                            *(__half2*)(g_ql + dst + d) = __halves2half2(
                                __float2half(o1a - __half2float(h1a)),
                                __float2half(o1b - __half2float(h1b)));
                            *(__half2*)(g_ql + dst + d + 32) = __halves2half2(
                                __float2half(o2a - __half2float(h2a)),
                                __float2half(o2b - __half2float(h2b)));
                        } else {
                            *(__half2*)(g_kr + dst + d)      = __floats2half2_rn(o1a, o1b);
                            *(__half2*)(g_kr + dst + d + 32) = __floats2half2_rn(o2a, o2b);
                        }
                    }
                }
            }
        }
    }
}

// ---------------- fp32 -> fp16 hi/lo split (x input only) -------------------
__global__ void split_a(const float* __restrict__ src,
                        __half* __restrict__ h, __half* __restrict__ l, int n)
{
    int i = blockIdx.x * blockDim.x + threadIdx.x;
    if (i >= n) return;
    float v = src[i];
    __half hb = __float2half(v);
    h[i] = hb;
    l[i] = __float2half(v - __half2float(hb));
}

// W[K][N] -> Bt[N][K] fp16, smem-tiled transpose
__global__ void wconv(const float* __restrict__ W, __half* __restrict__ Bt, int K, int N)
{
    __shared__ float tile[32][33];
    int n0 = blockIdx.x * 32, k0 = blockIdx.y * 32;
    int tx = threadIdx.x & 31, ty = threadIdx.x >> 5;
#pragma unroll
    for (int r = 0; r < 4; r++)
        tile[ty + 8 * r][tx] = W[(size_t)(k0 + ty + 8 * r) * N + n0 + tx];
    __syncthreads();
#pragma unroll
    for (int r = 0; r < 4; r++)
        Bt[(size_t)(n0 + ty + 8 * r) * K + k0 + tx] = __float2half(tile[tx][ty + 8 * r]);
}

// ---------------- RoPE cos/sin table ----------------------------------------
__global__ void rope_table()
{
    int idx = blockIdx.x * blockDim.x + threadIdx.x;
    if (idx >= TSEQ * 16) return;
    int t = idx >> 4, pg = idx & 15;
    float c0, s0, c1, s1;
    {
        float e = (float)(2 * (2 * pg)) * (1.0f / 64.0f);
        float ang = (float)t * exp2f(-e * 13.2877123795494493f);
        sincosf(ang, &s0, &c0);
    }
    {
        float e = (float)(2 * (2 * pg + 1)) * (1.0f / 64.0f);
        float ang = (float)t * exp2f(-e * 13.2877123795494493f);
        sincosf(ang, &s1, &c1);
    }
    g_rope[idx] = make_float4(c0, s0, c1, s1);
}

// ---------------- flash attention via mma.sync -------------------------------
// Q 2-term (Qh+Ql) for accurate scores; output written fp16 (hi only).
#define PADH 72
#define QS_BYTES (64 * PADH * 2)        // 9216
#define QL_OFF   QS_BYTES
#define KS_OFF   (2 * QS_BYTES)        // 18432
#define KS_BYTES (320 * PADH * 2)       // 46080
#define VS_OFF   (KS_OFF + KS_BYTES)
#define ATTN_SMEM (VS_OFF + KS_BYTES)   // 110592

__global__ __launch_bounds__(256, 2)
void attn_kernel()
{
    extern __shared__ __align__(128) char asmem[];
    uint32_t sb = smem_u32(asmem);
    float* mgb = (float*)(asmem + KS_OFF);   // merge buffer aliases Ks

    const int tid = threadIdx.x, wid = tid >> 5, lane = tid & 31;
    const int b = blockIdx.z, h = blockIdx.y;
    const int t0 = blockIdx.x * 64;
    const int warp_m = wid & 3, warp_n = wid >> 2;

    const size_t bh = (size_t)(b * NHEAD + h) * TSEQ;

    {
        const __half* qsrc = g_qr + (bh + t0) * HD;
        const __half* lsrc = g_ql + (bh + t0) * HD;
        for (int idx = tid; idx < 64 * 8; idx += 256) {
            int row = idx >> 3, cc = idx & 7;
            uint32_t so = (uint32_t)(row * PADH + cc * 8) * 2;
            cp16(sb + so, qsrc + row * HD + cc * 8);
            cp16(sb + QL_OFF + so, lsrc + row * HD + cc * 8);
        }
    }
    {
        const __half* ksrc = g_kr + bh * HD;
        const __half* vsrc = g_vp + bh * HD;
        for (int idx = tid; idx < 320 * 8; idx += 256) {
            int kk = idx >> 3, cc = idx & 7;
            int kg = t0 - 128 + kk;
            kg = kg < 0 ? 0 : (kg > TSEQ - 1 ? TSEQ - 1 : kg);
            cp16(sb + KS_OFF + (uint32_t)(kk * PADH + cc * 8) * 2, ksrc + (size_t)kg * HD + cc * 8);
            cp16(sb + VS_OFF + (uint32_t)(kk * PADH + cc * 8) * 2, vsrc + (size_t)kg * HD + cc * 8);
        }
    }
    CP_COMMIT();
    CP_WAIT(0);
    __syncthreads();

    const int a_r = lane & 15;
    const int a_c = (lane >> 4) << 3;
    const int b_r = ((lane < 16) ? (lane & 7) : (8 + (lane & 7)));
    const int b_c = ((lane >> 3) & 1) << 3;
    const int qlo = t0 + warp_m * 16;
    const int qi0 = qlo + (lane >> 2);

    float m0 = -1e30f, m1 = -1e30f, l0 = 0.f, l1 = 0.f;
    float o[8][4];
#pragma unroll
    for (int t = 0; t < 8; t++)
#pragma unroll
        for (int j = 0; j < 4; j++) o[t][j] = 0.f;

    for (int c = 0; c < 5; c++) {
        int kk0 = 64 * c + 32 * warp_n;
        int kgb = t0 - 128 + kk0;
        if (kgb + 31 < qlo - WIN || kgb > qlo + 15 + WIN) continue;

        float cS[4][4];
#pragma unroll
        for (int i = 0; i < 4; i++)
#pragma unroll
            for (int j = 0; j < 4; j++) cS[i][j] = 0.f;
#pragma unroll
        for (int ks = 0; ks < 4; ks++) {
            uint32_t aqh[4], aql[4], bk0[4], bk1[4];
            uint32_t qa = sb + (uint32_t)((warp_m * 16 + a_r) * PADH + ks * 16 + a_c) * 2;
            LDSM_X4(aqh, qa);
            LDSM_X4(aql, qa + QL_OFF);
            LDSM_X4(bk0, sb + KS_OFF + (uint32_t)((kk0 + b_r) * PADH + ks * 16 + b_c) * 2);
            LDSM_X4(bk1, sb + KS_OFF + (uint32_t)((kk0 + 16 + b_r) * PADH + ks * 16 + b_c) * 2);
            MMA_F16(cS[0], aqh, bk0[0], bk0[1]);
            MMA_F16(cS[1], aqh, bk0[2], bk0[3]);
            MMA_F16(cS[2], aqh, bk1[0], bk1[1]);
            MMA_F16(cS[3], aqh, bk1[2], bk1[3]);
            MMA_F16(cS[0], aql, bk0[0], bk0[1]);
            MMA_F16(cS[1], aql, bk0[2], bk0[3]);
            MMA_F16(cS[2], aql, bk1[0], bk1[1]);
            MMA_F16(cS[3], aql, bk1[2], bk1[3]);
        }

        float rmax0 = -1e30f, rmax1 = -1e30f;
#pragma unroll
        for (int n8 = 0; n8 < 4; n8++) {
            int jb = kgb + 8 * n8 + 2 * (lane & 3);
#pragma unroll
            for (int e = 0; e < 2; e++) {
                int j = jb + e;
                bool okj = (j >= 0) && (j < TSEQ);
                if (!(okj && j >= qi0 - WIN && j <= qi0 + WIN))         cS[n8][e]     = -1e30f;
                if (!(okj && j >= qi0 + 8 - WIN && j <= qi0 + 8 + WIN)) cS[n8][e + 2] = -1e30f;
            }
            rmax0 = fmaxf(rmax0, fmaxf(cS[n8][0], cS[n8][1]));
            rmax1 = fmaxf(rmax1, fmaxf(cS[n8][2], cS[n8][3]));
        }
        rmax0 = fmaxf(rmax0, __shfl_xor_sync(0xffffffffu, rmax0, 1));
        rmax0 = fmaxf(rmax0, __shfl_xor_sync(0xffffffffu, rmax0, 2));
        rmax1 = fmaxf(rmax1, __shfl_xor_sync(0xffffffffu, rmax1, 1));
        rmax1 = fmaxf(rmax1, __shfl_xor_sync(0xffffffffu, rmax1, 2));

        float mn0 = fmaxf(m0, rmax0), mn1 = fmaxf(m1, rmax1);
        float sc0 = __expf(m0 - mn0), sc1 = __expf(m1 - mn1);
        m0 = mn0; m1 = mn1;

        float ps0 = 0.f, ps1 = 0.f;
        uint32_t pa[4][2];
#pragma unroll
        for (int n8 = 0; n8 < 4; n8++) {
            float p0 = (cS[n8][0] < -1e29f) ? 0.f : __expf(cS[n8][0] - mn0);
            float p1 = (cS[n8][1] < -1e29f) ? 0.f : __expf(cS[n8][1] - mn0);
            float p2 = (cS[n8][2] < -1e29f) ? 0.f : __expf(cS[n8][2] - mn1);
            float p3 = (cS[n8][3] < -1e29f) ? 0.f : __expf(cS[n8][3] - mn1);
            ps0 += p0 + p1; ps1 += p2 + p3;
            pa[n8][0] = packh2(p0, p1);
            pa[n8][1] = packh2(p2, p3);
        }
        ps0 += __shfl_xor_sync(0xffffffffu, ps0, 1);
        ps0 += __shfl_xor_sync(0xffffffffu, ps0, 2);
        ps1 += __shfl_xor_sync(0xffffffffu, ps1, 1);
        ps1 += __shfl_xor_sync(0xffffffffu, ps1, 2);
        l0 = l0 * sc0 + ps0;
        l1 = l1 * sc1 + ps1;
#pragma unroll
        for (int t = 0; t < 8; t++) {
            o[t][0] *= sc0; o[t][1] *= sc0; o[t][2] *= sc1; o[t][3] *= sc1;
        }

#pragma unroll
        for (int kp = 0; kp < 2; kp++) {
            uint32_t a[4] = { pa[2 * kp][0], pa[2 * kp][1], pa[2 * kp + 1][0], pa[2 * kp + 1][1] };
#pragma unroll
            for (int np = 0; np < 4; np++) {
                uint32_t bv[4];
                LDSM_X4_T(bv, sb + VS_OFF +
                    (uint32_t)((kk0 + kp * 16 + a_r) * PADH + np * 16 + a_c) * 2);
                MMA_F16(o[2 * np],     a, bv[0], bv[1]);
                MMA_F16(o[2 * np + 1], a, bv[2], bv[3]);
            }
        }
    }

    __syncthreads();
    float* ob = mgb + (warp_m * 32 + lane) * 33;
    float2* mlb = (float2*)(mgb + 4 * 32 * 33);
    if (warp_n == 1) {
#pragma unroll
        for (int t = 0; t < 8; t++)
#pragma unroll
            for (int j = 0; j < 4; j++) ob[4 * t + j] = o[t][j];
        if ((lane & 3) == 0) {
            mlb[warp_m * 16 + (lane >> 2)]     = make_float2(m0, l0);
            mlb[warp_m * 16 + 8 + (lane >> 2)] = make_float2(m1, l1);
        }
    }
    __syncthreads();
    if (warp_n == 0) {
        float2 M0 = mlb[warp_m * 16 + (lane >> 2)];
        float2 M1 = mlb[warp_m * 16 + 8 + (lane >> 2)];
        float mm0 = fmaxf(m0, M0.x), mm1 = fmaxf(m1, M1.x);
        float w00 = __expf(m0 - mm0), w01 = __expf(M0.x - mm0);
        float w10 = __expf(m1 - mm1), w11 = __expf(M1.x - mm1);
        float inv0 = 1.0f / (l0 * w00 + M0.y * w01);
        float inv1 = 1.0f / (l1 * w10 + M1.y * w11);
        size_t r0 = (size_t)(b * TSEQ + qlo + (lane >> 2)) * DMODEL;
        size_t r1 = r0 + 8 * DMODEL;
#pragma unroll
        for (int t = 0; t < 8; t++) {
            int col = h * HD + t * 8 + 2 * (lane & 3);
            float v0 = (o[t][0] * w00 + ob[4 * t + 0] * w01) * inv0;
            float v1 = (o[t][1] * w00 + ob[4 * t + 1] * w01) * inv0;
            float v2 = (o[t][2] * w10 + ob[4 * t + 2] * w11) * inv1;
            float v3 = (o[t][3] * w10 + ob[4 * t + 3] * w11) * inv1;
            *(__half2*)(g_Ah + r0 + col) = __floats2half2_rn(v0, v1);
            *(__half2*)(g_Ah + r1 + col) = __floats2half2_rn(v2, v3);
        }
    }
}

// ---------------------------------------------------------------------------
extern "C" void kernel_launch(void* const* d_in, const int* in_sizes, int n_in,
                              void* d_out, int out_size)
{
    const float* x    = (const float*)d_in[0];
    const float* Wqkv = (const float*)d_in[1];
    const float* Wout = (const float*)d_in[2];
    const float* bout = (const float*)d_in[3];
    float* out = (float*)d_out;

    __half *Ah, *Al, *Bh;
    cudaGetSymbolAddress((void**)&Ah, g_Ah);
    cudaGetSymbolAddress((void**)&Al, g_Al);
    cudaGetSymbolAddress((void**)&Bh, g_Bh);

    const int GEMM_SMEM_S1 = 2 * 3 * MAT_BYTES;   // 110592 (SPLIT=1)
    const int GEMM_SMEM_S0 = 2 * 2 * MAT_BYTES;   // 73728  (SPLIT=0)

    cudaFuncSetAttribute(gemm_mma<1, 1>, cudaFuncAttributeMaxDynamicSharedMemorySize, GEMM_SMEM_S1);
    cudaFuncSetAttribute(gemm_mma<0, 0>, cudaFuncAttributeMaxDynamicSharedMemorySize, GEMM_SMEM_S0);
    cudaFuncSetAttribute(attn_kernel, cudaFuncAttributeMaxDynamicSharedMemorySize, ATTN_SMEM);

    rope_table<<<(TSEQ * 16 + 255) / 256, 256>>>();

    split_a<<<(ROWS * DMODEL + 511) / 512, 512>>>(x, Ah, Al, ROWS * DMODEL);
    wconv<<<dim3(QKVCOLS / 32, DMODEL / 32), 256>>>(Wqkv, Bh, DMODEL, QKVCOLS);
    // QKV projection (2-term) with fused rope/pack epilogue (Q hi/lo split)
    gemm_mma<1, 1><<<dim3(QKVCOLS / BN, ROWS / BM), 256, GEMM_SMEM_S1>>>(
        Ah, Al, Bh, nullptr, ROWS, QKVCOLS, DMODEL, nullptr);

    attn_kernel<<<dim3(TSEQ / 64, NHEAD, NB), 256, ATTN_SMEM>>>();

    wconv<<<dim3(DMODEL / 32, DMODEL / 32), 256>>>(Wout, Bh, DMODEL, DMODEL);
    // Output projection: 1-term A (attention output fp16)
    gemm_mma<0, 0><<<dim3(DMODEL / BN, ROWS / BM), 256, GEMM_SMEM_S0>>>(
        Ah, nullptr, Bh, out, ROWS, DMODEL, DMODEL, bout);
}

// round 11
// speedup vs baseline: 1.4057x; 1.1638x over previous
#include <cuda_runtime.h>
#include <cuda_fp16.h>
#include <math.h>
#include <stdint.h>

#define NB      4
#define TSEQ    2048
#define NHEAD   16
#define HD      64
#define DMODEL  1024
#define ROWS    (NB * TSEQ)          // 8192
#define QKVCOLS (3 * DMODEL)         // 3072
#define WIN     128

// ---------------- scratch (allocation-free rule: device globals) ----------
__device__ __align__(16) __half g_Ah[ROWS   * DMODEL];
__device__ __align__(16) __half g_Al[ROWS   * DMODEL];
__device__ __align__(16) __half g_Bh[QKVCOLS * DMODEL];  // [N][K] transposed fp16
__device__ __align__(16) __half g_qr[ROWS * DMODEL];     // [b,h][t][d] roped+scaled Q (hi)
__device__ __align__(16) __half g_ql[ROWS * DMODEL];     // [b,h][t][d] roped+scaled Q (lo)
__device__ __align__(16) __half g_kr[ROWS * DMODEL];     // [b,h][t][d] roped K
__device__ __align__(16) __half g_vp[ROWS * DMODEL];     // [b,h][t][d] packed V
__device__ float4 g_rope[TSEQ * 16];  // (t, pg): cos/sin for freqs 2pg, 2pg+1

// ---------------- PTX helpers ---------------------------------------------
__device__ __forceinline__ uint32_t smem_u32(const void* p) {
    uint32_t a;
    asm("{ .reg .u64 t; cvta.to.shared.u64 t, %1; cvt.u32.u64 %0, t; }" : "=r"(a) : "l"(p));
    return a;
}
__device__ __forceinline__ void cp16(uint32_t dst, const void* src) {
    asm volatile("cp.async.cg.shared.global [%0], [%1], 16;" :: "r"(dst), "l"(src));
}
#define CP_COMMIT() asm volatile("cp.async.commit_group;" ::: "memory")
#define CP_WAIT(n)  asm volatile("cp.async.wait_group %0;" :: "n"(n) : "memory")

#define LDSM_X4(r, addr) \
    asm volatile("ldmatrix.sync.aligned.m8n8.x4.shared.b16 {%0,%1,%2,%3}, [%4];" \
        : "=r"((r)[0]), "=r"((r)[1]), "=r"((r)[2]), "=r"((r)[3]) : "r"(addr))
#define LDSM_X4_T(r, addr) \
    asm volatile("ldmatrix.sync.aligned.m8n8.x4.trans.shared.b16 {%0,%1,%2,%3}, [%4];" \
        : "=r"((r)[0]), "=r"((r)[1]), "=r"((r)[2]), "=r"((r)[3]) : "r"(addr))

#define MMA_F16(c, a, b0, b1) \
    asm volatile("mma.sync.aligned.m16n8k16.row.col.f32.f16.f16.f32 " \
        "{%0,%1,%2,%3}, {%4,%5,%6,%7}, {%8,%9}, {%0,%1,%2,%3};" \
        : "+f"((c)[0]), "+f"((c)[1]), "+f"((c)[2]), "+f"((c)[3]) \
        : "r"((a)[0]), "r"((a)[1]), "r"((a)[2]), "r"((a)[3]), "r"(b0), "r"(b1))

__device__ __forceinline__ uint32_t packh2(float a, float b) {
    __half2 h = __floats2half2_rn(a, b);
    return *reinterpret_cast<uint32_t*>(&h);
}

// ---------------- mma.sync GEMM: C = A[M,K]*Bt[N,K]^T -----------------------
// CTA 128x128, 8 warps (4m x 2n), warp 32x64. BK=64, 2-stage cp.async,
// one barrier per chunk.
// SPLIT=1 (QKV): A = Ah + Al, but Al applied ONLY for V column blocks
//   (bcol >= 2*DMODEL); Q,K blocks are 1-term (score error washes out).
// SPLIT=0 (out-proj): A = Ah only.
// MODE 0: fp32 C + bias. MODE 1: fused rope/pack epilogue.
#define BM 128
#define BN 128
#define BK 64
#define PADK 72
#define MAT_BYTES (128 * PADK * 2)    // 18432

template <int SPLIT>
__device__ __forceinline__ void load_chunk(
    uint32_t sb, const __half* __restrict__ Ah, const __half* __restrict__ Al,
    const __half* __restrict__ Bh, bool use_al,
    int brow, int bcol, int K, int kc, int stage, int tid)
{
    const uint32_t STAGE_B = (SPLIT ? 3 : 2) * MAT_BYTES;
    const uint32_t SM_B = (SPLIT ? 2 : 1) * MAT_BYTES;
    uint32_t base = sb + stage * STAGE_B;
#pragma unroll
    for (int t = 0; t < 4; t++) {
        int idx = tid + t * 256;
        int row = idx >> 3;
        int c16 = idx & 7;
        uint32_t so = (uint32_t)(row * (PADK * 2) + c16 * 16);
        size_t ga = (size_t)(brow + row) * K + kc + c16 * 8;
        size_t gb = (size_t)(bcol + row) * K + kc + c16 * 8;
        cp16(base + so, Ah + ga);
        if (SPLIT && use_al) cp16(base + MAT_BYTES + so, Al + ga);
        cp16(base + SM_B + so, Bh + gb);
    }
}

template <int MODE, int SPLIT>
__global__ __launch_bounds__(256, 2)
void gemm_mma(const __half* __restrict__ Ah, const __half* __restrict__ Al,
              const __half* __restrict__ Bh,
              float* __restrict__ C, int M, int N, int K,
              const float* __restrict__ bias)
{
    extern __shared__ __align__(128) char smem[];
    uint32_t sb = smem_u32(smem);
    const uint32_t STAGE_B = (SPLIT ? 3 : 2) * MAT_BYTES;
    const uint32_t SM_B = (SPLIT ? 2 : 1) * MAT_BYTES;
    const int tid  = threadIdx.x;
    const int wid  = tid >> 5;
    const int lane = tid & 31;
    const int wm = (wid & 3) * 32;
    const int wn = (wid >> 2) * 64;
    const int brow = blockIdx.y * BM, bcol = blockIdx.x * BN;
    // V column blocks get the 2-term treatment; Q,K blocks 1-term.
    const bool use_al = SPLIT && (MODE == 0 || bcol >= 2 * DMODEL);

    float c[2][8][4];
#pragma unroll
    for (int i = 0; i < 2; i++)
#pragma unroll
        for (int j = 0; j < 8; j++)
#pragma unroll
            for (int r = 0; r < 4; r++) c[i][j][r] = 0.0f;

    const int nchunks = K / BK;
    load_chunk<SPLIT>(sb, Ah, Al, Bh, use_al, brow, bcol, K, 0, 0, tid);
    CP_COMMIT();

    const int a_r = lane & 15;
    const int a_c = (lane >> 4) << 3;
    const int b_r = ((lane < 16) ? (lane & 7) : (8 + (lane & 7)));
    const int b_c = ((lane >> 3) & 1) << 3;

    for (int ch = 0; ch < nchunks; ch++) {
        CP_WAIT(0);
        __syncthreads();
        if (ch + 1 < nchunks) {
            load_chunk<SPLIT>(sb, Ah, Al, Bh, use_al, brow, bcol, K, (ch + 1) * BK,
                              (ch + 1) & 1, tid);
            CP_COMMIT();
        }
        uint32_t stb = sb + (ch & 1) * STAGE_B;
#pragma unroll
        for (int ks = 0; ks < 4; ks++) {
            const int kb = ks * 16;
            uint32_t ah[2][4], al[2][4], bh[4][4];
#pragma unroll
            for (int mt = 0; mt < 2; mt++) {
                uint32_t ad = stb +
                    (uint32_t)((wm + mt * 16 + a_r) * (PADK * 2) + (kb + a_c) * 2);
                LDSM_X4(ah[mt], ad);
                if (SPLIT && use_al) LDSM_X4(al[mt], ad + MAT_BYTES);
            }
#pragma unroll
            for (int nt = 0; nt < 4; nt++) {
                uint32_t bd = stb + SM_B +
                    (uint32_t)((wn + nt * 16 + b_r) * (PADK * 2) + (kb + b_c) * 2);
                LDSM_X4(bh[nt], bd);
            }
#pragma unroll
            for (int mt = 0; mt < 2; mt++)
#pragma unroll
                for (int n8 = 0; n8 < 8; n8++)
                    MMA_F16(c[mt][n8], ah[mt],
                            bh[n8 >> 1][(n8 & 1) * 2], bh[n8 >> 1][(n8 & 1) * 2 + 1]);
            if (SPLIT && use_al) {
#pragma unroll
                for (int mt = 0; mt < 2; mt++)
#pragma unroll
                    for (int n8 = 0; n8 < 8; n8++)
                        MMA_F16(c[mt][n8], al[mt],
                                bh[n8 >> 1][(n8 & 1) * 2], bh[n8 >> 1][(n8 & 1) * 2 + 1]);
            }
        }
    }

    if (MODE == 0) {
#pragma unroll
        for (int mt = 0; mt < 2; mt++) {
            int row0 = brow + wm + mt * 16 + (lane >> 2);
#pragma unroll
            for (int n8 = 0; n8 < 8; n8++) {
                int col = bcol + wn + n8 * 8 + (lane & 3) * 2;
                float bx = bias[col], by = bias[col + 1];
                *(float2*)(C + (size_t)row0 * N + col) =
                    make_float2(c[mt][n8][0] + bx, c[mt][n8][1] + by);
                *(float2*)(C + (size_t)(row0 + 8) * N + col) =
                    make_float2(c[mt][n8][2] + bx, c[mt][n8][3] + by);
            }
        }
    } else {
        // fused rope/pack: warp's 64-col block = one (comp, head); pairs
        // (n8, n8+4) hold dims (d, d+32). Q written as hi/lo fp16 split.
        const int colbase = bcol + wn;
        const int comp = colbase >> 10;            // 0=q 1=k 2=v
        const int head = (colbase & 1023) >> 6;
#pragma unroll
        for (int mt = 0; mt < 2; mt++) {
#pragma unroll
            for (int r = 0; r < 2; r++) {
                int row = brow + wm + mt * 16 + (lane >> 2) + 8 * r;   // b*T + t
                int t = row & (TSEQ - 1);
                int bidx = row >> 11;
                size_t dst = ((size_t)(bidx * NHEAD + head) * TSEQ + t) * HD;
#pragma unroll
                for (int n8 = 0; n8 < 4; n8++) {
                    int d = n8 * 8 + 2 * (lane & 3);
                    float x1a = c[mt][n8][2 * r],     x1b = c[mt][n8][2 * r + 1];
                    float x2a = c[mt][n8 + 4][2 * r], x2b = c[mt][n8 + 4][2 * r + 1];
                    if (comp == 2) {
                        *(__half2*)(g_vp + dst + d)      = __floats2half2_rn(x1a, x1b);
                        *(__half2*)(g_vp + dst + d + 32) = __floats2half2_rn(x2a, x2b);
                    } else {
                        float4 cs = g_rope[t * 16 + (d >> 1)];
                        float o1a = x1a * cs.x - x2a * cs.y;
                        float o1b = x1b * cs.z - x2b * cs.w;
                        float o2a = x1a * cs.y + x2a * cs.x;
                        float o2b = x1b * cs.w + x2b * cs.z;
                        if (comp == 0) {
                            o1a *= 0.125f; o1b *= 0.125f; o2a *= 0.125f; o2b *= 0.125f;
                            __half h1a = __float2half(o1a), h1b = __float2half(o1b);
                            __half h2a = __float2half(o2a), h2b = __float2half(o2b);
                            *(__half2*)(g_qr + dst + d)      = __halves2half2(h1a, h1b);
                            *(__half2*)(g_qr + dst + d + 32) = __halves2half2(h2a, h2b);
                            *(__half2*)(g_ql + dst + d) = __halves2half2(
                                __float2half(o1a - __half2float(h1a)),
                                __float2half(o1b - __half2float(h1b)));
                            *(__half2*)(g_ql + dst + d + 32) = __halves2half2(
                                __float2half(o2a - __half2float(h2a)),
                                __float2half(o2b - __half2float(h2b)));
                        } else {
                            *(__half2*)(g_kr + dst + d)      = __floats2half2_rn(o1a, o1b);
                            *(__half2*)(g_kr + dst + d + 32) = __floats2half2_rn(o2a, o2b);
                        }
                    }
                }
            }
        }
    }
}

// ---------------- fp32 -> fp16 hi/lo split (x input only) -------------------
__global__ void split_a(const float* __restrict__ src,
                        __half* __restrict__ h, __half* __restrict__ l, int n)
{
    int i = blockIdx.x * blockDim.x + threadIdx.x;
    if (i >= n) return;
    float v = src[i];
    __half hb = __float2half(v);
    h[i] = hb;
    l[i] = __float2half(v - __half2float(hb));
}

// W[K][N] -> Bt[N][K] fp16, smem-tiled transpose
__global__ void wconv(const float* __restrict__ W, __half* __restrict__ Bt, int K, int N)
{
    __shared__ float tile[32][33];
    int n0 = blockIdx.x * 32, k0 = blockIdx.y * 32;
    int tx = threadIdx.x & 31, ty = threadIdx.x >> 5;
#pragma unroll
    for (int r = 0; r < 4; r++)
        tile[ty + 8 * r][tx] = W[(size_t)(k0 + ty + 8 * r) * N + n0 + tx];
    __syncthreads();
#pragma unroll
    for (int r = 0; r < 4; r++)
        Bt[(size_t)(n0 + ty + 8 * r) * K + k0 + tx] = __float2half(tile[tx][ty + 8 * r]);
}

// ---------------- RoPE cos/sin table ----------------------------------------
__global__ void rope_table()
{
    int idx = blockIdx.x * blockDim.x + threadIdx.x;
    if (idx >= TSEQ * 16) return;
    int t = idx >> 4, pg = idx & 15;
    float c0, s0, c1, s1;
    {
        float e = (float)(2 * (2 * pg)) * (1.0f / 64.0f);
        float ang = (float)t * exp2f(-e * 13.2877123795494493f);
        sincosf(ang, &s0, &c0);
    }
    {
        float e = (float)(2 * (2 * pg + 1)) * (1.0f / 64.0f);
        float ang = (float)t * exp2f(-e * 13.2877123795494493f);
        sincosf(ang, &s1, &c1);
    }
    g_rope[idx] = make_float4(c0, s0, c1, s1);
}

// ---------------- flash attention via mma.sync -------------------------------
// Q 2-term (Qh+Ql) for accurate scores; output written fp16 (hi only).
#define PADH 72
#define QS_BYTES (64 * PADH * 2)        // 9216
#define QL_OFF   QS_BYTES
#define KS_OFF   (2 * QS_BYTES)        // 18432
#define KS_BYTES (320 * PADH * 2)       // 46080
#define VS_OFF   (KS_OFF + KS_BYTES)
#define ATTN_SMEM (VS_OFF + KS_BYTES)   // 110592

__global__ __launch_bounds__(256, 2)
void attn_kernel()
{
    extern __shared__ __align__(128) char asmem[];
    uint32_t sb = smem_u32(asmem);
    float* mgb = (float*)(asmem + KS_OFF);   // merge buffer aliases Ks

    const int tid = threadIdx.x, wid = tid >> 5, lane = tid & 31;
    const int b = blockIdx.z, h = blockIdx.y;
    const int t0 = blockIdx.x * 64;
    const int warp_m = wid & 3, warp_n = wid >> 2;

    const size_t bh = (size_t)(b * NHEAD + h) * TSEQ;

    {
        const __half* qsrc = g_qr + (bh + t0) * HD;
        const __half* lsrc = g_ql + (bh + t0) * HD;
        for (int idx = tid; idx < 64 * 8; idx += 256) {
            int row = idx >> 3, cc = idx & 7;
            uint32_t so = (uint32_t)(row * PADH + cc * 8) * 2;
            cp16(sb + so, qsrc + row * HD + cc * 8);
            cp16(sb + QL_OFF + so, lsrc + row * HD + cc * 8);
        }
    }
    {
        const __half* ksrc = g_kr + bh * HD;
        const __half* vsrc = g_vp + bh * HD;
        for (int idx = tid; idx < 320 * 8; idx += 256) {
            int kk = idx >> 3, cc = idx & 7;
            int kg = t0 - 128 + kk;
            kg = kg < 0 ? 0 : (kg > TSEQ - 1 ? TSEQ - 1 : kg);
            cp16(sb + KS_OFF + (uint32_t)(kk * PADH + cc * 8) * 2, ksrc + (size_t)kg * HD + cc * 8);
            cp16(sb + VS_OFF + (uint32_t)(kk * PADH + cc * 8) * 2, vsrc + (size_t)kg * HD + cc * 8);
        }
    }
    CP_COMMIT();
    CP_WAIT(0);
    __syncthreads();

    const int a_r = lane & 15;
    const int a_c = (lane >> 4) << 3;
    const int b_r = ((lane < 16) ? (lane & 7) : (8 + (lane & 7)));
    const int b_c = ((lane >> 3) & 1) << 3;
    const int qlo = t0 + warp_m * 16;
    const int qi0 = qlo + (lane >> 2);

    float m0 = -1e30f, m1 = -1e30f, l0 = 0.f, l1 = 0.f;
    float o[8][4];
#pragma unroll
    for (int t = 0; t < 8; t++)
#pragma unroll
        for (int j = 0; j < 4; j++) o[t][j] = 0.f;

    for (int c = 0; c < 5; c++) {
        int kk0 = 64 * c + 32 * warp_n;
        int kgb = t0 - 128 + kk0;
        if (kgb + 31 < qlo - WIN || kgb > qlo + 15 + WIN) continue;

        float cS[4][4];
#pragma unroll
        for (int i = 0; i < 4; i++)
#pragma unroll
            for (int j = 0; j < 4; j++) cS[i][j] = 0.f;
#pragma unroll
        for (int ks = 0; ks < 4; ks++) {
            uint32_t aqh[4], aql[4], bk0[4], bk1[4];
            uint32_t qa = sb + (uint32_t)((warp_m * 16 + a_r) * PADH + ks * 16 + a_c) * 2;
            LDSM_X4(aqh, qa);
            LDSM_X4(aql, qa + QL_OFF);
            LDSM_X4(bk0, sb + KS_OFF + (uint32_t)((kk0 + b_r) * PADH + ks * 16 + b_c) * 2);
            LDSM_X4(bk1, sb + KS_OFF + (uint32_t)((kk0 + 16 + b_r) * PADH + ks * 16 + b_c) * 2);
            MMA_F16(cS[0], aqh, bk0[0], bk0[1]);
            MMA_F16(cS[1], aqh, bk0[2], bk0[3]);
            MMA_F16(cS[2], aqh, bk1[0], bk1[1]);
            MMA_F16(cS[3], aqh, bk1[2], bk1[3]);
            MMA_F16(cS[0], aql, bk0[0], bk0[1]);
            MMA_F16(cS[1], aql, bk0[2], bk0[3]);
            MMA_F16(cS[2], aql, bk1[0], bk1[1]);
            MMA_F16(cS[3], aql, bk1[2], bk1[3]);
        }

        float rmax0 = -1e30f, rmax1 = -1e30f;
#pragma unroll
        for (int n8 = 0; n8 < 4; n8++) {
            int jb = kgb + 8 * n8 + 2 * (lane & 3);
#pragma unroll
            for (int e = 0; e < 2; e++) {
                int j = jb + e;
                bool okj = (j >= 0) && (j < TSEQ);
                if (!(okj && j >= qi0 - WIN && j <= qi0 + WIN))         cS[n8][e]     = -1e30f;
                if (!(okj && j >= qi0 + 8 - WIN && j <= qi0 + 8 + WIN)) cS[n8][e + 2] = -1e30f;
            }
            rmax0 = fmaxf(rmax0, fmaxf(cS[n8][0], cS[n8][1]));
            rmax1 = fmaxf(rmax1, fmaxf(cS[n8][2], cS[n8][3]));
        }
        rmax0 = fmaxf(rmax0, __shfl_xor_sync(0xffffffffu, rmax0, 1));
        rmax0 = fmaxf(rmax0, __shfl_xor_sync(0xffffffffu, rmax0, 2));
        rmax1 = fmaxf(rmax1, __shfl_xor_sync(0xffffffffu, rmax1, 1));
        rmax1 = fmaxf(rmax1, __shfl_xor_sync(0xffffffffu, rmax1, 2));

        float mn0 = fmaxf(m0, rmax0), mn1 = fmaxf(m1, rmax1);
        float sc0 = __expf(m0 - mn0), sc1 = __expf(m1 - mn1);
        m0 = mn0; m1 = mn1;

        float ps0 = 0.f, ps1 = 0.f;
        uint32_t pa[4][2];
#pragma unroll
        for (int n8 = 0; n8 < 4; n8++) {
            float p0 = (cS[n8][0] < -1e29f) ? 0.f : __expf(cS[n8][0] - mn0);
            float p1 = (cS[n8][1] < -1e29f) ? 0.f : __expf(cS[n8][1] - mn0);
            float p2 = (cS[n8][2] < -1e29f) ? 0.f : __expf(cS[n8][2] - mn1);
            float p3 = (cS[n8][3] < -1e29f) ? 0.f : __expf(cS[n8][3] - mn1);
            ps0 += p0 + p1; ps1 += p2 + p3;
            pa[n8][0] = packh2(p0, p1);
            pa[n8][1] = packh2(p2, p3);
        }
        ps0 += __shfl_xor_sync(0xffffffffu, ps0, 1);
        ps0 += __shfl_xor_sync(0xffffffffu, ps0, 2);
        ps1 += __shfl_xor_sync(0xffffffffu, ps1, 1);
        ps1 += __shfl_xor_sync(0xffffffffu, ps1, 2);
        l0 = l0 * sc0 + ps0;
        l1 = l1 * sc1 + ps1;
#pragma unroll
        for (int t = 0; t < 8; t++) {
            o[t][0] *= sc0; o[t][1] *= sc0; o[t][2] *= sc1; o[t][3] *= sc1;
        }

#pragma unroll
        for (int kp = 0; kp < 2; kp++) {
            uint32_t a[4] = { pa[2 * kp][0], pa[2 * kp][1], pa[2 * kp + 1][0], pa[2 * kp + 1][1] };
#pragma unroll
            for (int np = 0; np < 4; np++) {
                uint32_t bv[4];
                LDSM_X4_T(bv, sb + VS_OFF +
                    (uint32_t)((kk0 + kp * 16 + a_r) * PADH + np * 16 + a_c) * 2);
                MMA_F16(o[2 * np],     a, bv[0], bv[1]);
                MMA_F16(o[2 * np + 1], a, bv[2], bv[3]);
            }
        }
    }

    __syncthreads();
    float* ob = mgb + (warp_m * 32 + lane) * 33;
    float2* mlb = (float2*)(mgb + 4 * 32 * 33);
    if (warp_n == 1) {
#pragma unroll
        for (int t = 0; t < 8; t++)
#pragma unroll
            for (int j = 0; j < 4; j++) ob[4 * t + j] = o[t][j];
        if ((lane & 3) == 0) {
            mlb[warp_m * 16 + (lane >> 2)]     = make_float2(m0, l0);
            mlb[warp_m * 16 + 8 + (lane >> 2)] = make_float2(m1, l1);
        }
    }
    __syncthreads();
    if (warp_n == 0) {
        float2 M0 = mlb[warp_m * 16 + (lane >> 2)];
        float2 M1 = mlb[warp_m * 16 + 8 + (lane >> 2)];
        float mm0 = fmaxf(m0, M0.x), mm1 = fmaxf(m1, M1.x);
        float w00 = __expf(m0 - mm0), w01 = __expf(M0.x - mm0);
        float w10 = __expf(m1 - mm1), w11 = __expf(M1.x - mm1);
        float inv0 = 1.0f / (l0 * w00 + M0.y * w01);
        float inv1 = 1.0f / (l1 * w10 + M1.y * w11);
        size_t r0 = (size_t)(b * TSEQ + qlo + (lane >> 2)) * DMODEL;
        size_t r1 = r0 + 8 * DMODEL;
#pragma unroll
        for (int t = 0; t < 8; t++) {
            int col = h * HD + t * 8 + 2 * (lane & 3);
            float v0 = (o[t][0] * w00 + ob[4 * t + 0] * w01) * inv0;
            float v1 = (o[t][1] * w00 + ob[4 * t + 1] * w01) * inv0;
            float v2 = (o[t][2] * w10 + ob[4 * t + 2] * w11) * inv1;
            float v3 = (o[t][3] * w10 + ob[4 * t + 3] * w11) * inv1;
            *(__half2*)(g_Ah + r0 + col) = __floats2half2_rn(v0, v1);
            *(__half2*)(g_Ah + r1 + col) = __floats2half2_rn(v2, v3);
        }
    }
}

// ---------------------------------------------------------------------------
extern "C" void kernel_launch(void* const* d_in, const int* in_sizes, int n_in,
                              void* d_out, int out_size)
{
    const float* x    = (const float*)d_in[0];
    const float* Wqkv = (const float*)d_in[1];
    const float* Wout = (const float*)d_in[2];
    const float* bout = (const float*)d_in[3];
    float* out = (float*)d_out;

    __half *Ah, *Al, *Bh;
    cudaGetSymbolAddress((void**)&Ah, g_Ah);
    cudaGetSymbolAddress((void**)&Al, g_Al);
    cudaGetSymbolAddress((void**)&Bh, g_Bh);

    const int GEMM_SMEM_S1 = 2 * 3 * MAT_BYTES;   // 110592 (SPLIT=1)
    const int GEMM_SMEM_S0 = 2 * 2 * MAT_BYTES;   // 73728  (SPLIT=0)

    cudaFuncSetAttribute(gemm_mma<1, 1>, cudaFuncAttributeMaxDynamicSharedMemorySize, GEMM_SMEM_S1);
    cudaFuncSetAttribute(gemm_mma<0, 0>, cudaFuncAttributeMaxDynamicSharedMemorySize, GEMM_SMEM_S0);
    cudaFuncSetAttribute(attn_kernel, cudaFuncAttributeMaxDynamicSharedMemorySize, ATTN_SMEM);

    rope_table<<<(TSEQ * 16 + 255) / 256, 256>>>();

    split_a<<<(ROWS * DMODEL + 511) / 512, 512>>>(x, Ah, Al, ROWS * DMODEL);
    wconv<<<dim3(QKVCOLS / 32, DMODEL / 32), 256>>>(Wqkv, Bh, DMODEL, QKVCOLS);
    // QKV projection: 1-term for Q,K blocks, 2-term for V blocks; fused rope/pack
    gemm_mma<1, 1><<<dim3(QKVCOLS / BN, ROWS / BM), 256, GEMM_SMEM_S1>>>(
        Ah, Al, Bh, nullptr, ROWS, QKVCOLS, DMODEL, nullptr);

    attn_kernel<<<dim3(TSEQ / 64, NHEAD, NB), 256, ATTN_SMEM>>>();

    wconv<<<dim3(DMODEL / 32, DMODEL / 32), 256>>>(Wout, Bh, DMODEL, DMODEL);
    // Output projection: 1-term A (attention output fp16)
    gemm_mma<0, 0><<<dim3(DMODEL / BN, ROWS / BM), 256, GEMM_SMEM_S0>>>(
        Ah, nullptr, Bh, out, ROWS, DMODEL, DMODEL, bout);
}

// round 12
// speedup vs baseline: 1.6036x; 1.1408x over previous
#include <cuda_runtime.h>
#include <cuda_fp16.h>
#include <math.h>
#include <stdint.h>

#define NB      4
#define TSEQ    2048
#define NHEAD   16
#define HD      64
#define DMODEL  1024
#define ROWS    (NB * TSEQ)          // 8192
#define QKVCOLS (3 * DMODEL)         // 3072
#define WIN     128

// ---------------- scratch (allocation-free rule: device globals) ----------
__device__ __align__(16) __half g_Ah[ROWS   * DMODEL];
__device__ __align__(16) __half g_Bh[QKVCOLS * DMODEL];  // [N][K] transposed fp16
__device__ __align__(16) __half g_qr[ROWS * DMODEL];     // [b,h][t][d] roped+scaled Q (hi)
__device__ __align__(16) __half g_ql[ROWS * DMODEL];     // [b,h][t][d] roped+scaled Q (lo)
__device__ __align__(16) __half g_kr[ROWS * DMODEL];     // [b,h][t][d] roped K
__device__ __align__(16) __half g_vp[ROWS * DMODEL];     // [b,h][t][d] packed V
__device__ float4 g_rope[TSEQ * 16];  // (t, pg): cos/sin for freqs 2pg, 2pg+1

// ---------------- PTX helpers ---------------------------------------------
__device__ __forceinline__ uint32_t smem_u32(const void* p) {
    uint32_t a;
    asm("{ .reg .u64 t; cvta.to.shared.u64 t, %1; cvt.u32.u64 %0, t; }" : "=r"(a) : "l"(p));
    return a;
}
__device__ __forceinline__ void cp16(uint32_t dst, const void* src) {
    asm volatile("cp.async.cg.shared.global [%0], [%1], 16;" :: "r"(dst), "l"(src));
}
#define CP_COMMIT() asm volatile("cp.async.commit_group;" ::: "memory")
#define CP_WAIT(n)  asm volatile("cp.async.wait_group %0;" :: "n"(n) : "memory")

#define LDSM_X4(r, addr) \
    asm volatile("ldmatrix.sync.aligned.m8n8.x4.shared.b16 {%0,%1,%2,%3}, [%4];" \
        : "=r"((r)[0]), "=r"((r)[1]), "=r"((r)[2]), "=r"((r)[3]) : "r"(addr))
#define LDSM_X4_T(r, addr) \
    asm volatile("ldmatrix.sync.aligned.m8n8.x4.trans.shared.b16 {%0,%1,%2,%3}, [%4];" \
        : "=r"((r)[0]), "=r"((r)[1]), "=r"((r)[2]), "=r"((r)[3]) : "r"(addr))

#define MMA_F16(c, a, b0, b1) \
    asm volatile("mma.sync.aligned.m16n8k16.row.col.f32.f16.f16.f32 " \
        "{%0,%1,%2,%3}, {%4,%5,%6,%7}, {%8,%9}, {%0,%1,%2,%3};" \
        : "+f"((c)[0]), "+f"((c)[1]), "+f"((c)[2]), "+f"((c)[3]) \
        : "r"((a)[0]), "r"((a)[1]), "r"((a)[2]), "r"((a)[3]), "r"(b0), "r"(b1))

__device__ __forceinline__ uint32_t packh2(float a, float b) {
    __half2 h = __floats2half2_rn(a, b);
    return *reinterpret_cast<uint32_t*>(&h);
}

// ---------------- mma.sync GEMM: C = A[M,K]*Bt[N,K]^T, 1-term fp16 A --------
// CTA 128x128, 8 warps (4m x 2n), warp 32x64. BK=64, 3-stage cp.async,
// one barrier per chunk. MODE 0: fp32 C + bias. MODE 1: fused rope/pack.
#define BM 128
#define BN 128
#define BK 64
#define PADK 72
#define MAT_BYTES (128 * PADK * 2)    // 18432
#define STAGE_B (2 * MAT_BYTES)       // 36864
#define GEMM_SMEM (3 * STAGE_B)       // 110592 (2 CTA/SM: 221184 <= 228KB)

__device__ __forceinline__ void load_chunk(
    uint32_t sb, const __half* __restrict__ Ah, const __half* __restrict__ Bh,
    int brow, int bcol, int K, int kc, int stage, int tid)
{
    uint32_t base = sb + stage * STAGE_B;
#pragma unroll
    for (int t = 0; t < 4; t++) {
        int idx = tid + t * 256;
        int row = idx >> 3;
        int c16 = idx & 7;
        uint32_t so = (uint32_t)(row * (PADK * 2) + c16 * 16);
        cp16(base + so, Ah + (size_t)(brow + row) * K + kc + c16 * 8);
        cp16(base + MAT_BYTES + so, Bh + (size_t)(bcol + row) * K + kc + c16 * 8);
    }
}

template <int MODE>
__global__ __launch_bounds__(256, 2)
void gemm_mma(const __half* __restrict__ Ah, const __half* __restrict__ Bh,
              float* __restrict__ C, int M, int N, int K,
              const float* __restrict__ bias)
{
    extern __shared__ __align__(128) char smem[];
    uint32_t sb = smem_u32(smem);
    const int tid  = threadIdx.x;
    const int wid  = tid >> 5;
    const int lane = tid & 31;
    const int wm = (wid & 3) * 32;
    const int wn = (wid >> 2) * 64;
    const int brow = blockIdx.y * BM, bcol = blockIdx.x * BN;

    float c[2][8][4];
#pragma unroll
    for (int i = 0; i < 2; i++)
#pragma unroll
        for (int j = 0; j < 8; j++)
#pragma unroll
            for (int r = 0; r < 4; r++) c[i][j][r] = 0.0f;

    const int nchunks = K / BK;       // 16
    load_chunk(sb, Ah, Bh, brow, bcol, K, 0, 0, tid);
    CP_COMMIT();
    load_chunk(sb, Ah, Bh, brow, bcol, K, BK, 1, tid);
    CP_COMMIT();

    const int a_r = lane & 15;
    const int a_c = (lane >> 4) << 3;
    const int b_r = ((lane < 16) ? (lane & 7) : (8 + (lane & 7)));
    const int b_c = ((lane >> 3) & 1) << 3;

    for (int ch = 0; ch < nchunks; ch++) {
        if (ch + 1 < nchunks) { CP_WAIT(1); } else { CP_WAIT(0); }
        __syncthreads();
        if (ch + 2 < nchunks) {
            load_chunk(sb, Ah, Bh, brow, bcol, K, (ch + 2) * BK, (ch + 2) % 3, tid);
            CP_COMMIT();
        }
        uint32_t stb = sb + (ch % 3) * STAGE_B;
#pragma unroll
        for (int ks = 0; ks < 4; ks++) {
            const int kb = ks * 16;
            uint32_t ah[2][4], bh[4][4];
#pragma unroll
            for (int mt = 0; mt < 2; mt++) {
                uint32_t ad = stb +
                    (uint32_t)((wm + mt * 16 + a_r) * (PADK * 2) + (kb + a_c) * 2);
                LDSM_X4(ah[mt], ad);
            }
#pragma unroll
            for (int nt = 0; nt < 4; nt++) {
                uint32_t bd = stb + MAT_BYTES +
                    (uint32_t)((wn + nt * 16 + b_r) * (PADK * 2) + (kb + b_c) * 2);
                LDSM_X4(bh[nt], bd);
            }
#pragma unroll
            for (int mt = 0; mt < 2; mt++)
#pragma unroll
                for (int n8 = 0; n8 < 8; n8++)
                    MMA_F16(c[mt][n8], ah[mt],
                            bh[n8 >> 1][(n8 & 1) * 2], bh[n8 >> 1][(n8 & 1) * 2 + 1]);
        }
    }

    if (MODE == 0) {
#pragma unroll
        for (int mt = 0; mt < 2; mt++) {
            int row0 = brow + wm + mt * 16 + (lane >> 2);
#pragma unroll
            for (int n8 = 0; n8 < 8; n8++) {
                int col = bcol + wn + n8 * 8 + (lane & 3) * 2;
                float bx = bias[col], by = bias[col + 1];
                *(float2*)(C + (size_t)row0 * N + col) =
                    make_float2(c[mt][n8][0] + bx, c[mt][n8][1] + by);
                *(float2*)(C + (size_t)(row0 + 8) * N + col) =
                    make_float2(c[mt][n8][2] + bx, c[mt][n8][3] + by);
            }
        }
    } else {
        // fused rope/pack: warp's 64-col block = one (comp, head); pairs
        // (n8, n8+4) hold dims (d, d+32). Q written as hi/lo fp16 split.
        const int colbase = bcol + wn;
        const int comp = colbase >> 10;            // 0=q 1=k 2=v
        const int head = (colbase & 1023) >> 6;
#pragma unroll
        for (int mt = 0; mt < 2; mt++) {
#pragma unroll
            for (int r = 0; r < 2; r++) {
                int row = brow + wm + mt * 16 + (lane >> 2) + 8 * r;   // b*T + t
                int t = row & (TSEQ - 1);
                int bidx = row >> 11;
                size_t dst = ((size_t)(bidx * NHEAD + head) * TSEQ + t) * HD;
#pragma unroll
                for (int n8 = 0; n8 < 4; n8++) {
                    int d = n8 * 8 + 2 * (lane & 3);
                    float x1a = c[mt][n8][2 * r],     x1b = c[mt][n8][2 * r + 1];
                    float x2a = c[mt][n8 + 4][2 * r], x2b = c[mt][n8 + 4][2 * r + 1];
                    if (comp == 2) {
                        *(__half2*)(g_vp + dst + d)      = __floats2half2_rn(x1a, x1b);
                        *(__half2*)(g_vp + dst + d + 32) = __floats2half2_rn(x2a, x2b);
                    } else {
                        float4 cs = g_rope[t * 16 + (d >> 1)];
                        float o1a = x1a * cs.x - x2a * cs.y;
                        float o1b = x1b * cs.z - x2b * cs.w;
                        float o2a = x1a * cs.y + x2a * cs.x;
                        float o2b = x1b * cs.w + x2b * cs.z;
                        if (comp == 0) {
                            o1a *= 0.125f; o1b *= 0.125f; o2a *= 0.125f; o2b *= 0.125f;
                            __half h1a = __float2half(o1a), h1b = __float2half(o1b);
                            __half h2a = __float2half(o2a), h2b = __float2half(o2b);
                            *(__half2*)(g_qr + dst + d)      = __halves2half2(h1a, h1b);
                            *(__half2*)(g_qr + dst + d + 32) = __halves2half2(h2a, h2b);
                            *(__half2*)(g_ql + dst + d) = __halves2half2(
                                __float2half(o1a - __half2float(h1a)),
                                __float2half(o1b - __half2float(h1b)));
                            *(__half2*)(g_ql + dst + d + 32) = __halves2half2(
                                __float2half(o2a - __half2float(h2a)),
                                __float2half(o2b - __half2float(h2b)));
                        } else {
                            *(__half2*)(g_kr + dst + d)      = __floats2half2_rn(o1a, o1b);
                            *(__half2*)(g_kr + dst + d + 32) = __floats2half2_rn(o2a, o2b);
                        }
                    }
                }
            }
        }
    }
}

// ---------------- fp32 -> fp16 convert (x input) ----------------------------
__global__ void conv_a(const float* __restrict__ src, __half* __restrict__ h, int n)
{
    int i = blockIdx.x * blockDim.x + threadIdx.x;
    if (i >= n) return;
    h[i] = __float2half(src[i]);
}

// W[K][N] -> Bt[N][K] fp16, smem-tiled transpose
__global__ void wconv(const float* __restrict__ W, __half* __restrict__ Bt, int K, int N)
{
    __shared__ float tile[32][33];
    int n0 = blockIdx.x * 32, k0 = blockIdx.y * 32;
    int tx = threadIdx.x & 31, ty = threadIdx.x >> 5;
#pragma unroll
    for (int r = 0; r < 4; r++)
        tile[ty + 8 * r][tx] = W[(size_t)(k0 + ty + 8 * r) * N + n0 + tx];
    __syncthreads();
#pragma unroll
    for (int r = 0; r < 4; r++)
        Bt[(size_t)(n0 + ty + 8 * r) * K + k0 + tx] = __float2half(tile[tx][ty + 8 * r]);
}

// ---------------- RoPE cos/sin table ----------------------------------------
__global__ void rope_table()
{
    int idx = blockIdx.x * blockDim.x + threadIdx.x;
    if (idx >= TSEQ * 16) return;
    int t = idx >> 4, pg = idx & 15;
    float c0, s0, c1, s1;
    {
        float e = (float)(2 * (2 * pg)) * (1.0f / 64.0f);
        float ang = (float)t * exp2f(-e * 13.2877123795494493f);
        sincosf(ang, &s0, &c0);
    }
    {
        float e = (float)(2 * (2 * pg + 1)) * (1.0f / 64.0f);
        float ang = (float)t * exp2f(-e * 13.2877123795494493f);
        sincosf(ang, &s1, &c1);
    }
    g_rope[idx] = make_float4(c0, s0, c1, s1);
}

// ---------------- flash attention via mma.sync -------------------------------
// Q 2-term (Qh+Ql) for accurate scores; output written fp16 (hi only).
#define PADH 72
#define QS_BYTES (64 * PADH * 2)        // 9216
#define QL_OFF   QS_BYTES
#define KS_OFF   (2 * QS_BYTES)        // 18432
#define KS_BYTES (320 * PADH * 2)       // 46080
#define VS_OFF   (KS_OFF + KS_BYTES)
#define ATTN_SMEM (VS_OFF + KS_BYTES)   // 110592

__global__ __launch_bounds__(256, 2)
void attn_kernel()
{
    extern __shared__ __align__(128) char asmem[];
    uint32_t sb = smem_u32(asmem);
    float* mgb = (float*)(asmem + KS_OFF);   // merge buffer aliases Ks

    const int tid = threadIdx.x, wid = tid >> 5, lane = tid & 31;
    const int b = blockIdx.z, h = blockIdx.y;
    const int t0 = blockIdx.x * 64;
    const int warp_m = wid & 3, warp_n = wid >> 2;

    const size_t bh = (size_t)(b * NHEAD + h) * TSEQ;

    {
        const __half* qsrc = g_qr + (bh + t0) * HD;
        const __half* lsrc = g_ql + (bh + t0) * HD;
        for (int idx = tid; idx < 64 * 8; idx += 256) {
            int row = idx >> 3, cc = idx & 7;
            uint32_t so = (uint32_t)(row * PADH + cc * 8) * 2;
            cp16(sb + so, qsrc + row * HD + cc * 8);
            cp16(sb + QL_OFF + so, lsrc + row * HD + cc * 8);
        }
    }
    {
        const __half* ksrc = g_kr + bh * HD;
        const __half* vsrc = g_vp + bh * HD;
        for (int idx = tid; idx < 320 * 8; idx += 256) {
            int kk = idx >> 3, cc = idx & 7;
            int kg = t0 - 128 + kk;
            kg = kg < 0 ? 0 : (kg > TSEQ - 1 ? TSEQ - 1 : kg);
            cp16(sb + KS_OFF + (uint32_t)(kk * PADH + cc * 8) * 2, ksrc + (size_t)kg * HD + cc * 8);
            cp16(sb + VS_OFF + (uint32_t)(kk * PADH + cc * 8) * 2, vsrc + (size_t)kg * HD + cc * 8);
        }
    }
    CP_COMMIT();
    CP_WAIT(0);
    __syncthreads();

    const int a_r = lane & 15;
    const int a_c = (lane >> 4) << 3;
    const int b_r = ((lane < 16) ? (lane & 7) : (8 + (lane & 7)));
    const int b_c = ((lane >> 3) & 1) << 3;
    const int qlo = t0 + warp_m * 16;
    const int qi0 = qlo + (lane >> 2);

    float m0 = -1e30f, m1 = -1e30f, l0 = 0.f, l1 = 0.f;
    float o[8][4];
#pragma unroll
    for (int t = 0; t < 8; t++)
#pragma unroll
        for (int j = 0; j < 4; j++) o[t][j] = 0.f;

    for (int c = 0; c < 5; c++) {
        int kk0 = 64 * c + 32 * warp_n;
        int kgb = t0 - 128 + kk0;
        if (kgb + 31 < qlo - WIN || kgb > qlo + 15 + WIN) continue;

        float cS[4][4];
#pragma unroll
        for (int i = 0; i < 4; i++)
#pragma unroll
            for (int j = 0; j < 4; j++) cS[i][j] = 0.f;
#pragma unroll
        for (int ks = 0; ks < 4; ks++) {
            uint32_t aqh[4], aql[4], bk0[4], bk1[4];
            uint32_t qa = sb + (uint32_t)((warp_m * 16 + a_r) * PADH + ks * 16 + a_c) * 2;
            LDSM_X4(aqh, qa);
            LDSM_X4(aql, qa + QL_OFF);
            LDSM_X4(bk0, sb + KS_OFF + (uint32_t)((kk0 + b_r) * PADH + ks * 16 + b_c) * 2);
            LDSM_X4(bk1, sb + KS_OFF + (uint32_t)((kk0 + 16 + b_r) * PADH + ks * 16 + b_c) * 2);
            MMA_F16(cS[0], aqh, bk0[0], bk0[1]);
            MMA_F16(cS[1], aqh, bk0[2], bk0[3]);
            MMA_F16(cS[2], aqh, bk1[0], bk1[1]);
            MMA_F16(cS[3], aqh, bk1[2], bk1[3]);
            MMA_F16(cS[0], aql, bk0[0], bk0[1]);
            MMA_F16(cS[1], aql, bk0[2], bk0[3]);
            MMA_F16(cS[2], aql, bk1[0], bk1[1]);
            MMA_F16(cS[3], aql, bk1[2], bk1[3]);
        }

        float rmax0 = -1e30f, rmax1 = -1e30f;
#pragma unroll
        for (int n8 = 0; n8 < 4; n8++) {
            int jb = kgb + 8 * n8 + 2 * (lane & 3);
#pragma unroll
            for (int e = 0; e < 2; e++) {
                int j = jb + e;
                bool okj = (j >= 0) && (j < TSEQ);
                if (!(okj && j >= qi0 - WIN && j <= qi0 + WIN))         cS[n8][e]     = -1e30f;
                if (!(okj && j >= qi0 + 8 - WIN && j <= qi0 + 8 + WIN)) cS[n8][e + 2] = -1e30f;
            }
            rmax0 = fmaxf(rmax0, fmaxf(cS[n8][0], cS[n8][1]));
            rmax1 = fmaxf(rmax1, fmaxf(cS[n8][2], cS[n8][3]));
        }
        rmax0 = fmaxf(rmax0, __shfl_xor_sync(0xffffffffu, rmax0, 1));
        rmax0 = fmaxf(rmax0, __shfl_xor_sync(0xffffffffu, rmax0, 2));
        rmax1 = fmaxf(rmax1, __shfl_xor_sync(0xffffffffu, rmax1, 1));
        rmax1 = fmaxf(rmax1, __shfl_xor_sync(0xffffffffu, rmax1, 2));

        float mn0 = fmaxf(m0, rmax0), mn1 = fmaxf(m1, rmax1);
        float sc0 = __expf(m0 - mn0), sc1 = __expf(m1 - mn1);
        m0 = mn0; m1 = mn1;

        float ps0 = 0.f, ps1 = 0.f;
        uint32_t pa[4][2];
#pragma unroll
        for (int n8 = 0; n8 < 4; n8++) {
            float p0 = (cS[n8][0] < -1e29f) ? 0.f : __expf(cS[n8][0] - mn0);
            float p1 = (cS[n8][1] < -1e29f) ? 0.f : __expf(cS[n8][1] - mn0);
            float p2 = (cS[n8][2] < -1e29f) ? 0.f : __expf(cS[n8][2] - mn1);
            float p3 = (cS[n8][3] < -1e29f) ? 0.f : __expf(cS[n8][3] - mn1);
            ps0 += p0 + p1; ps1 += p2 + p3;
            pa[n8][0] = packh2(p0, p1);
            pa[n8][1] = packh2(p2, p3);
        }
        ps0 += __shfl_xor_sync(0xffffffffu, ps0, 1);
        ps0 += __shfl_xor_sync(0xffffffffu, ps0, 2);
        ps1 += __shfl_xor_sync(0xffffffffu, ps1, 1);
        ps1 += __shfl_xor_sync(0xffffffffu, ps1, 2);
        l0 = l0 * sc0 + ps0;
        l1 = l1 * sc1 + ps1;
#pragma unroll
        for (int t = 0; t < 8; t++) {
            o[t][0] *= sc0; o[t][1] *= sc0; o[t][2] *= sc1; o[t][3] *= sc1;
        }

#pragma unroll
        for (int kp = 0; kp < 2; kp++) {
            uint32_t a[4] = { pa[2 * kp][0], pa[2 * kp][1], pa[2 * kp + 1][0], pa[2 * kp + 1][1] };
#pragma unroll
            for (int np = 0; np < 4; np++) {
                uint32_t bv[4];
                LDSM_X4_T(bv, sb + VS_OFF +
                    (uint32_t)((kk0 + kp * 16 + a_r) * PADH + np * 16 + a_c) * 2);
                MMA_F16(o[2 * np],     a, bv[0], bv[1]);
                MMA_F16(o[2 * np + 1], a, bv[2], bv[3]);
            }
        }
    }

    __syncthreads();
    float* ob = mgb + (warp_m * 32 + lane) * 33;
    float2* mlb = (float2*)(mgb + 4 * 32 * 33);
    if (warp_n == 1) {
#pragma unroll
        for (int t = 0; t < 8; t++)
#pragma unroll
            for (int j = 0; j < 4; j++) ob[4 * t + j] = o[t][j];
        if ((lane & 3) == 0) {
            mlb[warp_m * 16 + (lane >> 2)]     = make_float2(m0, l0);
            mlb[warp_m * 16 + 8 + (lane >> 2)] = make_float2(m1, l1);
        }
    }
    __syncthreads();
    if (warp_n == 0) {
        float2 M0 = mlb[warp_m * 16 + (lane >> 2)];
        float2 M1 = mlb[warp_m * 16 + 8 + (lane >> 2)];
        float mm0 = fmaxf(m0, M0.x), mm1 = fmaxf(m1, M1.x);
        float w00 = __expf(m0 - mm0), w01 = __expf(M0.x - mm0);
        float w10 = __expf(m1 - mm1), w11 = __expf(M1.x - mm1);
        float inv0 = 1.0f / (l0 * w00 + M0.y * w01);
        float inv1 = 1.0f / (l1 * w10 + M1.y * w11);
        size_t r0 = (size_t)(b * TSEQ + qlo + (lane >> 2)) * DMODEL;
        size_t r1 = r0 + 8 * DMODEL;
#pragma unroll
        for (int t = 0; t < 8; t++) {
            int col = h * HD + t * 8 + 2 * (lane & 3);
            float v0 = (o[t][0] * w00 + ob[4 * t + 0] * w01) * inv0;
            float v1 = (o[t][1] * w00 + ob[4 * t + 1] * w01) * inv0;
            float v2 = (o[t][2] * w10 + ob[4 * t + 2] * w11) * inv1;
            float v3 = (o[t][3] * w10 + ob[4 * t + 3] * w11) * inv1;
            *(__half2*)(g_Ah + r0 + col) = __floats2half2_rn(v0, v1);
            *(__half2*)(g_Ah + r1 + col) = __floats2half2_rn(v2, v3);
        }
    }
}

// ---------------------------------------------------------------------------
extern "C" void kernel_launch(void* const* d_in, const int* in_sizes, int n_in,
                              void* d_out, int out_size)
{
    const float* x    = (const float*)d_in[0];
    const float* Wqkv = (const float*)d_in[1];
    const float* Wout = (const float*)d_in[2];
    const float* bout = (const float*)d_in[3];
    float* out = (float*)d_out;

    __half *Ah, *Bh;
    cudaGetSymbolAddress((void**)&Ah, g_Ah);
    cudaGetSymbolAddress((void**)&Bh, g_Bh);

    cudaFuncSetAttribute(gemm_mma<0>, cudaFuncAttributeMaxDynamicSharedMemorySize, GEMM_SMEM);
    cudaFuncSetAttribute(gemm_mma<1>, cudaFuncAttributeMaxDynamicSharedMemorySize, GEMM_SMEM);
    cudaFuncSetAttribute(attn_kernel, cudaFuncAttributeMaxDynamicSharedMemorySize, ATTN_SMEM);

    rope_table<<<(TSEQ * 16 + 255) / 256, 256>>>();

    conv_a<<<(ROWS * DMODEL + 511) / 512, 512>>>(x, Ah, ROWS * DMODEL);
    wconv<<<dim3(QKVCOLS / 32, DMODEL / 32), 256>>>(Wqkv, Bh, DMODEL, QKVCOLS);
    // QKV projection (1-term) with fused rope/pack epilogue
    gemm_mma<1><<<dim3(QKVCOLS / BN, ROWS / BM), 256, GEMM_SMEM>>>(
        Ah, Bh, nullptr, ROWS, QKVCOLS, DMODEL, nullptr);

    attn_kernel<<<dim3(TSEQ / 64, NHEAD, NB), 256, ATTN_SMEM>>>();

    wconv<<<dim3(DMODEL / 32, DMODEL / 32), 256>>>(Wout, Bh, DMODEL, DMODEL);
    // Output projection (1-term)
    gemm_mma<0><<<dim3(DMODEL / BN, ROWS / BM), 256, GEMM_SMEM>>>(
        Ah, Bh, out, ROWS, DMODEL, DMODEL, bout);
}

// round 13
// speedup vs baseline: 1.7669x; 1.1018x over previous
#include <cuda_runtime.h>
#include <cuda_fp16.h>
#include <math.h>
#include <stdint.h>

#define NB      4
#define TSEQ    2048
#define NHEAD   16
#define HD      64
#define DMODEL  1024
#define ROWS    (NB * TSEQ)          // 8192
#define QKVCOLS (3 * DMODEL)         // 3072
#define WIN     128

// ---------------- scratch (allocation-free rule: device globals) ----------
__device__ __align__(16) __half g_Ah[ROWS   * DMODEL];
__device__ __align__(16) __half g_Bh[QKVCOLS * DMODEL];  // [N][K] transposed fp16
__device__ __align__(16) __half g_Bo[DMODEL * DMODEL];   // out-proj weights [N][K]
__device__ __align__(16) __half g_qr[ROWS * DMODEL];     // [b,h][t][d] roped+scaled Q (hi)
__device__ __align__(16) __half g_ql[ROWS * DMODEL];     // [b,h][t][d] roped+scaled Q (lo)
__device__ __align__(16) __half g_kr[ROWS * DMODEL];     // [b,h][t][d] roped K
__device__ __align__(16) __half g_vp[ROWS * DMODEL];     // [b,h][t][d] packed V
__device__ float4 g_rope[TSEQ * 16];  // (t, pg): cos/sin for freqs 2pg, 2pg+1

// ---------------- PTX helpers ---------------------------------------------
__device__ __forceinline__ uint32_t smem_u32(const void* p) {
    uint32_t a;
    asm("{ .reg .u64 t; cvta.to.shared.u64 t, %1; cvt.u32.u64 %0, t; }" : "=r"(a) : "l"(p));
    return a;
}
__device__ __forceinline__ void cp16(uint32_t dst, const void* src) {
    asm volatile("cp.async.cg.shared.global [%0], [%1], 16;" :: "r"(dst), "l"(src));
}
#define CP_COMMIT() asm volatile("cp.async.commit_group;" ::: "memory")
#define CP_WAIT(n)  asm volatile("cp.async.wait_group %0;" :: "n"(n) : "memory")

#define LDSM_X4(r, addr) \
    asm volatile("ldmatrix.sync.aligned.m8n8.x4.shared.b16 {%0,%1,%2,%3}, [%4];" \
        : "=r"((r)[0]), "=r"((r)[1]), "=r"((r)[2]), "=r"((r)[3]) : "r"(addr))
#define LDSM_X4_T(r, addr) \
    asm volatile("ldmatrix.sync.aligned.m8n8.x4.trans.shared.b16 {%0,%1,%2,%3}, [%4];" \
        : "=r"((r)[0]), "=r"((r)[1]), "=r"((r)[2]), "=r"((r)[3]) : "r"(addr))

#define MMA_F16(c, a, b0, b1) \
    asm volatile("mma.sync.aligned.m16n8k16.row.col.f32.f16.f16.f32 " \
        "{%0,%1,%2,%3}, {%4,%5,%6,%7}, {%8,%9}, {%0,%1,%2,%3};" \
        : "+f"((c)[0]), "+f"((c)[1]), "+f"((c)[2]), "+f"((c)[3]) \
        : "r"((a)[0]), "r"((a)[1]), "r"((a)[2]), "r"((a)[3]), "r"(b0), "r"(b1))

__device__ __forceinline__ uint32_t packh2(float a, float b) {
    __half2 h = __floats2half2_rn(a, b);
    return *reinterpret_cast<uint32_t*>(&h);
}

// ---------------- mma.sync GEMM: C = A[M,K]*Bt[N,K]^T, 1-term fp16 A --------
// CTA 128x128, 8 warps (4m x 2n), warp 32x64. BK=64, 3-stage cp.async.
#define BM 128
#define BN 128
#define BK 64
#define PADK 72
#define MAT_BYTES (128 * PADK * 2)    // 18432
#define STAGE_B (2 * MAT_BYTES)       // 36864
#define GEMM_SMEM (3 * STAGE_B)       // 110592

__device__ __forceinline__ void load_chunk(
    uint32_t sb, const __half* __restrict__ Ah, const __half* __restrict__ Bh,
    int brow, int bcol, int K, int kc, int stage, int tid)
{
    uint32_t base = sb + stage * STAGE_B;
#pragma unroll
    for (int t = 0; t < 4; t++) {
        int idx = tid + t * 256;
        int row = idx >> 3;
        int c16 = idx & 7;
        uint32_t so = (uint32_t)(row * (PADK * 2) + c16 * 16);
        cp16(base + so, Ah + (size_t)(brow + row) * K + kc + c16 * 8);
        cp16(base + MAT_BYTES + so, Bh + (size_t)(bcol + row) * K + kc + c16 * 8);
    }
}

template <int MODE>
__global__ __launch_bounds__(256, 2)
void gemm_mma(const __half* __restrict__ Ah, const __half* __restrict__ Bh,
              float* __restrict__ C, int M, int N, int K,
              const float* __restrict__ bias)
{
    extern __shared__ __align__(128) char smem[];
    uint32_t sb = smem_u32(smem);
    const int tid  = threadIdx.x;
    const int wid  = tid >> 5;
    const int lane = tid & 31;
    const int wm = (wid & 3) * 32;
    const int wn = (wid >> 2) * 64;
    const int brow = blockIdx.y * BM, bcol = blockIdx.x * BN;

    float c[2][8][4];
#pragma unroll
    for (int i = 0; i < 2; i++)
#pragma unroll
        for (int j = 0; j < 8; j++)
#pragma unroll
            for (int r = 0; r < 4; r++) c[i][j][r] = 0.0f;

    const int nchunks = K / BK;       // 16
    load_chunk(sb, Ah, Bh, brow, bcol, K, 0, 0, tid);
    CP_COMMIT();
    load_chunk(sb, Ah, Bh, brow, bcol, K, BK, 1, tid);
    CP_COMMIT();

    const int a_r = lane & 15;
    const int a_c = (lane >> 4) << 3;
    const int b_r = ((lane < 16) ? (lane & 7) : (8 + (lane & 7)));
    const int b_c = ((lane >> 3) & 1) << 3;

    for (int ch = 0; ch < nchunks; ch++) {
        if (ch + 1 < nchunks) { CP_WAIT(1); } else { CP_WAIT(0); }
        __syncthreads();
        if (ch + 2 < nchunks) {
            load_chunk(sb, Ah, Bh, brow, bcol, K, (ch + 2) * BK, (ch + 2) % 3, tid);
            CP_COMMIT();
        }
        uint32_t stb = sb + (ch % 3) * STAGE_B;
#pragma unroll
        for (int ks = 0; ks < 4; ks++) {
            const int kb = ks * 16;
            uint32_t ah[2][4], bh[4][4];
#pragma unroll
            for (int mt = 0; mt < 2; mt++) {
                uint32_t ad = stb +
                    (uint32_t)((wm + mt * 16 + a_r) * (PADK * 2) + (kb + a_c) * 2);
                LDSM_X4(ah[mt], ad);
            }
#pragma unroll
            for (int nt = 0; nt < 4; nt++) {
                uint32_t bd = stb + MAT_BYTES +
                    (uint32_t)((wn + nt * 16 + b_r) * (PADK * 2) + (kb + b_c) * 2);
                LDSM_X4(bh[nt], bd);
            }
#pragma unroll
            for (int mt = 0; mt < 2; mt++)
#pragma unroll
                for (int n8 = 0; n8 < 8; n8++)
                    MMA_F16(c[mt][n8], ah[mt],
                            bh[n8 >> 1][(n8 & 1) * 2], bh[n8 >> 1][(n8 & 1) * 2 + 1]);
        }
    }

    if (MODE == 0) {
#pragma unroll
        for (int mt = 0; mt < 2; mt++) {
            int row0 = brow + wm + mt * 16 + (lane >> 2);
#pragma unroll
            for (int n8 = 0; n8 < 8; n8++) {
                int col = bcol + wn + n8 * 8 + (lane & 3) * 2;
                float bx = bias[col], by = bias[col + 1];
                *(float2*)(C + (size_t)row0 * N + col) =
                    make_float2(c[mt][n8][0] + bx, c[mt][n8][1] + by);
                *(float2*)(C + (size_t)(row0 + 8) * N + col) =
                    make_float2(c[mt][n8][2] + bx, c[mt][n8][3] + by);
            }
        }
    } else {
        const int colbase = bcol + wn;
        const int comp = colbase >> 10;            // 0=q 1=k 2=v
        const int head = (colbase & 1023) >> 6;
#pragma unroll
        for (int mt = 0; mt < 2; mt++) {
#pragma unroll
            for (int r = 0; r < 2; r++) {
                int row = brow + wm + mt * 16 + (lane >> 2) + 8 * r;   // b*T + t
                int t = row & (TSEQ - 1);
                int bidx = row >> 11;
                size_t dst = ((size_t)(bidx * NHEAD + head) * TSEQ + t) * HD;
#pragma unroll
                for (int n8 = 0; n8 < 4; n8++) {
                    int d = n8 * 8 + 2 * (lane & 3);
                    float x1a = c[mt][n8][2 * r],     x1b = c[mt][n8][2 * r + 1];
                    float x2a = c[mt][n8 + 4][2 * r], x2b = c[mt][n8 + 4][2 * r + 1];
                    if (comp == 2) {
                        *(__half2*)(g_vp + dst + d)      = __floats2half2_rn(x1a, x1b);
                        *(__half2*)(g_vp + dst + d + 32) = __floats2half2_rn(x2a, x2b);
                    } else {
                        float4 cs = g_rope[t * 16 + (d >> 1)];
                        float o1a = x1a * cs.x - x2a * cs.y;
                        float o1b = x1b * cs.z - x2b * cs.w;
                        float o2a = x1a * cs.y + x2a * cs.x;
                        float o2b = x1b * cs.w + x2b * cs.z;
                        if (comp == 0) {
                            o1a *= 0.125f; o1b *= 0.125f; o2a *= 0.125f; o2b *= 0.125f;
                            __half h1a = __float2half(o1a), h1b = __float2half(o1b);
                            __half h2a = __float2half(o2a), h2b = __float2half(o2b);
                            *(__half2*)(g_qr + dst + d)      = __halves2half2(h1a, h1b);
                            *(__half2*)(g_qr + dst + d + 32) = __halves2half2(h2a, h2b);
                            *(__half2*)(g_ql + dst + d) = __halves2half2(
                                __float2half(o1a - __half2float(h1a)),
                                __float2half(o1b - __half2float(h1b)));
                            *(__half2*)(g_ql + dst + d + 32) = __halves2half2(
                                __float2half(o2a - __half2float(h2a)),
                                __float2half(o2b - __half2float(h2b)));
                        } else {
                            *(__half2*)(g_kr + dst + d)      = __floats2half2_rn(o1a, o1b);
                            *(__half2*)(g_kr + dst + d + 32) = __floats2half2_rn(o2a, o2b);
                        }
                    }
                }
            }
        }
    }
}

// ---------------- fused prep: conv_a + wconv(Wqkv) + wconv(Wout) + rope -----
#define CONV_BLKS  (ROWS * DMODEL / 1024)            // 8192 (256 thr x 4 elems)
#define W1_BLKS    ((QKVCOLS / 32) * (DMODEL / 32))  // 3072
#define W2_BLKS    ((DMODEL / 32) * (DMODEL / 32))   // 1024
#define ROPE_BLKS  ((TSEQ * 16) / 256)               // 128
#define PREP_BLKS  (CONV_BLKS + W1_BLKS + W2_BLKS + ROPE_BLKS)

__device__ __forceinline__ void wconv_body(
    const float* __restrict__ W, __half* __restrict__ Bt,
    int K, int N, int bx, int by, float* tile /*[32][33]*/)
{
    int n0 = bx * 32, k0 = by * 32;
    int tx = threadIdx.x & 31, ty = threadIdx.x >> 5;
#pragma unroll
    for (int r = 0; r < 4; r++)
        tile[(ty + 8 * r) * 33 + tx] = W[(size_t)(k0 + ty + 8 * r) * N + n0 + tx];
    __syncthreads();
#pragma unroll
    for (int r = 0; r < 4; r++)
        Bt[(size_t)(n0 + ty + 8 * r) * K + k0 + tx] = __float2half(tile[tx * 33 + ty + 8 * r]);
}

__global__ void prep_kernel(const float* __restrict__ x,
                            const float* __restrict__ Wqkv,
                            const float* __restrict__ Wout)
{
    __shared__ float tile[32 * 33];
    int bid = blockIdx.x;
    if (bid < CONV_BLKS) {
        int base = (bid * 256 + threadIdx.x) * 4;
        float4 v = *(const float4*)(x + base);
        *(__half2*)(g_Ah + base)     = __floats2half2_rn(v.x, v.y);
        *(__half2*)(g_Ah + base + 2) = __floats2half2_rn(v.z, v.w);
    } else if (bid < CONV_BLKS + W1_BLKS) {
        int i = bid - CONV_BLKS;
        wconv_body(Wqkv, g_Bh, DMODEL, QKVCOLS, i % (QKVCOLS / 32), i / (QKVCOLS / 32), tile);
    } else if (bid < CONV_BLKS + W1_BLKS + W2_BLKS) {
        int i = bid - CONV_BLKS - W1_BLKS;
        wconv_body(Wout, g_Bo, DMODEL, DMODEL, i % (DMODEL / 32), i / (DMODEL / 32), tile);
    } else {
        int idx = (bid - CONV_BLKS - W1_BLKS - W2_BLKS) * 256 + threadIdx.x;
        int t = idx >> 4, pg = idx & 15;
        float c0, s0, c1, s1;
        {
            float e = (float)(2 * (2 * pg)) * (1.0f / 64.0f);
            float ang = (float)t * exp2f(-e * 13.2877123795494493f);
            sincosf(ang, &s0, &c0);
        }
        {
            float e = (float)(2 * (2 * pg + 1)) * (1.0f / 64.0f);
            float ang = (float)t * exp2f(-e * 13.2877123795494493f);
            sincosf(ang, &s1, &c1);
        }
        g_rope[idx] = make_float4(c0, s0, c1, s1);
    }
}

// ---------------- flash attention via mma.sync -------------------------------
// Q 2-term (Qh+Ql); interior slabs skip masking; l kept lane-distributed.
#define PADH 72
#define QS_BYTES (64 * PADH * 2)        // 9216
#define QL_OFF   QS_BYTES
#define KS_OFF   (2 * QS_BYTES)        // 18432
#define KS_BYTES (320 * PADH * 2)       // 46080
#define VS_OFF   (KS_OFF + KS_BYTES)
#define ATTN_SMEM (VS_OFF + KS_BYTES)   // 110592

__global__ __launch_bounds__(256, 2)
void attn_kernel()
{
    extern __shared__ __align__(128) char asmem[];
    uint32_t sb = smem_u32(asmem);
    float* mgb = (float*)(asmem + KS_OFF);   // merge buffer aliases Ks

    const int tid = threadIdx.x, wid = tid >> 5, lane = tid & 31;
    const int b = blockIdx.z, h = blockIdx.y;
    const int t0 = blockIdx.x * 64;
    const int warp_m = wid & 3, warp_n = wid >> 2;

    const size_t bh = (size_t)(b * NHEAD + h) * TSEQ;

    {
        const __half* qsrc = g_qr + (bh + t0) * HD;
        const __half* lsrc = g_ql + (bh + t0) * HD;
        for (int idx = tid; idx < 64 * 8; idx += 256) {
            int row = idx >> 3, cc = idx & 7;
            uint32_t so = (uint32_t)(row * PADH + cc * 8) * 2;
            cp16(sb + so, qsrc + row * HD + cc * 8);
            cp16(sb + QL_OFF + so, lsrc + row * HD + cc * 8);
        }
    }
    {
        const __half* ksrc = g_kr + bh * HD;
        const __half* vsrc = g_vp + bh * HD;
        for (int idx = tid; idx < 320 * 8; idx += 256) {
            int kk = idx >> 3, cc = idx & 7;
            int kg = t0 - 128 + kk;
            kg = kg < 0 ? 0 : (kg > TSEQ - 1 ? TSEQ - 1 : kg);
            cp16(sb + KS_OFF + (uint32_t)(kk * PADH + cc * 8) * 2, ksrc + (size_t)kg * HD + cc * 8);
            cp16(sb + VS_OFF + (uint32_t)(kk * PADH + cc * 8) * 2, vsrc + (size_t)kg * HD + cc * 8);
        }
    }
    CP_COMMIT();
    CP_WAIT(0);
    __syncthreads();

    const int a_r = lane & 15;
    const int a_c = (lane >> 4) << 3;
    const int b_r = ((lane < 16) ? (lane & 7) : (8 + (lane & 7)));
    const int b_c = ((lane >> 3) & 1) << 3;
    const int qlo = t0 + warp_m * 16;
    const int qi0 = qlo + (lane >> 2);

    float m0 = -1e30f, m1 = -1e30f, l0 = 0.f, l1 = 0.f;   // l lane-distributed
    float o[8][4];
#pragma unroll
    for (int t = 0; t < 8; t++)
#pragma unroll
        for (int j = 0; j < 4; j++) o[t][j] = 0.f;

    for (int c = 0; c < 5; c++) {
        int kk0 = 64 * c + 32 * warp_n;
        int kgb = t0 - 128 + kk0;
        if (kgb + 31 < qlo - WIN || kgb > qlo + 15 + WIN) continue;
        // interior: every key in slab valid for every query of this warp
        bool interior = (kgb >= qlo + 15 - WIN) && (kgb + 31 <= qlo + WIN) &&
                        (kgb >= 0) && (kgb + 31 <= TSEQ - 1);

        float cS[4][4];
#pragma unroll
        for (int i = 0; i < 4; i++)
#pragma unroll
            for (int j = 0; j < 4; j++) cS[i][j] = 0.f;
#pragma unroll
        for (int ks = 0; ks < 4; ks++) {
            uint32_t aqh[4], aql[4], bk0[4], bk1[4];
            uint32_t qa = sb + (uint32_t)((warp_m * 16 + a_r) * PADH + ks * 16 + a_c) * 2;
            LDSM_X4(aqh, qa);
            LDSM_X4(aql, qa + QL_OFF);
            LDSM_X4(bk0, sb + KS_OFF + (uint32_t)((kk0 + b_r) * PADH + ks * 16 + b_c) * 2);
            LDSM_X4(bk1, sb + KS_OFF + (uint32_t)((kk0 + 16 + b_r) * PADH + ks * 16 + b_c) * 2);
            MMA_F16(cS[0], aqh, bk0[0], bk0[1]);
            MMA_F16(cS[1], aqh, bk0[2], bk0[3]);
            MMA_F16(cS[2], aqh, bk1[0], bk1[1]);
            MMA_F16(cS[3], aqh, bk1[2], bk1[3]);
            MMA_F16(cS[0], aql, bk0[0], bk0[1]);
            MMA_F16(cS[1], aql, bk0[2], bk0[3]);
            MMA_F16(cS[2], aql, bk1[0], bk1[1]);
            MMA_F16(cS[3], aql, bk1[2], bk1[3]);
        }

        float rmax0 = -1e30f, rmax1 = -1e30f;
        if (!interior) {
#pragma unroll
            for (int n8 = 0; n8 < 4; n8++) {
                int jb = kgb + 8 * n8 + 2 * (lane & 3);
#pragma unroll
                for (int e = 0; e < 2; e++) {
                    int j = jb + e;
                    bool okj = (j >= 0) && (j < TSEQ);
                    if (!(okj && j >= qi0 - WIN && j <= qi0 + WIN))         cS[n8][e]     = -1e30f;
                    if (!(okj && j >= qi0 + 8 - WIN && j <= qi0 + 8 + WIN)) cS[n8][e + 2] = -1e30f;
                }
            }
        }
#pragma unroll
        for (int n8 = 0; n8 < 4; n8++) {
            rmax0 = fmaxf(rmax0, fmaxf(cS[n8][0], cS[n8][1]));
            rmax1 = fmaxf(rmax1, fmaxf(cS[n8][2], cS[n8][3]));
        }
        rmax0 = fmaxf(rmax0, __shfl_xor_sync(0xffffffffu, rmax0, 1));
        rmax0 = fmaxf(rmax0, __shfl_xor_sync(0xffffffffu, rmax0, 2));
        rmax1 = fmaxf(rmax1, __shfl_xor_sync(0xffffffffu, rmax1, 1));
        rmax1 = fmaxf(rmax1, __shfl_xor_sync(0xffffffffu, rmax1, 2));

        float mn0 = fmaxf(m0, rmax0), mn1 = fmaxf(m1, rmax1);
        float sc0 = __expf(m0 - mn0), sc1 = __expf(m1 - mn1);
        m0 = mn0; m1 = mn1;

        float ps0 = 0.f, ps1 = 0.f;
        uint32_t pa[4][2];
        if (interior) {
#pragma unroll
            for (int n8 = 0; n8 < 4; n8++) {
                float p0 = __expf(cS[n8][0] - mn0);
                float p1 = __expf(cS[n8][1] - mn0);
                float p2 = __expf(cS[n8][2] - mn1);
                float p3 = __expf(cS[n8][3] - mn1);
                ps0 += p0 + p1; ps1 += p2 + p3;
                pa[n8][0] = packh2(p0, p1);
                pa[n8][1] = packh2(p2, p3);
            }
        } else {
#pragma unroll
            for (int n8 = 0; n8 < 4; n8++) {
                float p0 = (cS[n8][0] < -1e29f) ? 0.f : __expf(cS[n8][0] - mn0);
                float p1 = (cS[n8][1] < -1e29f) ? 0.f : __expf(cS[n8][1] - mn0);
                float p2 = (cS[n8][2] < -1e29f) ? 0.f : __expf(cS[n8][2] - mn1);
                float p3 = (cS[n8][3] < -1e29f) ? 0.f : __expf(cS[n8][3] - mn1);
                ps0 += p0 + p1; ps1 += p2 + p3;
                pa[n8][0] = packh2(p0, p1);
                pa[n8][1] = packh2(p2, p3);
            }
        }
        l0 = l0 * sc0 + ps0;      // lane-distributed partial
        l1 = l1 * sc1 + ps1;
#pragma unroll
        for (int t = 0; t < 8; t++) {
            o[t][0] *= sc0; o[t][1] *= sc0; o[t][2] *= sc1; o[t][3] *= sc1;
        }

#pragma unroll
        for (int kp = 0; kp < 2; kp++) {
            uint32_t a[4] = { pa[2 * kp][0], pa[2 * kp][1], pa[2 * kp + 1][0], pa[2 * kp + 1][1] };
#pragma unroll
            for (int np = 0; np < 4; np++) {
                uint32_t bv[4];
                LDSM_X4_T(bv, sb + VS_OFF +
                    (uint32_t)((kk0 + kp * 16 + a_r) * PADH + np * 16 + a_c) * 2);
                MMA_F16(o[2 * np],     a, bv[0], bv[1]);
                MMA_F16(o[2 * np + 1], a, bv[2], bv[3]);
            }
        }
    }

    // reduce distributed l across the quad (lanes sharing a row)
    l0 += __shfl_xor_sync(0xffffffffu, l0, 1);
    l0 += __shfl_xor_sync(0xffffffffu, l0, 2);
    l1 += __shfl_xor_sync(0xffffffffu, l1, 1);
    l1 += __shfl_xor_sync(0xffffffffu, l1, 2);

    __syncthreads();
    float* ob = mgb + (warp_m * 32 + lane) * 33;
    float2* mlb = (float2*)(mgb + 4 * 32 * 33);
    if (warp_n == 1) {
#pragma unroll
        for (int t = 0; t < 8; t++)
#pragma unroll
            for (int j = 0; j < 4; j++) ob[4 * t + j] = o[t][j];
        if ((lane & 3) == 0) {
            mlb[warp_m * 16 + (lane >> 2)]     = make_float2(m0, l0);
            mlb[warp_m * 16 + 8 + (lane >> 2)] = make_float2(m1, l1);
        }
    }
    __syncthreads();
    if (warp_n == 0) {
        float2 M0 = mlb[warp_m * 16 + (lane >> 2)];
        float2 M1 = mlb[warp_m * 16 + 8 + (lane >> 2)];
        float mm0 = fmaxf(m0, M0.x), mm1 = fmaxf(m1, M1.x);
        float w00 = __expf(m0 - mm0), w01 = __expf(M0.x - mm0);
        float w10 = __expf(m1 - mm1), w11 = __expf(M1.x - mm1);
        float inv0 = 1.0f / (l0 * w00 + M0.y * w01);
        float inv1 = 1.0f / (l1 * w10 + M1.y * w11);
        size_t r0 = (size_t)(b * TSEQ + qlo + (lane >> 2)) * DMODEL;
        size_t r1 = r0 + 8 * DMODEL;
#pragma unroll
        for (int t = 0; t < 8; t++) {
            int col = h * HD + t * 8 + 2 * (lane & 3);
            float v0 = (o[t][0] * w00 + ob[4 * t + 0] * w01) * inv0;
            float v1 = (o[t][1] * w00 + ob[4 * t + 1] * w01) * inv0;
            float v2 = (o[t][2] * w10 + ob[4 * t + 2] * w11) * inv1;
            float v3 = (o[t][3] * w10 + ob[4 * t + 3] * w11) * inv1;
            *(__half2*)(g_Ah + r0 + col) = __floats2half2_rn(v0, v1);
            *(__half2*)(g_Ah + r1 + col) = __floats2half2_rn(v2, v3);
        }
    }
}

// ---------------------------------------------------------------------------
extern "C" void kernel_launch(void* const* d_in, const int* in_sizes, int n_in,
                              void* d_out, int out_size)
{
    const float* x    = (const float*)d_in[0];
    const float* Wqkv = (const float*)d_in[1];
    const float* Wout = (const float*)d_in[2];
    const float* bout = (const float*)d_in[3];
    float* out = (float*)d_out;

    __half *Ah, *Bh, *Bo;
    cudaGetSymbolAddress((void**)&Ah, g_Ah);
    cudaGetSymbolAddress((void**)&Bh, g_Bh);
    cudaGetSymbolAddress((void**)&Bo, g_Bo);

    cudaFuncSetAttribute(gemm_mma<0>, cudaFuncAttributeMaxDynamicSharedMemorySize, GEMM_SMEM);
    cudaFuncSetAttribute(gemm_mma<1>, cudaFuncAttributeMaxDynamicSharedMemorySize, GEMM_SMEM);
    cudaFuncSetAttribute(attn_kernel, cudaFuncAttributeMaxDynamicSharedMemorySize, ATTN_SMEM);

    // fused prep: x->fp16, both weight transposes, rope table
    prep_kernel<<<PREP_BLKS, 256>>>(x, Wqkv, Wout);

    // QKV projection (1-term) with fused rope/pack epilogue
    gemm_mma<1><<<dim3(QKVCOLS / BN, ROWS / BM), 256, GEMM_SMEM>>>(
        Ah, Bh, nullptr, ROWS, QKVCOLS, DMODEL, nullptr);

    attn_kernel<<<dim3(TSEQ / 64, NHEAD, NB), 256, ATTN_SMEM>>>();

    // Output projection (1-term)
    gemm_mma<0><<<dim3(DMODEL / BN, ROWS / BM), 256, GEMM_SMEM>>>(
        Ah, Bo, out, ROWS, DMODEL, DMODEL, bout);
}

// round 14
// speedup vs baseline: 1.8181x; 1.0290x over previous
#include <cuda_runtime.h>
#include <cuda_fp16.h>
#include <math.h>
#include <stdint.h>

#define NB      4
#define TSEQ    2048
#define NHEAD   16
#define HD      64
#define DMODEL  1024
#define ROWS    (NB * TSEQ)          // 8192
#define QKVCOLS (3 * DMODEL)         // 3072
#define WIN     128

// ---------------- scratch (allocation-free rule: device globals) ----------
__device__ __align__(16) __half g_Ah[ROWS   * DMODEL];
__device__ __align__(16) __half g_Bh[QKVCOLS * DMODEL];  // [N][K] transposed fp16
__device__ __align__(16) __half g_Bo[DMODEL * DMODEL];   // out-proj weights [N][K]
__device__ __align__(16) __half g_qr[ROWS * DMODEL];     // [b,h][t][d] roped+scaled Q (hi)
__device__ __align__(16) __half g_ql[ROWS * DMODEL];     // [b,h][t][d] roped+scaled Q (lo)
__device__ __align__(16) __half g_kr[ROWS * DMODEL];     // [b,h][t][d] roped K
__device__ __align__(16) __half g_vp[ROWS * DMODEL];     // [b,h][t][d] packed V
__device__ float4 g_rope[TSEQ * 16];  // (t, pg): cos/sin for freqs 2pg, 2pg+1

// ---------------- PTX helpers ---------------------------------------------
__device__ __forceinline__ uint32_t smem_u32(const void* p) {
    uint32_t a;
    asm("{ .reg .u64 t; cvta.to.shared.u64 t, %1; cvt.u32.u64 %0, t; }" : "=r"(a) : "l"(p));
    return a;
}
__device__ __forceinline__ void cp16(uint32_t dst, const void* src) {
    asm volatile("cp.async.cg.shared.global [%0], [%1], 16;" :: "r"(dst), "l"(src));
}
#define CP_COMMIT() asm volatile("cp.async.commit_group;" ::: "memory")
#define CP_WAIT(n)  asm volatile("cp.async.wait_group %0;" :: "n"(n) : "memory")

#define LDSM_X4(r, addr) \
    asm volatile("ldmatrix.sync.aligned.m8n8.x4.shared.b16 {%0,%1,%2,%3}, [%4];" \
        : "=r"((r)[0]), "=r"((r)[1]), "=r"((r)[2]), "=r"((r)[3]) : "r"(addr))
#define LDSM_X4_T(r, addr) \
    asm volatile("ldmatrix.sync.aligned.m8n8.x4.trans.shared.b16 {%0,%1,%2,%3}, [%4];" \
        : "=r"((r)[0]), "=r"((r)[1]), "=r"((r)[2]), "=r"((r)[3]) : "r"(addr))

#define MMA_F16(c, a, b0, b1) \
    asm volatile("mma.sync.aligned.m16n8k16.row.col.f32.f16.f16.f32 " \
        "{%0,%1,%2,%3}, {%4,%5,%6,%7}, {%8,%9}, {%0,%1,%2,%3};" \
        : "+f"((c)[0]), "+f"((c)[1]), "+f"((c)[2]), "+f"((c)[3]) \
        : "r"((a)[0]), "r"((a)[1]), "r"((a)[2]), "r"((a)[3]), "r"(b0), "r"(b1))

__device__ __forceinline__ uint32_t packh2(float a, float b) {
    __half2 h = __floats2half2_rn(a, b);
    return *reinterpret_cast<uint32_t*>(&h);
}

// ---------------- mma.sync GEMM: C = A[M,K]*Bt[N,K]^T, 1-term fp16 A --------
// CTA 128x128 with 128 threads: 4 warps (2m x 2n), warp tile 64x64.
// BK=64, 2-stage cp.async, 3 CTAs/SM (launch_bounds 128,3 -> <=170 regs).
// B-fragments ephemeral (loaded per-nt) to fit the register cap.
#define BM 128
#define BN 128
#define BK 64
#define PADK 72
#define MAT_BYTES (128 * PADK * 2)    // 18432
#define STAGE_B (2 * MAT_BYTES)       // 36864
#define GEMM_SMEM (2 * STAGE_B)       // 73728 (3 CTA/SM: 221184 <= 228KB)

__device__ __forceinline__ void load_chunk(
    uint32_t sb, const __half* __restrict__ Ah, const __half* __restrict__ Bh,
    int brow, int bcol, int K, int kc, int stage, int tid)
{
    uint32_t base = sb + stage * STAGE_B;
#pragma unroll
    for (int t = 0; t < 8; t++) {
        int idx = tid + t * 128;          // 0..1023
        int row = idx >> 3;
        int c16 = idx & 7;
        uint32_t so = (uint32_t)(row * (PADK * 2) + c16 * 16);
        cp16(base + so, Ah + (size_t)(brow + row) * K + kc + c16 * 8);
        cp16(base + MAT_BYTES + so, Bh + (size_t)(bcol + row) * K + kc + c16 * 8);
    }
}

template <int MODE>
__global__ __launch_bounds__(128, 3)
void gemm_mma(const __half* __restrict__ Ah, const __half* __restrict__ Bh,
              float* __restrict__ C, int M, int N, int K,
              const float* __restrict__ bias)
{
    extern __shared__ __align__(128) char smem[];
    uint32_t sb = smem_u32(smem);
    const int tid  = threadIdx.x;
    const int wid  = tid >> 5;
    const int lane = tid & 31;
    const int wm = (wid >> 1) * 64;     // 2 warp-rows
    const int wn = (wid & 1) * 64;      // 2 warp-cols
    const int brow = blockIdx.y * BM, bcol = blockIdx.x * BN;

    float c[4][8][4];
#pragma unroll
    for (int i = 0; i < 4; i++)
#pragma unroll
        for (int j = 0; j < 8; j++)
#pragma unroll
            for (int r = 0; r < 4; r++) c[i][j][r] = 0.0f;

    const int nchunks = K / BK;       // 16
    load_chunk(sb, Ah, Bh, brow, bcol, K, 0, 0, tid);
    CP_COMMIT();

    const int a_r = lane & 15;
    const int a_c = (lane >> 4) << 3;
    const int b_r = ((lane < 16) ? (lane & 7) : (8 + (lane & 7)));
    const int b_c = ((lane >> 3) & 1) << 3;

    for (int ch = 0; ch < nchunks; ch++) {
        CP_WAIT(0);
        __syncthreads();
        if (ch + 1 < nchunks) {
            load_chunk(sb, Ah, Bh, brow, bcol, K, (ch + 1) * BK, (ch + 1) & 1, tid);
            CP_COMMIT();
        }
        uint32_t stb = sb + (ch & 1) * STAGE_B;
        const uint32_t aad = stb + (uint32_t)((wm + a_r) * (PADK * 2) + a_c * 2);
        const uint32_t bad = stb + MAT_BYTES + (uint32_t)((wn + b_r) * (PADK * 2) + b_c * 2);
#pragma unroll
        for (int ks = 0; ks < 4; ks++) {
            const uint32_t ko = (uint32_t)(ks * 32);   // 16 halves * 2B
            uint32_t ah[4][4];
#pragma unroll
            for (int mt = 0; mt < 4; mt++)
                LDSM_X4(ah[mt], aad + (uint32_t)(mt * 16 * PADK * 2) + ko);
#pragma unroll
            for (int nt = 0; nt < 4; nt++) {
                uint32_t bh[4];
                LDSM_X4(bh, bad + (uint32_t)(nt * 16 * PADK * 2) + ko);
#pragma unroll
                for (int mt = 0; mt < 4; mt++) {
                    MMA_F16(c[mt][2 * nt],     ah[mt], bh[0], bh[1]);
                    MMA_F16(c[mt][2 * nt + 1], ah[mt], bh[2], bh[3]);
                }
            }
        }
    }

    if (MODE == 0) {
#pragma unroll
        for (int mt = 0; mt < 4; mt++) {
            int row0 = brow + wm + mt * 16 + (lane >> 2);
#pragma unroll
            for (int n8 = 0; n8 < 8; n8++) {
                int col = bcol + wn + n8 * 8 + (lane & 3) * 2;
                float bx = bias[col], by = bias[col + 1];
                *(float2*)(C + (size_t)row0 * N + col) =
                    make_float2(c[mt][n8][0] + bx, c[mt][n8][1] + by);
                *(float2*)(C + (size_t)(row0 + 8) * N + col) =
                    make_float2(c[mt][n8][2] + bx, c[mt][n8][3] + by);
            }
        }
    } else {
        // fused rope/pack: warp's 64-col block = one (comp, head); pairs
        // (n8, n8+4) hold dims (d, d+32). Q written as hi/lo fp16 split.
        const int colbase = bcol + wn;
        const int comp = colbase >> 10;            // 0=q 1=k 2=v
        const int head = (colbase & 1023) >> 6;
#pragma unroll
        for (int mt = 0; mt < 4; mt++) {
#pragma unroll
            for (int r = 0; r < 2; r++) {
                int row = brow + wm + mt * 16 + (lane >> 2) + 8 * r;   // b*T + t
                int t = row & (TSEQ - 1);
                int bidx = row >> 11;
                size_t dst = ((size_t)(bidx * NHEAD + head) * TSEQ + t) * HD;
#pragma unroll
                for (int n8 = 0; n8 < 4; n8++) {
                    int d = n8 * 8 + 2 * (lane & 3);
                    float x1a = c[mt][n8][2 * r],     x1b = c[mt][n8][2 * r + 1];
                    float x2a = c[mt][n8 + 4][2 * r], x2b = c[mt][n8 + 4][2 * r + 1];
                    if (comp == 2) {
                        *(__half2*)(g_vp + dst + d)      = __floats2half2_rn(x1a, x1b);
                        *(__half2*)(g_vp + dst + d + 32) = __floats2half2_rn(x2a, x2b);
                    } else {
                        float4 cs = g_rope[t * 16 + (d >> 1)];
                        float o1a = x1a * cs.x - x2a * cs.y;
                        float o1b = x1b * cs.z - x2b * cs.w;
                        float o2a = x1a * cs.y + x2a * cs.x;
                        float o2b = x1b * cs.w + x2b * cs.z;
                        if (comp == 0) {
                            o1a *= 0.125f; o1b *= 0.125f; o2a *= 0.125f; o2b *= 0.125f;
                            __half h1a = __float2half(o1a), h1b = __float2half(o1b);
                            __half h2a = __float2half(o2a), h2b = __float2half(o2b);
                            *(__half2*)(g_qr + dst + d)      = __halves2half2(h1a, h1b);
                            *(__half2*)(g_qr + dst + d + 32) = __halves2half2(h2a, h2b);
                            *(__half2*)(g_ql + dst + d) = __halves2half2(
                                __float2half(o1a - __half2float(h1a)),
                                __float2half(o1b - __half2float(h1b)));
                            *(__half2*)(g_ql + dst + d + 32) = __halves2half2(
                                __float2half(o2a - __half2float(h2a)),
                                __float2half(o2b - __half2float(h2b)));
                        } else {
                            *(__half2*)(g_kr + dst + d)      = __floats2half2_rn(o1a, o1b);
                            *(__half2*)(g_kr + dst + d + 32) = __floats2half2_rn(o2a, o2b);
                        }
                    }
                }
            }
        }
    }
}

// ---------------- fused prep: conv_a + wconv(Wqkv) + wconv(Wout) + rope -----
#define CONV_BLKS  (ROWS * DMODEL / 1024)            // 8192 (256 thr x 4 elems)
#define W1_BLKS    ((QKVCOLS / 32) * (DMODEL / 32))  // 3072
#define W2_BLKS    ((DMODEL / 32) * (DMODEL / 32))   // 1024
#define ROPE_BLKS  ((TSEQ * 16) / 256)               // 128
#define PREP_BLKS  (CONV_BLKS + W1_BLKS + W2_BLKS + ROPE_BLKS)

__device__ __forceinline__ void wconv_body(
    const float* __restrict__ W, __half* __restrict__ Bt,
    int K, int N, int bx, int by, float* tile /*[32][33]*/)
{
    int n0 = bx * 32, k0 = by * 32;
    int tx = threadIdx.x & 31, ty = threadIdx.x >> 5;
#pragma unroll
    for (int r = 0; r < 4; r++)
        tile[(ty + 8 * r) * 33 + tx] = W[(size_t)(k0 + ty + 8 * r) * N + n0 + tx];
    __syncthreads();
#pragma unroll
    for (int r = 0; r < 4; r++)
        Bt[(size_t)(n0 + ty + 8 * r) * K + k0 + tx] = __float2half(tile[tx * 33 + ty + 8 * r]);
}

__global__ void prep_kernel(const float* __restrict__ x,
                            const float* __restrict__ Wqkv,
                            const float* __restrict__ Wout)
{
    __shared__ float tile[32 * 33];
    int bid = blockIdx.x;
    if (bid < CONV_BLKS) {
        int base = (bid * 256 + threadIdx.x) * 4;
        float4 v = *(const float4*)(x + base);
        *(__half2*)(g_Ah + base)     = __floats2half2_rn(v.x, v.y);
        *(__half2*)(g_Ah + base + 2) = __floats2half2_rn(v.z, v.w);
    } else if (bid < CONV_BLKS + W1_BLKS) {
        int i = bid - CONV_BLKS;
        wconv_body(Wqkv, g_Bh, DMODEL, QKVCOLS, i % (QKVCOLS / 32), i / (QKVCOLS / 32), tile);
    } else if (bid < CONV_BLKS + W1_BLKS + W2_BLKS) {
        int i = bid - CONV_BLKS - W1_BLKS;
        wconv_body(Wout, g_Bo, DMODEL, DMODEL, i % (DMODEL / 32), i / (DMODEL / 32), tile);
    } else {
        int idx = (bid - CONV_BLKS - W1_BLKS - W2_BLKS) * 256 + threadIdx.x;
        int t = idx >> 4, pg = idx & 15;
        float c0, s0, c1, s1;
        {
            float e = (float)(2 * (2 * pg)) * (1.0f / 64.0f);
            float ang = (float)t * exp2f(-e * 13.2877123795494493f);
            sincosf(ang, &s0, &c0);
        }
        {
            float e = (float)(2 * (2 * pg + 1)) * (1.0f / 64.0f);
            float ang = (float)t * exp2f(-e * 13.2877123795494493f);
            sincosf(ang, &s1, &c1);
        }
        g_rope[idx] = make_float4(c0, s0, c1, s1);
    }
}

// ---------------- flash attention via mma.sync -------------------------------
// Q 2-term (Qh+Ql); interior slabs skip masking; l kept lane-distributed.
#define PADH 72
#define QS_BYTES (64 * PADH * 2)        // 9216
#define QL_OFF   QS_BYTES
#define KS_OFF   (2 * QS_BYTES)        // 18432
#define KS_BYTES (320 * PADH * 2)       // 46080
#define VS_OFF   (KS_OFF + KS_BYTES)
#define ATTN_SMEM (VS_OFF + KS_BYTES)   // 110592

__global__ __launch_bounds__(256, 2)
void attn_kernel()
{
    extern __shared__ __align__(128) char asmem[];
    uint32_t sb = smem_u32(asmem);
    float* mgb = (float*)(asmem + KS_OFF);   // merge buffer aliases Ks

    const int tid = threadIdx.x, wid = tid >> 5, lane = tid & 31;
    const int b = blockIdx.z, h = blockIdx.y;
    const int t0 = blockIdx.x * 64;
    const int warp_m = wid & 3, warp_n = wid >> 2;

    const size_t bh = (size_t)(b * NHEAD + h) * TSEQ;

    {
        const __half* qsrc = g_qr + (bh + t0) * HD;
        const __half* lsrc = g_ql + (bh + t0) * HD;
        for (int idx = tid; idx < 64 * 8; idx += 256) {
            int row = idx >> 3, cc = idx & 7;
            uint32_t so = (uint32_t)(row * PADH + cc * 8) * 2;
            cp16(sb + so, qsrc + row * HD + cc * 8);
            cp16(sb + QL_OFF + so, lsrc + row * HD + cc * 8);
        }
    }
    {
        const __half* ksrc = g_kr + bh * HD;
        const __half* vsrc = g_vp + bh * HD;
        for (int idx = tid; idx < 320 * 8; idx += 256) {
            int kk = idx >> 3, cc = idx & 7;
            int kg = t0 - 128 + kk;
            kg = kg < 0 ? 0 : (kg > TSEQ - 1 ? TSEQ - 1 : kg);
            cp16(sb + KS_OFF + (uint32_t)(kk * PADH + cc * 8) * 2, ksrc + (size_t)kg * HD + cc * 8);
            cp16(sb + VS_OFF + (uint32_t)(kk * PADH + cc * 8) * 2, vsrc + (size_t)kg * HD + cc * 8);
        }
    }
    CP_COMMIT();
    CP_WAIT(0);
    __syncthreads();

    const int a_r = lane & 15;
    const int a_c = (lane >> 4) << 3;
    const int b_r = ((lane < 16) ? (lane & 7) : (8 + (lane & 7)));
    const int b_c = ((lane >> 3) & 1) << 3;
    const int qlo = t0 + warp_m * 16;
    const int qi0 = qlo + (lane >> 2);

    float m0 = -1e30f, m1 = -1e30f, l0 = 0.f, l1 = 0.f;   // l lane-distributed
    float o[8][4];
#pragma unroll
    for (int t = 0; t < 8; t++)
#pragma unroll
        for (int j = 0; j < 4; j++) o[t][j] = 0.f;

    for (int c = 0; c < 5; c++) {
        int kk0 = 64 * c + 32 * warp_n;
        int kgb = t0 - 128 + kk0;
        if (kgb + 31 < qlo - WIN || kgb > qlo + 15 + WIN) continue;
        bool interior = (kgb >= qlo + 15 - WIN) && (kgb + 31 <= qlo + WIN) &&
                        (kgb >= 0) && (kgb + 31 <= TSEQ - 1);

        float cS[4][4];
#pragma unroll
        for (int i = 0; i < 4; i++)
#pragma unroll
            for (int j = 0; j < 4; j++) cS[i][j] = 0.f;
#pragma unroll
        for (int ks = 0; ks < 4; ks++) {
            uint32_t aqh[4], aql[4], bk0[4], bk1[4];
            uint32_t qa = sb + (uint32_t)((warp_m * 16 + a_r) * PADH + ks * 16 + a_c) * 2;
            LDSM_X4(aqh, qa);
            LDSM_X4(aql, qa + QL_OFF);
            LDSM_X4(bk0, sb + KS_OFF + (uint32_t)((kk0 + b_r) * PADH + ks * 16 + b_c) * 2);
            LDSM_X4(bk1, sb + KS_OFF + (uint32_t)((kk0 + 16 + b_r) * PADH + ks * 16 + b_c) * 2);
            MMA_F16(cS[0], aqh, bk0[0], bk0[1]);
            MMA_F16(cS[1], aqh, bk0[2], bk0[3]);
            MMA_F16(cS[2], aqh, bk1[0], bk1[1]);
            MMA_F16(cS[3], aqh, bk1[2], bk1[3]);
            MMA_F16(cS[0], aql, bk0[0], bk0[1]);
            MMA_F16(cS[1], aql, bk0[2], bk0[3]);
            MMA_F16(cS[2], aql, bk1[0], bk1[1]);
            MMA_F16(cS[3], aql, bk1[2], bk1[3]);
        }

        float rmax0 = -1e30f, rmax1 = -1e30f;
        if (!interior) {
#pragma unroll
            for (int n8 = 0; n8 < 4; n8++) {
                int jb = kgb + 8 * n8 + 2 * (lane & 3);
#pragma unroll
                for (int e = 0; e < 2; e++) {
                    int j = jb + e;
                    bool okj = (j >= 0) && (j < TSEQ);
                    if (!(okj && j >= qi0 - WIN && j <= qi0 + WIN))         cS[n8][e]     = -1e30f;
                    if (!(okj && j >= qi0 + 8 - WIN && j <= qi0 + 8 + WIN)) cS[n8][e + 2] = -1e30f;
                }
            }
        }
#pragma unroll
        for (int n8 = 0; n8 < 4; n8++) {
            rmax0 = fmaxf(rmax0, fmaxf(cS[n8][0], cS[n8][1]));
            rmax1 = fmaxf(rmax1, fmaxf(cS[n8][2], cS[n8][3]));
        }
        rmax0 = fmaxf(rmax0, __shfl_xor_sync(0xffffffffu, rmax0, 1));
        rmax0 = fmaxf(rmax0, __shfl_xor_sync(0xffffffffu, rmax0, 2));
        rmax1 = fmaxf(rmax1, __shfl_xor_sync(0xffffffffu, rmax1, 1));
        rmax1 = fmaxf(rmax1, __shfl_xor_sync(0xffffffffu, rmax1, 2));

        float mn0 = fmaxf(m0, rmax0), mn1 = fmaxf(m1, rmax1);
        float sc0 = __expf(m0 - mn0), sc1 = __expf(m1 - mn1);
        m0 = mn0; m1 = mn1;

        float ps0 = 0.f, ps1 = 0.f;
        uint32_t pa[4][2];
        if (interior) {
#pragma unroll
            for (int n8 = 0; n8 < 4; n8++) {
                float p0 = __expf(cS[n8][0] - mn0);
                float p1 = __expf(cS[n8][1] - mn0);
                float p2 = __expf(cS[n8][2] - mn1);
                float p3 = __expf(cS[n8][3] - mn1);
                ps0 += p0 + p1; ps1 += p2 + p3;
                pa[n8][0] = packh2(p0, p1);
                pa[n8][1] = packh2(p2, p3);
            }
        } else {
#pragma unroll
            for (int n8 = 0; n8 < 4; n8++) {
                float p0 = (cS[n8][0] < -1e29f) ? 0.f : __expf(cS[n8][0] - mn0);
                float p1 = (cS[n8][1] < -1e29f) ? 0.f : __expf(cS[n8][1] - mn0);
                float p2 = (cS[n8][2] < -1e29f) ? 0.f : __expf(cS[n8][2] - mn1);
                float p3 = (cS[n8][3] < -1e29f) ? 0.f : __expf(cS[n8][3] - mn1);
                ps0 += p0 + p1; ps1 += p2 + p3;
                pa[n8][0] = packh2(p0, p1);
                pa[n8][1] = packh2(p2, p3);
            }
        }
        l0 = l0 * sc0 + ps0;
        l1 = l1 * sc1 + ps1;
#pragma unroll
        for (int t = 0; t < 8; t++) {
            o[t][0] *= sc0; o[t][1] *= sc0; o[t][2] *= sc1; o[t][3] *= sc1;
        }

#pragma unroll
        for (int kp = 0; kp < 2; kp++) {
            uint32_t a[4] = { pa[2 * kp][0], pa[2 * kp][1], pa[2 * kp + 1][0], pa[2 * kp + 1][1] };
#pragma unroll
            for (int np = 0; np < 4; np++) {
                uint32_t bv[4];
                LDSM_X4_T(bv, sb + VS_OFF +
                    (uint32_t)((kk0 + kp * 16 + a_r) * PADH + np * 16 + a_c) * 2);
                MMA_F16(o[2 * np],     a, bv[0], bv[1]);
                MMA_F16(o[2 * np + 1], a, bv[2], bv[3]);
            }
        }
    }

    l0 += __shfl_xor_sync(0xffffffffu, l0, 1);
    l0 += __shfl_xor_sync(0xffffffffu, l0, 2);
    l1 += __shfl_xor_sync(0xffffffffu, l1, 1);
    l1 += __shfl_xor_sync(0xffffffffu, l1, 2);

    __syncthreads();
    float* ob = mgb + (warp_m * 32 + lane) * 33;
    float2* mlb = (float2*)(mgb + 4 * 32 * 33);
    if (warp_n == 1) {
#pragma unroll
        for (int t = 0; t < 8; t++)
#pragma unroll
            for (int j = 0; j < 4; j++) ob[4 * t + j] = o[t][j];
        if ((lane & 3) == 0) {
            mlb[warp_m * 16 + (lane >> 2)]     = make_float2(m0, l0);
            mlb[warp_m * 16 + 8 + (lane >> 2)] = make_float2(m1, l1);
        }
    }
    __syncthreads();
    if (warp_n == 0) {
        float2 M0 = mlb[warp_m * 16 + (lane >> 2)];
        float2 M1 = mlb[warp_m * 16 + 8 + (lane >> 2)];
        float mm0 = fmaxf(m0, M0.x), mm1 = fmaxf(m1, M1.x);
        float w00 = __expf(m0 - mm0), w01 = __expf(M0.x - mm0);
        float w10 = __expf(m1 - mm1), w11 = __expf(M1.x - mm1);
        float inv0 = 1.0f / (l0 * w00 + M0.y * w01);
        float inv1 = 1.0f / (l1 * w10 + M1.y * w11);
        size_t r0 = (size_t)(b * TSEQ + qlo + (lane >> 2)) * DMODEL;
        size_t r1 = r0 + 8 * DMODEL;
#pragma unroll
        for (int t = 0; t < 8; t++) {
            int col = h * HD + t * 8 + 2 * (lane & 3);
            float v0 = (o[t][0] * w00 + ob[4 * t + 0] * w01) * inv0;
            float v1 = (o[t][1] * w00 + ob[4 * t + 1] * w01) * inv0;
            float v2 = (o[t][2] * w10 + ob[4 * t + 2] * w11) * inv1;
            float v3 = (o[t][3] * w10 + ob[4 * t + 3] * w11) * inv1;
            *(__half2*)(g_Ah + r0 + col) = __floats2half2_rn(v0, v1);
            *(__half2*)(g_Ah + r1 + col) = __floats2half2_rn(v2, v3);
        }
    }
}

// ---------------------------------------------------------------------------
extern "C" void kernel_launch(void* const* d_in, const int* in_sizes, int n_in,
                              void* d_out, int out_size)
{
    const float* x    = (const float*)d_in[0];
    const float* Wqkv = (const float*)d_in[1];
    const float* Wout = (const float*)d_in[2];
    const float* bout = (const float*)d_in[3];
    float* out = (float*)d_out;

    __half *Ah, *Bh, *Bo;
    cudaGetSymbolAddress((void**)&Ah, g_Ah);
    cudaGetSymbolAddress((void**)&Bh, g_Bh);
    cudaGetSymbolAddress((void**)&Bo, g_Bo);

    cudaFuncSetAttribute(gemm_mma<0>, cudaFuncAttributeMaxDynamicSharedMemorySize, GEMM_SMEM);
    cudaFuncSetAttribute(gemm_mma<1>, cudaFuncAttributeMaxDynamicSharedMemorySize, GEMM_SMEM);
    cudaFuncSetAttribute(attn_kernel, cudaFuncAttributeMaxDynamicSharedMemorySize, ATTN_SMEM);

    prep_kernel<<<PREP_BLKS, 256>>>(x, Wqkv, Wout);

    // QKV projection (1-term) with fused rope/pack epilogue
    gemm_mma<1><<<dim3(QKVCOLS / BN, ROWS / BM), 128, GEMM_SMEM>>>(
        Ah, Bh, nullptr, ROWS, QKVCOLS, DMODEL, nullptr);

    attn_kernel<<<dim3(TSEQ / 64, NHEAD, NB), 256, ATTN_SMEM>>>();

    // Output projection (1-term)
    gemm_mma<0><<<dim3(DMODEL / BN, ROWS / BM), 128, GEMM_SMEM>>>(
        Ah, Bo, out, ROWS, DMODEL, DMODEL, bout);
}

// round 15
// speedup vs baseline: 1.8767x; 1.0322x over previous
#include <cuda_runtime.h>
#include <cuda_fp16.h>
#include <math.h>
#include <stdint.h>

#define NB      4
#define TSEQ    2048
#define NHEAD   16
#define HD      64
#define DMODEL  1024
#define ROWS    (NB * TSEQ)          // 8192
#define QKVCOLS (3 * DMODEL)         // 3072
#define WIN     128

// ---------------- scratch (allocation-free rule: device globals) ----------
__device__ __align__(16) __half g_Ah[ROWS   * DMODEL];
__device__ __align__(16) __half g_Bh[QKVCOLS * DMODEL];  // [N][K] transposed fp16
__device__ __align__(16) __half g_Bo[DMODEL * DMODEL];   // out-proj weights [N][K]
__device__ __align__(16) __half g_qr[ROWS * DMODEL];     // [b,h][t][d] roped+scaled Q
__device__ __align__(16) __half g_kr[ROWS * DMODEL];     // [b,h][t][d] roped K
__device__ __align__(16) __half g_vp[ROWS * DMODEL];     // [b,h][t][d] packed V
__device__ float4 g_rope[TSEQ * 16];  // (t, pg): cos/sin for freqs 2pg, 2pg+1

// ---------------- PTX helpers ---------------------------------------------
__device__ __forceinline__ uint32_t smem_u32(const void* p) {
    uint32_t a;
    asm("{ .reg .u64 t; cvta.to.shared.u64 t, %1; cvt.u32.u64 %0, t; }" : "=r"(a) : "l"(p));
    return a;
}
__device__ __forceinline__ void cp16(uint32_t dst, const void* src) {
    asm volatile("cp.async.cg.shared.global [%0], [%1], 16;" :: "r"(dst), "l"(src));
}
#define CP_COMMIT() asm volatile("cp.async.commit_group;" ::: "memory")
#define CP_WAIT(n)  asm volatile("cp.async.wait_group %0;" :: "n"(n) : "memory")

#define LDSM_X4(r, addr) \
    asm volatile("ldmatrix.sync.aligned.m8n8.x4.shared.b16 {%0,%1,%2,%3}, [%4];" \
        : "=r"((r)[0]), "=r"((r)[1]), "=r"((r)[2]), "=r"((r)[3]) : "r"(addr))
#define LDSM_X4_T(r, addr) \
    asm volatile("ldmatrix.sync.aligned.m8n8.x4.trans.shared.b16 {%0,%1,%2,%3}, [%4];" \
        : "=r"((r)[0]), "=r"((r)[1]), "=r"((r)[2]), "=r"((r)[3]) : "r"(addr))

#define MMA_F16(c, a, b0, b1) \
    asm volatile("mma.sync.aligned.m16n8k16.row.col.f32.f16.f16.f32 " \
        "{%0,%1,%2,%3}, {%4,%5,%6,%7}, {%8,%9}, {%0,%1,%2,%3};" \
        : "+f"((c)[0]), "+f"((c)[1]), "+f"((c)[2]), "+f"((c)[3]) \
        : "r"((a)[0]), "r"((a)[1]), "r"((a)[2]), "r"((a)[3]), "r"(b0), "r"(b1))

__device__ __forceinline__ uint32_t packh2(float a, float b) {
    __half2 h = __floats2half2_rn(a, b);
    return *reinterpret_cast<uint32_t*>(&h);
}

// ---------------- mma.sync GEMM: C = A[M,K]*Bt[N,K]^T, 1-term fp16 A --------
// CTA 128x128, 128 threads: 4 warps (2m x 2n), warp 64x64. BK=64, 2-stage.
#define BM 128
#define BN 128
#define BK 64
#define PADK 72
#define MAT_BYTES (128 * PADK * 2)    // 18432
#define STAGE_B (2 * MAT_BYTES)       // 36864
#define GEMM_SMEM (2 * STAGE_B)       // 73728

__device__ __forceinline__ void load_chunk(
    uint32_t sb, const __half* __restrict__ Ah, const __half* __restrict__ Bh,
    int brow, int bcol, int K, int kc, int stage, int tid)
{
    uint32_t base = sb + stage * STAGE_B;
#pragma unroll
    for (int t = 0; t < 8; t++) {
        int idx = tid + t * 128;
        int row = idx >> 3;
        int c16 = idx & 7;
        uint32_t so = (uint32_t)(row * (PADK * 2) + c16 * 16);
        cp16(base + so, Ah + (size_t)(brow + row) * K + kc + c16 * 8);
        cp16(base + MAT_BYTES + so, Bh + (size_t)(bcol + row) * K + kc + c16 * 8);
    }
}

template <int MODE>
__global__ __launch_bounds__(128, 3)
void gemm_mma(const __half* __restrict__ Ah, const __half* __restrict__ Bh,
              float* __restrict__ C, int M, int N, int K,
              const float* __restrict__ bias)
{
    extern __shared__ __align__(128) char smem[];
    uint32_t sb = smem_u32(smem);
    const int tid  = threadIdx.x;
    const int wid  = tid >> 5;
    const int lane = tid & 31;
    const int wm = (wid >> 1) * 64;
    const int wn = (wid & 1) * 64;
    const int brow = blockIdx.y * BM, bcol = blockIdx.x * BN;

    float c[4][8][4];
#pragma unroll
    for (int i = 0; i < 4; i++)
#pragma unroll
        for (int j = 0; j < 8; j++)
#pragma unroll
            for (int r = 0; r < 4; r++) c[i][j][r] = 0.0f;

    const int nchunks = K / BK;
    load_chunk(sb, Ah, Bh, brow, bcol, K, 0, 0, tid);
    CP_COMMIT();

    const int a_r = lane & 15;
    const int a_c = (lane >> 4) << 3;
    const int b_r = ((lane < 16) ? (lane & 7) : (8 + (lane & 7)));
    const int b_c = ((lane >> 3) & 1) << 3;

    for (int ch = 0; ch < nchunks; ch++) {
        CP_WAIT(0);
        __syncthreads();
        if (ch + 1 < nchunks) {
            load_chunk(sb, Ah, Bh, brow, bcol, K, (ch + 1) * BK, (ch + 1) & 1, tid);
            CP_COMMIT();
        }
        uint32_t stb = sb + (ch & 1) * STAGE_B;
        const uint32_t aad = stb + (uint32_t)((wm + a_r) * (PADK * 2) + a_c * 2);
        const uint32_t bad = stb + MAT_BYTES + (uint32_t)((wn + b_r) * (PADK * 2) + b_c * 2);
#pragma unroll
        for (int ks = 0; ks < 4; ks++) {
            const uint32_t ko = (uint32_t)(ks * 32);
            uint32_t ah[4][4];
#pragma unroll
            for (int mt = 0; mt < 4; mt++)
                LDSM_X4(ah[mt], aad + (uint32_t)(mt * 16 * PADK * 2) + ko);
#pragma unroll
            for (int nt = 0; nt < 4; nt++) {
                uint32_t bh[4];
                LDSM_X4(bh, bad + (uint32_t)(nt * 16 * PADK * 2) + ko);
#pragma unroll
                for (int mt = 0; mt < 4; mt++) {
                    MMA_F16(c[mt][2 * nt],     ah[mt], bh[0], bh[1]);
                    MMA_F16(c[mt][2 * nt + 1], ah[mt], bh[2], bh[3]);
                }
            }
        }
    }

    if (MODE == 0) {
#pragma unroll
        for (int mt = 0; mt < 4; mt++) {
            int row0 = brow + wm + mt * 16 + (lane >> 2);
#pragma unroll
            for (int n8 = 0; n8 < 8; n8++) {
                int col = bcol + wn + n8 * 8 + (lane & 3) * 2;
                float bx = bias[col], by = bias[col + 1];
                *(float2*)(C + (size_t)row0 * N + col) =
                    make_float2(c[mt][n8][0] + bx, c[mt][n8][1] + by);
                *(float2*)(C + (size_t)(row0 + 8) * N + col) =
                    make_float2(c[mt][n8][2] + bx, c[mt][n8][3] + by);
            }
        }
    } else {
        const int colbase = bcol + wn;
        const int comp = colbase >> 10;            // 0=q 1=k 2=v
        const int head = (colbase & 1023) >> 6;
#pragma unroll
        for (int mt = 0; mt < 4; mt++) {
#pragma unroll
            for (int r = 0; r < 2; r++) {
                int row = brow + wm + mt * 16 + (lane >> 2) + 8 * r;   // b*T + t
                int t = row & (TSEQ - 1);
                int bidx = row >> 11;
                size_t dst = ((size_t)(bidx * NHEAD + head) * TSEQ + t) * HD;
#pragma unroll
                for (int n8 = 0; n8 < 4; n8++) {
                    int d = n8 * 8 + 2 * (lane & 3);
                    float x1a = c[mt][n8][2 * r],     x1b = c[mt][n8][2 * r + 1];
                    float x2a = c[mt][n8 + 4][2 * r], x2b = c[mt][n8 + 4][2 * r + 1];
                    if (comp == 2) {
                        *(__half2*)(g_vp + dst + d)      = __floats2half2_rn(x1a, x1b);
                        *(__half2*)(g_vp + dst + d + 32) = __floats2half2_rn(x2a, x2b);
                    } else {
                        float4 cs = g_rope[t * 16 + (d >> 1)];
                        float o1a = x1a * cs.x - x2a * cs.y;
                        float o1b = x1b * cs.z - x2b * cs.w;
                        float o2a = x1a * cs.y + x2a * cs.x;
                        float o2b = x1b * cs.w + x2b * cs.z;
                        if (comp == 0) {
                            *(__half2*)(g_qr + dst + d) =
                                __floats2half2_rn(0.125f * o1a, 0.125f * o1b);
                            *(__half2*)(g_qr + dst + d + 32) =
                                __floats2half2_rn(0.125f * o2a, 0.125f * o2b);
                        } else {
                            *(__half2*)(g_kr + dst + d)      = __floats2half2_rn(o1a, o1b);
                            *(__half2*)(g_kr + dst + d + 32) = __floats2half2_rn(o2a, o2b);
                        }
                    }
                }
            }
        }
    }
}

// ---------------- fused prep: conv_a + wconv(Wqkv) + wconv(Wout) + rope -----
#define CONV_BLKS  (ROWS * DMODEL / 1024)            // 8192
#define W1_BLKS    ((QKVCOLS / 32) * (DMODEL / 32))  // 3072
#define W2_BLKS    ((DMODEL / 32) * (DMODEL / 32))   // 1024
#define ROPE_BLKS  ((TSEQ * 16) / 256)               // 128
#define PREP_BLKS  (CONV_BLKS + W1_BLKS + W2_BLKS + ROPE_BLKS)

__device__ __forceinline__ void wconv_body(
    const float* __restrict__ W, __half* __restrict__ Bt,
    int K, int N, int bx, int by, float* tile)
{
    int n0 = bx * 32, k0 = by * 32;
    int tx = threadIdx.x & 31, ty = threadIdx.x >> 5;
#pragma unroll
    for (int r = 0; r < 4; r++)
        tile[(ty + 8 * r) * 33 + tx] = W[(size_t)(k0 + ty + 8 * r) * N + n0 + tx];
    __syncthreads();
#pragma unroll
    for (int r = 0; r < 4; r++)
        Bt[(size_t)(n0 + ty + 8 * r) * K + k0 + tx] = __float2half(tile[tx * 33 + ty + 8 * r]);
}

__global__ void prep_kernel(const float* __restrict__ x,
                            const float* __restrict__ Wqkv,
                            const float* __restrict__ Wout)
{
    __shared__ float tile[32 * 33];
    int bid = blockIdx.x;
    if (bid < CONV_BLKS) {
        int base = (bid * 256 + threadIdx.x) * 4;
        float4 v = *(const float4*)(x + base);
        *(__half2*)(g_Ah + base)     = __floats2half2_rn(v.x, v.y);
        *(__half2*)(g_Ah + base + 2) = __floats2half2_rn(v.z, v.w);
    } else if (bid < CONV_BLKS + W1_BLKS) {
        int i = bid - CONV_BLKS;
        wconv_body(Wqkv, g_Bh, DMODEL, QKVCOLS, i % (QKVCOLS / 32), i / (QKVCOLS / 32), tile);
    } else if (bid < CONV_BLKS + W1_BLKS + W2_BLKS) {
        int i = bid - CONV_BLKS - W1_BLKS;
        wconv_body(Wout, g_Bo, DMODEL, DMODEL, i % (DMODEL / 32), i / (DMODEL / 32), tile);
    } else {
        int idx = (bid - CONV_BLKS - W1_BLKS - W2_BLKS) * 256 + threadIdx.x;
        int t = idx >> 4, pg = idx & 15;
        float c0, s0, c1, s1;
        {
            float e = (float)(2 * (2 * pg)) * (1.0f / 64.0f);
            float ang = (float)t * exp2f(-e * 13.2877123795494493f);
            sincosf(ang, &s0, &c0);
        }
        {
            float e = (float)(2 * (2 * pg + 1)) * (1.0f / 64.0f);
            float ang = (float)t * exp2f(-e * 13.2877123795494493f);
            sincosf(ang, &s1, &c1);
        }
        g_rope[idx] = make_float4(c0, s0, c1, s1);
    }
}

// ---------------- flash attention via mma.sync -------------------------------
// 1-term Q; interior slabs skip masking; l lane-distributed.
#define PADH 72
#define QS_BYTES (64 * PADH * 2)        // 9216
#define KS_OFF   QS_BYTES
#define KS_BYTES (320 * PADH * 2)       // 46080
#define VS_OFF   (KS_OFF + KS_BYTES)
#define ATTN_SMEM (VS_OFF + KS_BYTES)   // 101376

__global__ __launch_bounds__(256, 2)
void attn_kernel()
{
    extern __shared__ __align__(128) char asmem[];
    uint32_t sb = smem_u32(asmem);
    float* mgb = (float*)(asmem + KS_OFF);   // merge buffer aliases Ks

    const int tid = threadIdx.x, wid = tid >> 5, lane = tid & 31;
    const int b = blockIdx.z, h = blockIdx.y;
    const int t0 = blockIdx.x * 64;
    const int warp_m = wid & 3, warp_n = wid >> 2;

    const size_t bh = (size_t)(b * NHEAD + h) * TSEQ;

    {
        const __half* qsrc = g_qr + (bh + t0) * HD;
        for (int idx = tid; idx < 64 * 8; idx += 256) {
            int row = idx >> 3, cc = idx & 7;
            cp16(sb + (uint32_t)(row * PADH + cc * 8) * 2, qsrc + row * HD + cc * 8);
        }
    }
    {
        const __half* ksrc = g_kr + bh * HD;
        const __half* vsrc = g_vp + bh * HD;
        for (int idx = tid; idx < 320 * 8; idx += 256) {
            int kk = idx >> 3, cc = idx & 7;
            int kg = t0 - 128 + kk;
            kg = kg < 0 ? 0 : (kg > TSEQ - 1 ? TSEQ - 1 : kg);
            cp16(sb + KS_OFF + (uint32_t)(kk * PADH + cc * 8) * 2, ksrc + (size_t)kg * HD + cc * 8);
            cp16(sb + VS_OFF + (uint32_t)(kk * PADH + cc * 8) * 2, vsrc + (size_t)kg * HD + cc * 8);
        }
    }
    CP_COMMIT();
    CP_WAIT(0);
    __syncthreads();

    const int a_r = lane & 15;
    const int a_c = (lane >> 4) << 3;
    const int b_r = ((lane < 16) ? (lane & 7) : (8 + (lane & 7)));
    const int b_c = ((lane >> 3) & 1) << 3;
    const int qlo = t0 + warp_m * 16;
    const int qi0 = qlo + (lane >> 2);

    float m0 = -1e30f, m1 = -1e30f, l0 = 0.f, l1 = 0.f;
    float o[8][4];
#pragma unroll
    for (int t = 0; t < 8; t++)
#pragma unroll
        for (int j = 0; j < 4; j++) o[t][j] = 0.f;

    for (int c = 0; c < 5; c++) {
        int kk0 = 64 * c + 32 * warp_n;
        int kgb = t0 - 128 + kk0;
        if (kgb + 31 < qlo - WIN || kgb > qlo + 15 + WIN) continue;
        bool interior = (kgb >= qlo + 15 - WIN) && (kgb + 31 <= qlo + WIN) &&
                        (kgb >= 0) && (kgb + 31 <= TSEQ - 1);

        float cS[4][4];
#pragma unroll
        for (int i = 0; i < 4; i++)
#pragma unroll
            for (int j = 0; j < 4; j++) cS[i][j] = 0.f;
#pragma unroll
        for (int ks = 0; ks < 4; ks++) {
            uint32_t aq[4], bk0[4], bk1[4];
            LDSM_X4(aq, sb + (uint32_t)((warp_m * 16 + a_r) * PADH + ks * 16 + a_c) * 2);
            LDSM_X4(bk0, sb + KS_OFF + (uint32_t)((kk0 + b_r) * PADH + ks * 16 + b_c) * 2);
            LDSM_X4(bk1, sb + KS_OFF + (uint32_t)((kk0 + 16 + b_r) * PADH + ks * 16 + b_c) * 2);
            MMA_F16(cS[0], aq, bk0[0], bk0[1]);
            MMA_F16(cS[1], aq, bk0[2], bk0[3]);
            MMA_F16(cS[2], aq, bk1[0], bk1[1]);
            MMA_F16(cS[3], aq, bk1[2], bk1[3]);
        }

        float rmax0 = -1e30f, rmax1 = -1e30f;
        if (!interior) {
#pragma unroll
            for (int n8 = 0; n8 < 4; n8++) {
                int jb = kgb + 8 * n8 + 2 * (lane & 3);
#pragma unroll
                for (int e = 0; e < 2; e++) {
                    int j = jb + e;
                    bool okj = (j >= 0) && (j < TSEQ);
                    if (!(okj && j >= qi0 - WIN && j <= qi0 + WIN))         cS[n8][e]     = -1e30f;
                    if (!(okj && j >= qi0 + 8 - WIN && j <= qi0 + 8 + WIN)) cS[n8][e + 2] = -1e30f;
                }
            }
        }
#pragma unroll
        for (int n8 = 0; n8 < 4; n8++) {
            rmax0 = fmaxf(rmax0, fmaxf(cS[n8][0], cS[n8][1]));
            rmax1 = fmaxf(rmax1, fmaxf(cS[n8][2], cS[n8][3]));
        }
        rmax0 = fmaxf(rmax0, __shfl_xor_sync(0xffffffffu, rmax0, 1));
        rmax0 = fmaxf(rmax0, __shfl_xor_sync(0xffffffffu, rmax0, 2));
        rmax1 = fmaxf(rmax1, __shfl_xor_sync(0xffffffffu, rmax1, 1));
        rmax1 = fmaxf(rmax1, __shfl_xor_sync(0xffffffffu, rmax1, 2));

        float mn0 = fmaxf(m0, rmax0), mn1 = fmaxf(m1, rmax1);
        float sc0 = __expf(m0 - mn0), sc1 = __expf(m1 - mn1);
        m0 = mn0; m1 = mn1;

        float ps0 = 0.f, ps1 = 0.f;
        uint32_t pa[4][2];
        if (interior) {
#pragma unroll
            for (int n8 = 0; n8 < 4; n8++) {
                float p0 = __expf(cS[n8][0] - mn0);
                float p1 = __expf(cS[n8][1] - mn0);
                float p2 = __expf(cS[n8][2] - mn1);
                float p3 = __expf(cS[n8][3] - mn1);
                ps0 += p0 + p1; ps1 += p2 + p3;
                pa[n8][0] = packh2(p0, p1);
                pa[n8][1] = packh2(p2, p3);
            }
        } else {
#pragma unroll
            for (int n8 = 0; n8 < 4; n8++) {
                float p0 = (cS[n8][0] < -1e29f) ? 0.f : __expf(cS[n8][0] - mn0);
                float p1 = (cS[n8][1] < -1e29f) ? 0.f : __expf(cS[n8][1] - mn0);
                float p2 = (cS[n8][2] < -1e29f) ? 0.f : __expf(cS[n8][2] - mn1);
                float p3 = (cS[n8][3] < -1e29f) ? 0.f : __expf(cS[n8][3] - mn1);
                ps0 += p0 + p1; ps1 += p2 + p3;
                pa[n8][0] = packh2(p0, p1);
                pa[n8][1] = packh2(p2, p3);
            }
        }
        l0 = l0 * sc0 + ps0;
        l1 = l1 * sc1 + ps1;
#pragma unroll
        for (int t = 0; t < 8; t++) {
            o[t][0] *= sc0; o[t][1] *= sc0; o[t][2] *= sc1; o[t][3] *= sc1;
        }

#pragma unroll
        for (int kp = 0; kp < 2; kp++) {
            uint32_t a[4] = { pa[2 * kp][0], pa[2 * kp][1], pa[2 * kp + 1][0], pa[2 * kp + 1][1] };
#pragma unroll
            for (int np = 0; np < 4; np++) {
                uint32_t bv[4];
                LDSM_X4_T(bv, sb + VS_OFF +
                    (uint32_t)((kk0 + kp * 16 + a_r) * PADH + np * 16 + a_c) * 2);
                MMA_F16(o[2 * np],     a, bv[0], bv[1]);
                MMA_F16(o[2 * np + 1], a, bv[2], bv[3]);
            }
        }
    }

    l0 += __shfl_xor_sync(0xffffffffu, l0, 1);
    l0 += __shfl_xor_sync(0xffffffffu, l0, 2);
    l1 += __shfl_xor_sync(0xffffffffu, l1, 1);
    l1 += __shfl_xor_sync(0xffffffffu, l1, 2);

    __syncthreads();
    float* ob = mgb + (warp_m * 32 + lane) * 33;
    float2* mlb = (float2*)(mgb + 4 * 32 * 33);
    if (warp_n == 1) {
#pragma unroll
        for (int t = 0; t < 8; t++)
#pragma unroll
            for (int j = 0; j < 4; j++) ob[4 * t + j] = o[t][j];
        if ((lane & 3) == 0) {
            mlb[warp_m * 16 + (lane >> 2)]     = make_float2(m0, l0);
            mlb[warp_m * 16 + 8 + (lane >> 2)] = make_float2(m1, l1);
        }
    }
    __syncthreads();
    if (warp_n == 0) {
        float2 M0 = mlb[warp_m * 16 + (lane >> 2)];
        float2 M1 = mlb[warp_m * 16 + 8 + (lane >> 2)];
        float mm0 = fmaxf(m0, M0.x), mm1 = fmaxf(m1, M1.x);
        float w00 = __expf(m0 - mm0), w01 = __expf(M0.x - mm0);
        float w10 = __expf(m1 - mm1), w11 = __expf(M1.x - mm1);
        float inv0 = 1.0f / (l0 * w00 + M0.y * w01);
        float inv1 = 1.0f / (l1 * w10 + M1.y * w11);
        size_t r0 = (size_t)(b * TSEQ + qlo + (lane >> 2)) * DMODEL;
        size_t r1 = r0 + 8 * DMODEL;
#pragma unroll
        for (int t = 0; t < 8; t++) {
            int col = h * HD + t * 8 + 2 * (lane & 3);
            float v0 = (o[t][0] * w00 + ob[4 * t + 0] * w01) * inv0;
            float v1 = (o[t][1] * w00 + ob[4 * t + 1] * w01) * inv0;
            float v2 = (o[t][2] * w10 + ob[4 * t + 2] * w11) * inv1;
            float v3 = (o[t][3] * w10 + ob[4 * t + 3] * w11) * inv1;
            *(__half2*)(g_Ah + r0 + col) = __floats2half2_rn(v0, v1);
            *(__half2*)(g_Ah + r1 + col) = __floats2half2_rn(v2, v3);
        }
    }
}

// ---------------------------------------------------------------------------
extern "C" void kernel_launch(void* const* d_in, const int* in_sizes, int n_in,
                              void* d_out, int out_size)
{
    const float* x    = (const float*)d_in[0];
    const float* Wqkv = (const float*)d_in[1];
    const float* Wout = (const float*)d_in[2];
    const float* bout = (const float*)d_in[3];
    float* out = (float*)d_out;

    __half *Ah, *Bh, *Bo;
    cudaGetSymbolAddress((void**)&Ah, g_Ah);
    cudaGetSymbolAddress((void**)&Bh, g_Bh);
    cudaGetSymbolAddress((void**)&Bo, g_Bo);

    cudaFuncSetAttribute(gemm_mma<0>, cudaFuncAttributeMaxDynamicSharedMemorySize, GEMM_SMEM);
    cudaFuncSetAttribute(gemm_mma<1>, cudaFuncAttributeMaxDynamicSharedMemorySize, GEMM_SMEM);
    cudaFuncSetAttribute(attn_kernel, cudaFuncAttributeMaxDynamicSharedMemorySize, ATTN_SMEM);

    prep_kernel<<<PREP_BLKS, 256>>>(x, Wqkv, Wout);

    gemm_mma<1><<<dim3(QKVCOLS / BN, ROWS / BM), 128, GEMM_SMEM>>>(
        Ah, Bh, nullptr, ROWS, QKVCOLS, DMODEL, nullptr);

    attn_kernel<<<dim3(TSEQ / 64, NHEAD, NB), 256, ATTN_SMEM>>>();

    gemm_mma<0><<<dim3(DMODEL / BN, ROWS / BM), 128, GEMM_SMEM>>>(
        Ah, Bo, out, ROWS, DMODEL, DMODEL, bout);
}

// round 16
// speedup vs baseline: 1.9449x; 1.0364x over previous
#include <cuda_runtime.h>
#include <cuda_fp16.h>
#include <math.h>
#include <stdint.h>

#define NB      4
#define TSEQ    2048
#define NHEAD   16
#define HD      64
#define DMODEL  1024
#define ROWS    (NB * TSEQ)          // 8192
#define QKVCOLS (3 * DMODEL)         // 3072
#define WIN     128

// ---------------- scratch (allocation-free rule: device globals) ----------
__device__ __align__(16) __half g_Ah[ROWS   * DMODEL];
__device__ __align__(16) __half g_Bh[QKVCOLS * DMODEL];  // [N][K] transposed fp16
__device__ __align__(16) __half g_Bo[DMODEL * DMODEL];   // out-proj weights [N][K]
__device__ __align__(16) __half g_qr[ROWS * DMODEL];     // [b,h][t][d] roped+scaled Q
__device__ __align__(16) __half g_kr[ROWS * DMODEL];     // [b,h][t][d] roped K
__device__ __align__(16) __half g_vp[ROWS * DMODEL];     // [b,h][t][d] packed V
__device__ float4 g_rope[TSEQ * 16];  // (t, pg): cos/sin for freqs 2pg, 2pg+1

// ---------------- PTX helpers ---------------------------------------------
__device__ __forceinline__ uint32_t smem_u32(const void* p) {
    uint32_t a;
    asm("{ .reg .u64 t; cvta.to.shared.u64 t, %1; cvt.u32.u64 %0, t; }" : "=r"(a) : "l"(p));
    return a;
}
__device__ __forceinline__ void cp16(uint32_t dst, const void* src) {
    asm volatile("cp.async.cg.shared.global [%0], [%1], 16;" :: "r"(dst), "l"(src));
}
#define CP_COMMIT() asm volatile("cp.async.commit_group;" ::: "memory")
#define CP_WAIT(n)  asm volatile("cp.async.wait_group %0;" :: "n"(n) : "memory")

#define LDSM_X4(r, addr) \
    asm volatile("ldmatrix.sync.aligned.m8n8.x4.shared.b16 {%0,%1,%2,%3}, [%4];" \
        : "=r"((r)[0]), "=r"((r)[1]), "=r"((r)[2]), "=r"((r)[3]) : "r"(addr))
#define LDSM_X4_T(r, addr) \
    asm volatile("ldmatrix.sync.aligned.m8n8.x4.trans.shared.b16 {%0,%1,%2,%3}, [%4];" \
        : "=r"((r)[0]), "=r"((r)[1]), "=r"((r)[2]), "=r"((r)[3]) : "r"(addr))

#define MMA_F16(c, a, b0, b1) \
    asm volatile("mma.sync.aligned.m16n8k16.row.col.f32.f16.f16.f32 " \
        "{%0,%1,%2,%3}, {%4,%5,%6,%7}, {%8,%9}, {%0,%1,%2,%3};" \
        : "+f"((c)[0]), "+f"((c)[1]), "+f"((c)[2]), "+f"((c)[3]) \
        : "r"((a)[0]), "r"((a)[1]), "r"((a)[2]), "r"((a)[3]), "r"(b0), "r"(b1))

__device__ __forceinline__ uint32_t packh2(float a, float b) {
    __half2 h = __floats2half2_rn(a, b);
    return *reinterpret_cast<uint32_t*>(&h);
}

// ---------------- mma.sync GEMM: C = A[M,K]*Bt[N,K]^T, 1-term fp16 A --------
// CTA 128x128, 128 threads: 4 warps (2m x 2n), warp 64x64. BK=64, 2-stage.
#define BM 128
#define BN 128
#define BK 64
#define PADK 72
#define MAT_BYTES (128 * PADK * 2)    // 18432
#define STAGE_B (2 * MAT_BYTES)       // 36864
#define GEMM_SMEM (2 * STAGE_B)       // 73728

__device__ __forceinline__ void load_chunk(
    uint32_t sb, const __half* __restrict__ Ah, const __half* __restrict__ Bh,
    int brow, int bcol, int K, int kc, int stage, int tid)
{
    uint32_t base = sb + stage * STAGE_B;
#pragma unroll
    for (int t = 0; t < 8; t++) {
        int idx = tid + t * 128;
        int row = idx >> 3;
        int c16 = idx & 7;
        uint32_t so = (uint32_t)(row * (PADK * 2) + c16 * 16);
        cp16(base + so, Ah + (size_t)(brow + row) * K + kc + c16 * 8);
        cp16(base + MAT_BYTES + so, Bh + (size_t)(bcol + row) * K + kc + c16 * 8);
    }
}

template <int MODE>
__global__ __launch_bounds__(128, 3)
void gemm_mma(const __half* __restrict__ Ah, const __half* __restrict__ Bh,
              float* __restrict__ C, int M, int N, int K,
              const float* __restrict__ bias)
{
    extern __shared__ __align__(128) char smem[];
    uint32_t sb = smem_u32(smem);
    const int tid  = threadIdx.x;
    const int wid  = tid >> 5;
    const int lane = tid & 31;
    const int wm = (wid >> 1) * 64;
    const int wn = (wid & 1) * 64;
    const int brow = blockIdx.y * BM, bcol = blockIdx.x * BN;

    float c[4][8][4];
#pragma unroll
    for (int i = 0; i < 4; i++)
#pragma unroll
        for (int j = 0; j < 8; j++)
#pragma unroll
            for (int r = 0; r < 4; r++) c[i][j][r] = 0.0f;

    const int nchunks = K / BK;
    load_chunk(sb, Ah, Bh, brow, bcol, K, 0, 0, tid);
    CP_COMMIT();

    const int a_r = lane & 15;
    const int a_c = (lane >> 4) << 3;
    const int b_r = ((lane < 16) ? (lane & 7) : (8 + (lane & 7)));
    const int b_c = ((lane >> 3) & 1) << 3;

    for (int ch = 0; ch < nchunks; ch++) {
        CP_WAIT(0);
        __syncthreads();
        if (ch + 1 < nchunks) {
            load_chunk(sb, Ah, Bh, brow, bcol, K, (ch + 1) * BK, (ch + 1) & 1, tid);
            CP_COMMIT();
        }
        uint32_t stb = sb + (ch & 1) * STAGE_B;
        const uint32_t aad = stb + (uint32_t)((wm + a_r) * (PADK * 2) + a_c * 2);
        const uint32_t bad = stb + MAT_BYTES + (uint32_t)((wn + b_r) * (PADK * 2) + b_c * 2);
#pragma unroll
        for (int ks = 0; ks < 4; ks++) {
            const uint32_t ko = (uint32_t)(ks * 32);
            uint32_t ah[4][4];
#pragma unroll
            for (int mt = 0; mt < 4; mt++)
                LDSM_X4(ah[mt], aad + (uint32_t)(mt * 16 * PADK * 2) + ko);
#pragma unroll
            for (int nt = 0; nt < 4; nt++) {
                uint32_t bh[4];
                LDSM_X4(bh, bad + (uint32_t)(nt * 16 * PADK * 2) + ko);
#pragma unroll
                for (int mt = 0; mt < 4; mt++) {
                    MMA_F16(c[mt][2 * nt],     ah[mt], bh[0], bh[1]);
                    MMA_F16(c[mt][2 * nt + 1], ah[mt], bh[2], bh[3]);
                }
            }
        }
    }

    if (MODE == 0) {
#pragma unroll
        for (int mt = 0; mt < 4; mt++) {
            int row0 = brow + wm + mt * 16 + (lane >> 2);
#pragma unroll
            for (int n8 = 0; n8 < 8; n8++) {
                int col = bcol + wn + n8 * 8 + (lane & 3) * 2;
                float bx = bias[col], by = bias[col + 1];
                *(float2*)(C + (size_t)row0 * N + col) =
                    make_float2(c[mt][n8][0] + bx, c[mt][n8][1] + by);
                *(float2*)(C + (size_t)(row0 + 8) * N + col) =
                    make_float2(c[mt][n8][2] + bx, c[mt][n8][3] + by);
            }
        }
    } else {
        const int colbase = bcol + wn;
        const int comp = colbase >> 10;            // 0=q 1=k 2=v
        const int head = (colbase & 1023) >> 6;
#pragma unroll
        for (int mt = 0; mt < 4; mt++) {
#pragma unroll
            for (int r = 0; r < 2; r++) {
                int row = brow + wm + mt * 16 + (lane >> 2) + 8 * r;   // b*T + t
                int t = row & (TSEQ - 1);
                int bidx = row >> 11;
                size_t dst = ((size_t)(bidx * NHEAD + head) * TSEQ + t) * HD;
#pragma unroll
                for (int n8 = 0; n8 < 4; n8++) {
                    int d = n8 * 8 + 2 * (lane & 3);
                    float x1a = c[mt][n8][2 * r],     x1b = c[mt][n8][2 * r + 1];
                    float x2a = c[mt][n8 + 4][2 * r], x2b = c[mt][n8 + 4][2 * r + 1];
                    if (comp == 2) {
                        *(__half2*)(g_vp + dst + d)      = __floats2half2_rn(x1a, x1b);
                        *(__half2*)(g_vp + dst + d + 32) = __floats2half2_rn(x2a, x2b);
                    } else {
                        float4 cs = g_rope[t * 16 + (d >> 1)];
                        float o1a = x1a * cs.x - x2a * cs.y;
                        float o1b = x1b * cs.z - x2b * cs.w;
                        float o2a = x1a * cs.y + x2a * cs.x;
                        float o2b = x1b * cs.w + x2b * cs.z;
                        if (comp == 0) {
                            *(__half2*)(g_qr + dst + d) =
                                __floats2half2_rn(0.125f * o1a, 0.125f * o1b);
                            *(__half2*)(g_qr + dst + d + 32) =
                                __floats2half2_rn(0.125f * o2a, 0.125f * o2b);
                        } else {
                            *(__half2*)(g_kr + dst + d)      = __floats2half2_rn(o1a, o1b);
                            *(__half2*)(g_kr + dst + d + 32) = __floats2half2_rn(o2a, o2b);
                        }
                    }
                }
            }
        }
    }
}

// ---------------- fused prep: conv_a + wconv(Wqkv) + wconv(Wout) + rope -----
#define CONV_BLKS  (ROWS * DMODEL / 1024)            // 8192
#define W1_BLKS    ((QKVCOLS / 32) * (DMODEL / 32))  // 3072
#define W2_BLKS    ((DMODEL / 32) * (DMODEL / 32))   // 1024
#define ROPE_BLKS  ((TSEQ * 16) / 256)               // 128
#define PREP_BLKS  (CONV_BLKS + W1_BLKS + W2_BLKS + ROPE_BLKS)

__device__ __forceinline__ void wconv_body(
    const float* __restrict__ W, __half* __restrict__ Bt,
    int K, int N, int bx, int by, float* tile)
{
    int n0 = bx * 32, k0 = by * 32;
    int tx = threadIdx.x & 31, ty = threadIdx.x >> 5;
#pragma unroll
    for (int r = 0; r < 4; r++)
        tile[(ty + 8 * r) * 33 + tx] = W[(size_t)(k0 + ty + 8 * r) * N + n0 + tx];
    __syncthreads();
#pragma unroll
    for (int r = 0; r < 4; r++)
        Bt[(size_t)(n0 + ty + 8 * r) * K + k0 + tx] = __float2half(tile[tx * 33 + ty + 8 * r]);
}

__global__ void prep_kernel(const float* __restrict__ x,
                            const float* __restrict__ Wqkv,
                            const float* __restrict__ Wout)
{
    __shared__ float tile[32 * 33];
    int bid = blockIdx.x;
    if (bid < CONV_BLKS) {
        int base = (bid * 256 + threadIdx.x) * 4;
        float4 v = *(const float4*)(x + base);
        *(__half2*)(g_Ah + base)     = __floats2half2_rn(v.x, v.y);
        *(__half2*)(g_Ah + base + 2) = __floats2half2_rn(v.z, v.w);
    } else if (bid < CONV_BLKS + W1_BLKS) {
        int i = bid - CONV_BLKS;
        wconv_body(Wqkv, g_Bh, DMODEL, QKVCOLS, i % (QKVCOLS / 32), i / (QKVCOLS / 32), tile);
    } else if (bid < CONV_BLKS + W1_BLKS + W2_BLKS) {
        int i = bid - CONV_BLKS - W1_BLKS;
        wconv_body(Wout, g_Bo, DMODEL, DMODEL, i % (DMODEL / 32), i / (DMODEL / 32), tile);
    } else {
        int idx = (bid - CONV_BLKS - W1_BLKS - W2_BLKS) * 256 + threadIdx.x;
        int t = idx >> 4, pg = idx & 15;
        float c0, s0, c1, s1;
        {
            float e = (float)(2 * (2 * pg)) * (1.0f / 64.0f);
            float ang = (float)t * exp2f(-e * 13.2877123795494493f);
            sincosf(ang, &s0, &c0);
        }
        {
            float e = (float)(2 * (2 * pg + 1)) * (1.0f / 64.0f);
            float ang = (float)t * exp2f(-e * 13.2877123795494493f);
            sincosf(ang, &s1, &c1);
        }
        g_rope[idx] = make_float4(c0, s0, c1, s1);
    }
}

// ---------------- flash attention via mma.sync -------------------------------
// CTA = 128 queries, 8 warps x 16 queries, full key range per warp (no merge).
// Q in registers (staged once through K smem region). K/V: 384 rows in smem.
#define PADH 72
#define KROWS 384
#define KS_BYTES (KROWS * PADH * 2)     // 55296
#define VS_OFF   KS_BYTES
#define ATTN_SMEM (2 * KS_BYTES)        // 110592

__global__ __launch_bounds__(256, 2)
void attn_kernel()
{
    extern __shared__ __align__(128) char asmem[];
    uint32_t sb = smem_u32(asmem);

    const int tid = threadIdx.x, wid = tid >> 5, lane = tid & 31;
    const int b = blockIdx.z, h = blockIdx.y;
    const int t0 = blockIdx.x * 128;

    const size_t bh = (size_t)(b * NHEAD + h) * TSEQ;
    const __half* ksrc = g_kr + bh * HD;
    const __half* vsrc = g_vp + bh * HD;

    const int a_r = lane & 15;
    const int a_c = (lane >> 4) << 3;
    const int b_r = ((lane < 16) ? (lane & 7) : (8 + (lane & 7)));
    const int b_c = ((lane >> 3) & 1) << 3;
    const int qlo = t0 + wid * 16;
    const int qi0 = qlo + (lane >> 2);

    // ---- Phase 1: stage Q through K smem region, grab fragments
    {
        const __half* qsrc = g_qr + (bh + t0) * HD;
        for (int idx = tid; idx < 128 * 8; idx += 256) {
            int row = idx >> 3, cc = idx & 7;
            cp16(sb + (uint32_t)(row * PADH + cc * 8) * 2, qsrc + row * HD + cc * 8);
        }
        CP_COMMIT();
        CP_WAIT(0);
        __syncthreads();
    }
    uint32_t aq[4][4];
#pragma unroll
    for (int ks = 0; ks < 4; ks++)
        LDSM_X4(aq[ks], sb + (uint32_t)((wid * 16 + a_r) * PADH + ks * 16 + a_c) * 2);
    __syncthreads();      // all Q fragments read before K overwrites

    // ---- Phase 2: fill K and V (384 rows each, clamped)
    for (int idx = tid; idx < KROWS * 8; idx += 256) {
        int kk = idx >> 3, cc = idx & 7;
        int kg = t0 - 128 + kk;
        kg = kg < 0 ? 0 : (kg > TSEQ - 1 ? TSEQ - 1 : kg);
        cp16(sb + (uint32_t)(kk * PADH + cc * 8) * 2, ksrc + (size_t)kg * HD + cc * 8);
        cp16(sb + VS_OFF + (uint32_t)(kk * PADH + cc * 8) * 2, vsrc + (size_t)kg * HD + cc * 8);
    }
    CP_COMMIT();
    CP_WAIT(0);
    __syncthreads();

    float m0 = -1e30f, m1 = -1e30f, l0 = 0.f, l1 = 0.f;
    float o[8][4];
#pragma unroll
    for (int t = 0; t < 8; t++)
#pragma unroll
        for (int j = 0; j < 4; j++) o[t][j] = 0.f;

    for (int c = 0; c < 12; c++) {
        int kk0 = 32 * c;
        int kgb = t0 - 128 + kk0;
        if (kgb + 31 < qlo - WIN || kgb > qlo + 15 + WIN) continue;   // warp-uniform
        bool interior = (kgb >= qlo + 15 - WIN) && (kgb + 31 <= qlo + WIN) &&
                        (kgb >= 0) && (kgb + 31 <= TSEQ - 1);

        float cS[4][4];
#pragma unroll
        for (int i = 0; i < 4; i++)
#pragma unroll
            for (int j = 0; j < 4; j++) cS[i][j] = 0.f;
#pragma unroll
        for (int ks = 0; ks < 4; ks++) {
            uint32_t bk0[4], bk1[4];
            LDSM_X4(bk0, sb + (uint32_t)((kk0 + b_r) * PADH + ks * 16 + b_c) * 2);
            LDSM_X4(bk1, sb + (uint32_t)((kk0 + 16 + b_r) * PADH + ks * 16 + b_c) * 2);
            MMA_F16(cS[0], aq[ks], bk0[0], bk0[1]);
            MMA_F16(cS[1], aq[ks], bk0[2], bk0[3]);
            MMA_F16(cS[2], aq[ks], bk1[0], bk1[1]);
            MMA_F16(cS[3], aq[ks], bk1[2], bk1[3]);
        }

        float rmax0 = -1e30f, rmax1 = -1e30f;
        if (!interior) {
#pragma unroll
            for (int n8 = 0; n8 < 4; n8++) {
                int jb = kgb + 8 * n8 + 2 * (lane & 3);
#pragma unroll
                for (int e = 0; e < 2; e++) {
                    int j = jb + e;
                    bool okj = (j >= 0) && (j < TSEQ);
                    if (!(okj && j >= qi0 - WIN && j <= qi0 + WIN))         cS[n8][e]     = -1e30f;
                    if (!(okj && j >= qi0 + 8 - WIN && j <= qi0 + 8 + WIN)) cS[n8][e + 2] = -1e30f;
                }
            }
        }
#pragma unroll
        for (int n8 = 0; n8 < 4; n8++) {
            rmax0 = fmaxf(rmax0, fmaxf(cS[n8][0], cS[n8][1]));
            rmax1 = fmaxf(rmax1, fmaxf(cS[n8][2], cS[n8][3]));
        }
        rmax0 = fmaxf(rmax0, __shfl_xor_sync(0xffffffffu, rmax0, 1));
        rmax0 = fmaxf(rmax0, __shfl_xor_sync(0xffffffffu, rmax0, 2));
        rmax1 = fmaxf(rmax1, __shfl_xor_sync(0xffffffffu, rmax1, 1));
        rmax1 = fmaxf(rmax1, __shfl_xor_sync(0xffffffffu, rmax1, 2));

        float mn0 = fmaxf(m0, rmax0), mn1 = fmaxf(m1, rmax1);
        float sc0 = __expf(m0 - mn0), sc1 = __expf(m1 - mn1);
        m0 = mn0; m1 = mn1;

        float ps0 = 0.f, ps1 = 0.f;
        uint32_t pa[4][2];
        if (interior) {
#pragma unroll
            for (int n8 = 0; n8 < 4; n8++) {
                float p0 = __expf(cS[n8][0] - mn0);
                float p1 = __expf(cS[n8][1] - mn0);
                float p2 = __expf(cS[n8][2] - mn1);
                float p3 = __expf(cS[n8][3] - mn1);
                ps0 += p0 + p1; ps1 += p2 + p3;
                pa[n8][0] = packh2(p0, p1);
                pa[n8][1] = packh2(p2, p3);
            }
        } else {
#pragma unroll
            for (int n8 = 0; n8 < 4; n8++) {
                float p0 = (cS[n8][0] < -1e29f) ? 0.f : __expf(cS[n8][0] - mn0);
                float p1 = (cS[n8][1] < -1e29f) ? 0.f : __expf(cS[n8][1] - mn0);
                float p2 = (cS[n8][2] < -1e29f) ? 0.f : __expf(cS[n8][2] - mn1);
                float p3 = (cS[n8][3] < -1e29f) ? 0.f : __expf(cS[n8][3] - mn1);
                ps0 += p0 + p1; ps1 += p2 + p3;
                pa[n8][0] = packh2(p0, p1);
                pa[n8][1] = packh2(p2, p3);
            }
        }
        l0 = l0 * sc0 + ps0;
        l1 = l1 * sc1 + ps1;
#pragma unroll
        for (int t = 0; t < 8; t++) {
            o[t][0] *= sc0; o[t][1] *= sc0; o[t][2] *= sc1; o[t][3] *= sc1;
        }

#pragma unroll
        for (int kp = 0; kp < 2; kp++) {
            uint32_t a[4] = { pa[2 * kp][0], pa[2 * kp][1], pa[2 * kp + 1][0], pa[2 * kp + 1][1] };
#pragma unroll
            for (int np = 0; np < 4; np++) {
                uint32_t bv[4];
                LDSM_X4_T(bv, sb + VS_OFF +
                    (uint32_t)((kk0 + kp * 16 + a_r) * PADH + np * 16 + a_c) * 2);
                MMA_F16(o[2 * np],     a, bv[0], bv[1]);
                MMA_F16(o[2 * np + 1], a, bv[2], bv[3]);
            }
        }
    }

    // quad-reduce l, normalize, write (no cross-warp merge needed)
    l0 += __shfl_xor_sync(0xffffffffu, l0, 1);
    l0 += __shfl_xor_sync(0xffffffffu, l0, 2);
    l1 += __shfl_xor_sync(0xffffffffu, l1, 1);
    l1 += __shfl_xor_sync(0xffffffffu, l1, 2);
    float inv0 = 1.0f / l0;
    float inv1 = 1.0f / l1;

    size_t r0 = (size_t)(b * TSEQ + qi0) * DMODEL;
    size_t r1 = r0 + 8 * DMODEL;
#pragma unroll
    for (int t = 0; t < 8; t++) {
        int col = h * HD + t * 8 + 2 * (lane & 3);
        *(__half2*)(g_Ah + r0 + col) = __floats2half2_rn(o[t][0] * inv0, o[t][1] * inv0);
        *(__half2*)(g_Ah + r1 + col) = __floats2half2_rn(o[t][2] * inv1, o[t][3] * inv1);
    }
}

// ---------------------------------------------------------------------------
extern "C" void kernel_launch(void* const* d_in, const int* in_sizes, int n_in,
                              void* d_out, int out_size)
{
    const float* x    = (const float*)d_in[0];
    const float* Wqkv = (const float*)d_in[1];
    const float* Wout = (const float*)d_in[2];
    const float* bout = (const float*)d_in[3];
    float* out = (float*)d_out;

    __half *Ah, *Bh, *Bo;
    cudaGetSymbolAddress((void**)&Ah, g_Ah);
    cudaGetSymbolAddress((void**)&Bh, g_Bh);
    cudaGetSymbolAddress((void**)&Bo, g_Bo);

    cudaFuncSetAttribute(gemm_mma<0>, cudaFuncAttributeMaxDynamicSharedMemorySize, GEMM_SMEM);
    cudaFuncSetAttribute(gemm_mma<1>, cudaFuncAttributeMaxDynamicSharedMemorySize, GEMM_SMEM);
    cudaFuncSetAttribute(attn_kernel, cudaFuncAttributeMaxDynamicSharedMemorySize, ATTN_SMEM);

    prep_kernel<<<PREP_BLKS, 256>>>(x, Wqkv, Wout);

    gemm_mma<1><<<dim3(QKVCOLS / BN, ROWS / BM), 128, GEMM_SMEM>>>(
        Ah, Bh, nullptr, ROWS, QKVCOLS, DMODEL, nullptr);

    attn_kernel<<<dim3(TSEQ / 128, NHEAD, NB), 256, ATTN_SMEM>>>();

    gemm_mma<0><<<dim3(DMODEL / BN, ROWS / BM), 128, GEMM_SMEM>>>(
        Ah, Bo, out, ROWS, DMODEL, DMODEL, bout);
}

// round 17
// speedup vs baseline: 1.9748x; 1.0154x over previous
#include <cuda_runtime.h>
#include <cuda_fp16.h>
#include <math.h>
#include <stdint.h>

#define NB      4
#define TSEQ    2048
#define NHEAD   16
#define HD      64
#define DMODEL  1024
#define ROWS    (NB * TSEQ)          // 8192
#define QKVCOLS (3 * DMODEL)         // 3072
#define WIN     128

// ---------------- scratch (allocation-free rule: device globals) ----------
__device__ __align__(16) __half g_Ah[ROWS   * DMODEL];
__device__ __align__(16) __half g_Bh[QKVCOLS * DMODEL];  // [N][K] transposed fp16
__device__ __align__(16) __half g_Bo[DMODEL * DMODEL];   // out-proj weights [N][K]
__device__ __align__(16) __half g_qr[ROWS * DMODEL];     // [b,h][t][d] roped+scaled Q
__device__ __align__(16) __half g_kr[ROWS * DMODEL];     // [b,h][t][d] roped K
__device__ __align__(16) __half g_vp[ROWS * DMODEL];     // [b,h][t][d] packed V
__device__ float4 g_rope[TSEQ * 16];  // (t, pg): cos/sin for freqs 2pg, 2pg+1

// ---------------- PTX helpers ---------------------------------------------
__device__ __forceinline__ uint32_t smem_u32(const void* p) {
    uint32_t a;
    asm("{ .reg .u64 t; cvta.to.shared.u64 t, %1; cvt.u32.u64 %0, t; }" : "=r"(a) : "l"(p));
    return a;
}
__device__ __forceinline__ void cp16(uint32_t dst, const void* src) {
    asm volatile("cp.async.cg.shared.global [%0], [%1], 16;" :: "r"(dst), "l"(src));
}
#define CP_COMMIT() asm volatile("cp.async.commit_group;" ::: "memory")
#define CP_WAIT(n)  asm volatile("cp.async.wait_group %0;" :: "n"(n) : "memory")

#define LDSM_X4(r, addr) \
    asm volatile("ldmatrix.sync.aligned.m8n8.x4.shared.b16 {%0,%1,%2,%3}, [%4];" \
        : "=r"((r)[0]), "=r"((r)[1]), "=r"((r)[2]), "=r"((r)[3]) : "r"(addr))
#define LDSM_X4_T(r, addr) \
    asm volatile("ldmatrix.sync.aligned.m8n8.x4.trans.shared.b16 {%0,%1,%2,%3}, [%4];" \
        : "=r"((r)[0]), "=r"((r)[1]), "=r"((r)[2]), "=r"((r)[3]) : "r"(addr))

#define MMA_F16(c, a, b0, b1) \
    asm volatile("mma.sync.aligned.m16n8k16.row.col.f32.f16.f16.f32 " \
        "{%0,%1,%2,%3}, {%4,%5,%6,%7}, {%8,%9}, {%0,%1,%2,%3};" \
        : "+f"((c)[0]), "+f"((c)[1]), "+f"((c)[2]), "+f"((c)[3]) \
        : "r"((a)[0]), "r"((a)[1]), "r"((a)[2]), "r"((a)[3]), "r"(b0), "r"(b1))

__device__ __forceinline__ uint32_t packh2(float a, float b) {
    __half2 h = __floats2half2_rn(a, b);
    return *reinterpret_cast<uint32_t*>(&h);
}

// ---------------- QKV GEMM: CTA 128x128, 128 thr, warp 64x64, BK=64 --------
#define BM 128
#define BN 128
#define BK 64
#define PADK 72
#define MAT_BYTES (128 * PADK * 2)    // 18432
#define STAGE_B (2 * MAT_BYTES)       // 36864
#define GEMM_SMEM (2 * STAGE_B)       // 73728

__device__ __forceinline__ void load_chunk(
    uint32_t sb, const __half* __restrict__ Ah, const __half* __restrict__ Bh,
    int brow, int bcol, int K, int kc, int stage, int tid)
{
    uint32_t base = sb + stage * STAGE_B;
#pragma unroll
    for (int t = 0; t < 8; t++) {
        int idx = tid + t * 128;
        int row = idx >> 3;
        int c16 = idx & 7;
        uint32_t so = (uint32_t)(row * (PADK * 2) + c16 * 16);
        cp16(base + so, Ah + (size_t)(brow + row) * K + kc + c16 * 8);
        cp16(base + MAT_BYTES + so, Bh + (size_t)(bcol + row) * K + kc + c16 * 8);
    }
}

__global__ __launch_bounds__(128, 3)
void gemm_qkv(const __half* __restrict__ Ah, const __half* __restrict__ Bh,
              int M, int N, int K)
{
    extern __shared__ __align__(128) char smem[];
    uint32_t sb = smem_u32(smem);
    const int tid  = threadIdx.x;
    const int wid  = tid >> 5;
    const int lane = tid & 31;
    const int wm = (wid >> 1) * 64;
    const int wn = (wid & 1) * 64;
    const int brow = blockIdx.y * BM, bcol = blockIdx.x * BN;

    float c[4][8][4];
#pragma unroll
    for (int i = 0; i < 4; i++)
#pragma unroll
        for (int j = 0; j < 8; j++)
#pragma unroll
            for (int r = 0; r < 4; r++) c[i][j][r] = 0.0f;

    const int nchunks = K / BK;
    load_chunk(sb, Ah, Bh, brow, bcol, K, 0, 0, tid);
    CP_COMMIT();

    const int a_r = lane & 15;
    const int a_c = (lane >> 4) << 3;
    const int b_r = ((lane < 16) ? (lane & 7) : (8 + (lane & 7)));
    const int b_c = ((lane >> 3) & 1) << 3;

    for (int ch = 0; ch < nchunks; ch++) {
        CP_WAIT(0);
        __syncthreads();
        if (ch + 1 < nchunks) {
            load_chunk(sb, Ah, Bh, brow, bcol, K, (ch + 1) * BK, (ch + 1) & 1, tid);
            CP_COMMIT();
        }
        uint32_t stb = sb + (ch & 1) * STAGE_B;
        const uint32_t aad = stb + (uint32_t)((wm + a_r) * (PADK * 2) + a_c * 2);
        const uint32_t bad = stb + MAT_BYTES + (uint32_t)((wn + b_r) * (PADK * 2) + b_c * 2);
#pragma unroll
        for (int ks = 0; ks < 4; ks++) {
            const uint32_t ko = (uint32_t)(ks * 32);
            uint32_t ah[4][4];
#pragma unroll
            for (int mt = 0; mt < 4; mt++)
                LDSM_X4(ah[mt], aad + (uint32_t)(mt * 16 * PADK * 2) + ko);
#pragma unroll
            for (int nt = 0; nt < 4; nt++) {
                uint32_t bh[4];
                LDSM_X4(bh, bad + (uint32_t)(nt * 16 * PADK * 2) + ko);
#pragma unroll
                for (int mt = 0; mt < 4; mt++) {
                    MMA_F16(c[mt][2 * nt],     ah[mt], bh[0], bh[1]);
                    MMA_F16(c[mt][2 * nt + 1], ah[mt], bh[2], bh[3]);
                }
            }
        }
    }

    // fused rope/pack epilogue
    const int colbase = bcol + wn;
    const int comp = colbase >> 10;            // 0=q 1=k 2=v
    const int head = (colbase & 1023) >> 6;
#pragma unroll
    for (int mt = 0; mt < 4; mt++) {
#pragma unroll
        for (int r = 0; r < 2; r++) {
            int row = brow + wm + mt * 16 + (lane >> 2) + 8 * r;   // b*T + t
            int t = row & (TSEQ - 1);
            int bidx = row >> 11;
            size_t dst = ((size_t)(bidx * NHEAD + head) * TSEQ + t) * HD;
#pragma unroll
            for (int n8 = 0; n8 < 4; n8++) {
                int d = n8 * 8 + 2 * (lane & 3);
                float x1a = c[mt][n8][2 * r],     x1b = c[mt][n8][2 * r + 1];
                float x2a = c[mt][n8 + 4][2 * r], x2b = c[mt][n8 + 4][2 * r + 1];
                if (comp == 2) {
                    *(__half2*)(g_vp + dst + d)      = __floats2half2_rn(x1a, x1b);
                    *(__half2*)(g_vp + dst + d + 32) = __floats2half2_rn(x2a, x2b);
                } else {
                    float4 cs = g_rope[t * 16 + (d >> 1)];
                    float o1a = x1a * cs.x - x2a * cs.y;
                    float o1b = x1b * cs.z - x2b * cs.w;
                    float o2a = x1a * cs.y + x2a * cs.x;
                    float o2b = x1b * cs.w + x2b * cs.z;
                    if (comp == 0) {
                        *(__half2*)(g_qr + dst + d) =
                            __floats2half2_rn(0.125f * o1a, 0.125f * o1b);
                        *(__half2*)(g_qr + dst + d + 32) =
                            __floats2half2_rn(0.125f * o2a, 0.125f * o2b);
                    } else {
                        *(__half2*)(g_kr + dst + d)      = __floats2half2_rn(o1a, o1b);
                        *(__half2*)(g_kr + dst + d + 32) = __floats2half2_rn(o2a, o2b);
                    }
                }
            }
        }
    }
}

// ---------------- out-proj GEMM: CTA 64x128, 128 thr, warp 32x64 -----------
// Smaller CTAs kill the wave-quantization tail (512 -> 1024 CTAs, 4 CTA/SM).
#define OBM 64
#define OA_BYTES (64 * PADK * 2)          // 9216
#define OSTAGE (OA_BYTES + MAT_BYTES)     // 27648
#define OGEMM_SMEM (2 * OSTAGE)           // 55296 (4 CTA/SM: 221184)

__device__ __forceinline__ void load_chunk_o(
    uint32_t sb, const __half* __restrict__ Ah, const __half* __restrict__ Bh,
    int brow, int bcol, int K, int kc, int stage, int tid)
{
    uint32_t base = sb + stage * OSTAGE;
#pragma unroll
    for (int t = 0; t < 4; t++) {          // A: 64 rows
        int idx = tid + t * 128;
        int row = idx >> 3;
        int c16 = idx & 7;
        uint32_t so = (uint32_t)(row * (PADK * 2) + c16 * 16);
        cp16(base + so, Ah + (size_t)(brow + row) * K + kc + c16 * 8);
    }
#pragma unroll
    for (int t = 0; t < 8; t++) {          // B: 128 rows
        int idx = tid + t * 128;
        int row = idx >> 3;
        int c16 = idx & 7;
        uint32_t so = (uint32_t)(row * (PADK * 2) + c16 * 16);
        cp16(base + OA_BYTES + so, Bh + (size_t)(bcol + row) * K + kc + c16 * 8);
    }
}

__global__ __launch_bounds__(128, 4)
void gemm_out(const __half* __restrict__ Ah, const __half* __restrict__ Bh,
              float* __restrict__ C, int M, int N, int K,
              const float* __restrict__ bias)
{
    extern __shared__ __align__(128) char smem[];
    uint32_t sb = smem_u32(smem);
    const int tid  = threadIdx.x;
    const int wid  = tid >> 5;
    const int lane = tid & 31;
    const int wm = (wid >> 1) * 32;      // 2 warp-rows
    const int wn = (wid & 1) * 64;       // 2 warp-cols
    const int brow = blockIdx.y * OBM, bcol = blockIdx.x * BN;

    float c[2][8][4];
#pragma unroll
    for (int i = 0; i < 2; i++)
#pragma unroll
        for (int j = 0; j < 8; j++)
#pragma unroll
            for (int r = 0; r < 4; r++) c[i][j][r] = 0.0f;

    const int nchunks = K / BK;
    load_chunk_o(sb, Ah, Bh, brow, bcol, K, 0, 0, tid);
    CP_COMMIT();

    const int a_r = lane & 15;
    const int a_c = (lane >> 4) << 3;
    const int b_r = ((lane < 16) ? (lane & 7) : (8 + (lane & 7)));
    const int b_c = ((lane >> 3) & 1) << 3;

    for (int ch = 0; ch < nchunks; ch++) {
        CP_WAIT(0);
        __syncthreads();
        if (ch + 1 < nchunks) {
            load_chunk_o(sb, Ah, Bh, brow, bcol, K, (ch + 1) * BK, (ch + 1) & 1, tid);
            CP_COMMIT();
        }
        uint32_t stb = sb + (ch & 1) * OSTAGE;
        const uint32_t aad = stb + (uint32_t)((wm + a_r) * (PADK * 2) + a_c * 2);
        const uint32_t bad = stb + OA_BYTES + (uint32_t)((wn + b_r) * (PADK * 2) + b_c * 2);
#pragma unroll
        for (int ks = 0; ks < 4; ks++) {
            const uint32_t ko = (uint32_t)(ks * 32);
            uint32_t ah[2][4];
#pragma unroll
            for (int mt = 0; mt < 2; mt++)
                LDSM_X4(ah[mt], aad + (uint32_t)(mt * 16 * PADK * 2) + ko);
#pragma unroll
            for (int nt = 0; nt < 4; nt++) {
                uint32_t bh[4];
                LDSM_X4(bh, bad + (uint32_t)(nt * 16 * PADK * 2) + ko);
#pragma unroll
                for (int mt = 0; mt < 2; mt++) {
                    MMA_F16(c[mt][2 * nt],     ah[mt], bh[0], bh[1]);
                    MMA_F16(c[mt][2 * nt + 1], ah[mt], bh[2], bh[3]);
                }
            }
        }
    }

#pragma unroll
    for (int mt = 0; mt < 2; mt++) {
        int row0 = brow + wm + mt * 16 + (lane >> 2);
#pragma unroll
        for (int n8 = 0; n8 < 8; n8++) {
            int col = bcol + wn + n8 * 8 + (lane & 3) * 2;
            float bx = bias[col], by = bias[col + 1];
            *(float2*)(C + (size_t)row0 * N + col) =
                make_float2(c[mt][n8][0] + bx, c[mt][n8][1] + by);
            *(float2*)(C + (size_t)(row0 + 8) * N + col) =
                make_float2(c[mt][n8][2] + bx, c[mt][n8][3] + by);
        }
    }
}

// ---------------- fused prep: conv_a + wconv(Wqkv) + wconv(Wout) + rope -----
#define CONV_BLKS  (ROWS * DMODEL / 1024)            // 8192
#define W1_BLKS    ((QKVCOLS / 32) * (DMODEL / 32))  // 3072
#define W2_BLKS    ((DMODEL / 32) * (DMODEL / 32))   // 1024
#define ROPE_BLKS  ((TSEQ * 16) / 256)               // 128
#define PREP_BLKS  (CONV_BLKS + W1_BLKS + W2_BLKS + ROPE_BLKS)

__device__ __forceinline__ void wconv_body(
    const float* __restrict__ W, __half* __restrict__ Bt,
    int K, int N, int bx, int by, float* tile)
{
    int n0 = bx * 32, k0 = by * 32;
    int tx = threadIdx.x & 31, ty = threadIdx.x >> 5;
#pragma unroll
    for (int r = 0; r < 4; r++)
        tile[(ty + 8 * r) * 33 + tx] = W[(size_t)(k0 + ty + 8 * r) * N + n0 + tx];
    __syncthreads();
#pragma unroll
    for (int r = 0; r < 4; r++)
        Bt[(size_t)(n0 + ty + 8 * r) * K + k0 + tx] = __float2half(tile[tx * 33 + ty + 8 * r]);
}

__global__ void prep_kernel(const float* __restrict__ x,
                            const float* __restrict__ Wqkv,
                            const float* __restrict__ Wout)
{
    __shared__ float tile[32 * 33];
    int bid = blockIdx.x;
    if (bid < CONV_BLKS) {
        int base = (bid * 256 + threadIdx.x) * 4;
        float4 v = *(const float4*)(x + base);
        *(__half2*)(g_Ah + base)     = __floats2half2_rn(v.x, v.y);
        *(__half2*)(g_Ah + base + 2) = __floats2half2_rn(v.z, v.w);
    } else if (bid < CONV_BLKS + W1_BLKS) {
        int i = bid - CONV_BLKS;
        wconv_body(Wqkv, g_Bh, DMODEL, QKVCOLS, i % (QKVCOLS / 32), i / (QKVCOLS / 32), tile);
    } else if (bid < CONV_BLKS + W1_BLKS + W2_BLKS) {
        int i = bid - CONV_BLKS - W1_BLKS;
        wconv_body(Wout, g_Bo, DMODEL, DMODEL, i % (DMODEL / 32), i / (DMODEL / 32), tile);
    } else {
        int idx = (bid - CONV_BLKS - W1_BLKS - W2_BLKS) * 256 + threadIdx.x;
        int t = idx >> 4, pg = idx & 15;
        float c0, s0, c1, s1;
        {
            float e = (float)(2 * (2 * pg)) * (1.0f / 64.0f);
            float ang = (float)t * exp2f(-e * 13.2877123795494493f);
            sincosf(ang, &s0, &c0);
        }
        {
            float e = (float)(2 * (2 * pg + 1)) * (1.0f / 64.0f);
            float ang = (float)t * exp2f(-e * 13.2877123795494493f);
            sincosf(ang, &s1, &c1);
        }
        g_rope[idx] = make_float4(c0, s0, c1, s1);
    }
}

// ---------------- flash attention via mma.sync -------------------------------
// CTA = 128 queries, 8 warps x 16 queries, full key range per warp (no merge).
#define PADH 72
#define KROWS 384
#define KS_BYTES (KROWS * PADH * 2)     // 55296
#define VS_OFF   KS_BYTES
#define ATTN_SMEM (2 * KS_BYTES)        // 110592

__global__ __launch_bounds__(256, 2)
void attn_kernel()
{
    extern __shared__ __align__(128) char asmem[];
    uint32_t sb = smem_u32(asmem);

    const int tid = threadIdx.x, wid = tid >> 5, lane = tid & 31;
    const int b = blockIdx.z, h = blockIdx.y;
    const int t0 = blockIdx.x * 128;

    const size_t bh = (size_t)(b * NHEAD + h) * TSEQ;
    const __half* ksrc = g_kr + bh * HD;
    const __half* vsrc = g_vp + bh * HD;

    const int a_r = lane & 15;
    const int a_c = (lane >> 4) << 3;
    const int b_r = ((lane < 16) ? (lane & 7) : (8 + (lane & 7)));
    const int b_c = ((lane >> 3) & 1) << 3;
    const int qlo = t0 + wid * 16;
    const int qi0 = qlo + (lane >> 2);

    {
        const __half* qsrc = g_qr + (bh + t0) * HD;
        for (int idx = tid; idx < 128 * 8; idx += 256) {
            int row = idx >> 3, cc = idx & 7;
            cp16(sb + (uint32_t)(row * PADH + cc * 8) * 2, qsrc + row * HD + cc * 8);
        }
        CP_COMMIT();
        CP_WAIT(0);
        __syncthreads();
    }
    uint32_t aq[4][4];
#pragma unroll
    for (int ks = 0; ks < 4; ks++)
        LDSM_X4(aq[ks], sb + (uint32_t)((wid * 16 + a_r) * PADH + ks * 16 + a_c) * 2);
    __syncthreads();

    for (int idx = tid; idx < KROWS * 8; idx += 256) {
        int kk = idx >> 3, cc = idx & 7;
        int kg = t0 - 128 + kk;
        kg = kg < 0 ? 0 : (kg > TSEQ - 1 ? TSEQ - 1 : kg);
        cp16(sb + (uint32_t)(kk * PADH + cc * 8) * 2, ksrc + (size_t)kg * HD + cc * 8);
        cp16(sb + VS_OFF + (uint32_t)(kk * PADH + cc * 8) * 2, vsrc + (size_t)kg * HD + cc * 8);
    }
    CP_COMMIT();
    CP_WAIT(0);
    __syncthreads();

    float m0 = -1e30f, m1 = -1e30f, l0 = 0.f, l1 = 0.f;
    float o[8][4];
#pragma unroll
    for (int t = 0; t < 8; t++)
#pragma unroll
        for (int j = 0; j < 4; j++) o[t][j] = 0.f;

    for (int c = 0; c < 12; c++) {
        int kk0 = 32 * c;
        int kgb = t0 - 128 + kk0;
        if (kgb + 31 < qlo - WIN || kgb > qlo + 15 + WIN) continue;
        bool interior = (kgb >= qlo + 15 - WIN) && (kgb + 31 <= qlo + WIN) &&
                        (kgb >= 0) && (kgb + 31 <= TSEQ - 1);

        float cS[4][4];
#pragma unroll
        for (int i = 0; i < 4; i++)
#pragma unroll
            for (int j = 0; j < 4; j++) cS[i][j] = 0.f;
#pragma unroll
        for (int ks = 0; ks < 4; ks++) {
            uint32_t bk0[4], bk1[4];
            LDSM_X4(bk0, sb + (uint32_t)((kk0 + b_r) * PADH + ks * 16 + b_c) * 2);
            LDSM_X4(bk1, sb + (uint32_t)((kk0 + 16 + b_r) * PADH + ks * 16 + b_c) * 2);
            MMA_F16(cS[0], aq[ks], bk0[0], bk0[1]);
            MMA_F16(cS[1], aq[ks], bk0[2], bk0[3]);
            MMA_F16(cS[2], aq[ks], bk1[0], bk1[1]);
            MMA_F16(cS[3], aq[ks], bk1[2], bk1[3]);
        }

        float rmax0 = -1e30f, rmax1 = -1e30f;
        if (!interior) {
#pragma unroll
            for (int n8 = 0; n8 < 4; n8++) {
                int jb = kgb + 8 * n8 + 2 * (lane & 3);
#pragma unroll
                for (int e = 0; e < 2; e++) {
                    int j = jb + e;
                    bool okj = (j >= 0) && (j < TSEQ);
                    if (!(okj && j >= qi0 - WIN && j <= qi0 + WIN))         cS[n8][e]     = -1e30f;
                    if (!(okj && j >= qi0 + 8 - WIN && j <= qi0 + 8 + WIN)) cS[n8][e + 2] = -1e30f;
                }
            }
        }
#pragma unroll
        for (int n8 = 0; n8 < 4; n8++) {
            rmax0 = fmaxf(rmax0, fmaxf(cS[n8][0], cS[n8][1]));
            rmax1 = fmaxf(rmax1, fmaxf(cS[n8][2], cS[n8][3]));
        }
        rmax0 = fmaxf(rmax0, __shfl_xor_sync(0xffffffffu, rmax0, 1));
        rmax0 = fmaxf(rmax0, __shfl_xor_sync(0xffffffffu, rmax0, 2));
        rmax1 = fmaxf(rmax1, __shfl_xor_sync(0xffffffffu, rmax1, 1));
        rmax1 = fmaxf(rmax1, __shfl_xor_sync(0xffffffffu, rmax1, 2));

        float mn0 = fmaxf(m0, rmax0), mn1 = fmaxf(m1, rmax1);
        float sc0 = __expf(m0 - mn0), sc1 = __expf(m1 - mn1);
        m0 = mn0; m1 = mn1;

        float ps0 = 0.f, ps1 = 0.f;
        uint32_t pa[4][2];
        if (interior) {
#pragma unroll
            for (int n8 = 0; n8 < 4; n8++) {
                float p0 = __expf(cS[n8][0] - mn0);
                float p1 = __expf(cS[n8][1] - mn0);
                float p2 = __expf(cS[n8][2] - mn1);
                float p3 = __expf(cS[n8][3] - mn1);
                ps0 += p0 + p1; ps1 += p2 + p3;
                pa[n8][0] = packh2(p0, p1);
                pa[n8][1] = packh2(p2, p3);
            }
        } else {
#pragma unroll
            for (int n8 = 0; n8 < 4; n8++) {
                float p0 = (cS[n8][0] < -1e29f) ? 0.f : __expf(cS[n8][0] - mn0);
                float p1 = (cS[n8][1] < -1e29f) ? 0.f : __expf(cS[n8][1] - mn0);
                float p2 = (cS[n8][2] < -1e29f) ? 0.f : __expf(cS[n8][2] - mn1);
                float p3 = (cS[n8][3] < -1e29f) ? 0.f : __expf(cS[n8][3] - mn1);
                ps0 += p0 + p1; ps1 += p2 + p3;
                pa[n8][0] = packh2(p0, p1);
                pa[n8][1] = packh2(p2, p3);
            }
        }
        l0 = l0 * sc0 + ps0;
        l1 = l1 * sc1 + ps1;
#pragma unroll
        for (int t = 0; t < 8; t++) {
            o[t][0] *= sc0; o[t][1] *= sc0; o[t][2] *= sc1; o[t][3] *= sc1;
        }

#pragma unroll
        for (int kp = 0; kp < 2; kp++) {
            uint32_t a[4] = { pa[2 * kp][0], pa[2 * kp][1], pa[2 * kp + 1][0], pa[2 * kp + 1][1] };
#pragma unroll
            for (int np = 0; np < 4; np++) {
                uint32_t bv[4];
                LDSM_X4_T(bv, sb + VS_OFF +
                    (uint32_t)((kk0 + kp * 16 + a_r) * PADH + np * 16 + a_c) * 2);
                MMA_F16(o[2 * np],     a, bv[0], bv[1]);
                MMA_F16(o[2 * np + 1], a, bv[2], bv[3]);
            }
        }
    }

    l0 += __shfl_xor_sync(0xffffffffu, l0, 1);
    l0 += __shfl_xor_sync(0xffffffffu, l0, 2);
    l1 += __shfl_xor_sync(0xffffffffu, l1, 1);
    l1 += __shfl_xor_sync(0xffffffffu, l1, 2);
    float inv0 = 1.0f / l0;
    float inv1 = 1.0f / l1;

    size_t r0 = (size_t)(b * TSEQ + qi0) * DMODEL;
    size_t r1 = r0 + 8 * DMODEL;
#pragma unroll
    for (int t = 0; t < 8; t++) {
        int col = h * HD + t * 8 + 2 * (lane & 3);
        *(__half2*)(g_Ah + r0 + col) = __floats2half2_rn(o[t][0] * inv0, o[t][1] * inv0);
        *(__half2*)(g_Ah + r1 + col) = __floats2half2_rn(o[t][2] * inv1, o[t][3] * inv1);
    }
}

// ---------------------------------------------------------------------------
extern "C" void kernel_launch(void* const* d_in, const int* in_sizes, int n_in,
                              void* d_out, int out_size)
{
    const float* x    = (const float*)d_in[0];
    const float* Wqkv = (const float*)d_in[1];
    const float* Wout = (const float*)d_in[2];
    const float* bout = (const float*)d_in[3];
    float* out = (float*)d_out;

    __half *Ah, *Bh, *Bo;
    cudaGetSymbolAddress((void**)&Ah, g_Ah);
    cudaGetSymbolAddress((void**)&Bh, g_Bh);
    cudaGetSymbolAddress((void**)&Bo, g_Bo);

    cudaFuncSetAttribute(gemm_qkv, cudaFuncAttributeMaxDynamicSharedMemorySize, GEMM_SMEM);
    cudaFuncSetAttribute(gemm_out, cudaFuncAttributeMaxDynamicSharedMemorySize, OGEMM_SMEM);
    cudaFuncSetAttribute(attn_kernel, cudaFuncAttributeMaxDynamicSharedMemorySize, ATTN_SMEM);

    prep_kernel<<<PREP_BLKS, 256>>>(x, Wqkv, Wout);

    gemm_qkv<<<dim3(QKVCOLS / BN, ROWS / BM), 128, GEMM_SMEM>>>(
        Ah, Bh, ROWS, QKVCOLS, DMODEL);

    attn_kernel<<<dim3(TSEQ / 128, NHEAD, NB), 256, ATTN_SMEM>>>();

    gemm_out<<<dim3(DMODEL / BN, ROWS / OBM), 128, OGEMM_SMEM>>>(
        Ah, Bo, out, ROWS, DMODEL, DMODEL, bout);
}